// round 5
// baseline (speedup 1.0000x reference)
#include <cuda_runtime.h>
#include <cuda_bf16.h>
#include <cstdint>

// ---------------------------------------------------------------------------
// Problem constants (fixed by setup_inputs)
// ---------------------------------------------------------------------------
constexpr int Hh  = 160;
constexpr int Ww  = 160;
constexpr int Q   = Hh * Ww;      // 25600
constexpr int C   = 256;
constexpr int NH  = 8;
constexpr int HD  = C / NH;       // 32
constexpr int NP  = 4;
constexpr int LC  = 2;
constexpr int QC  = Q * C;        // 6,553,600

// ---------------------------------------------------------------------------
// Scratch (device globals -- no allocations allowed)
// ---------------------------------------------------------------------------
__device__ float g_qsum[QC];
__device__ float g_v[2 * QC];
__device__ float g_off[Q * NH * LC * NP * 2];
__device__ float g_aw [Q * NH * LC * NP];
__device__ float g_attn[QC];
__device__ float g_x [QC];
__device__ float g_q1[QC];
__device__ float g_q2[QC];
__device__ float g_hid[Q * 4 * C];

// ---------------------------------------------------------------------------
// Generic tiled SGEMM:  C[M,N] = A[M,K] @ B[K,N] + bias[N] (+ res[M,N]) (ReLU?)
// Requires: M%BM==0, N%BN==0, K%BK==0, K%4==0, N%4==0 (all true here).
// ---------------------------------------------------------------------------
template<int BM, int BN, int BK, int TM, int TN, bool RELU>
__global__ void __launch_bounds__((BM / TM) * (BN / TN))
sgemm(int M, int N, int K,
      const float* __restrict__ A, const float* __restrict__ B,
      const float* __restrict__ bias, const float* __restrict__ res,
      float* __restrict__ Cout)
{
    constexpr int NT = (BM / TM) * (BN / TN);
    __shared__ float As[BK][BM];
    __shared__ float Bs[BK][BN];

    const int tid = threadIdx.x;
    const int tx  = tid % (BN / TN);
    const int ty  = tid / (BN / TN);
    const int rowBase = blockIdx.y * BM;
    const int colBase = blockIdx.x * BN;

    const float* Ab = A + (size_t)rowBase * K;
    const float* Bb = B + colBase;

    float acc[TM][TN];
#pragma unroll
    for (int i = 0; i < TM; i++)
#pragma unroll
        for (int j = 0; j < TN; j++) acc[i][j] = 0.f;

    for (int k0 = 0; k0 < K; k0 += BK) {
        // load A tile (BM x BK), transposed into As[BK][BM]
        for (int i = tid; i < BM * BK / 4; i += NT) {
            int r = i / (BK / 4);
            int c = (i % (BK / 4)) * 4;
            float4 v = *reinterpret_cast<const float4*>(Ab + (size_t)r * K + k0 + c);
            As[c + 0][r] = v.x; As[c + 1][r] = v.y;
            As[c + 2][r] = v.z; As[c + 3][r] = v.w;
        }
        // load B tile (BK x BN)
        for (int i = tid; i < BK * BN / 4; i += NT) {
            int r = i / (BN / 4);
            int c = (i % (BN / 4)) * 4;
            *reinterpret_cast<float4*>(&Bs[r][c]) =
                *reinterpret_cast<const float4*>(Bb + (size_t)(k0 + r) * N + c);
        }
        __syncthreads();

#pragma unroll
        for (int k = 0; k < BK; k++) {
            float a[TM], b[TN];
#pragma unroll
            for (int i = 0; i < TM; i += 4) {
                float4 t = *reinterpret_cast<const float4*>(&As[k][ty * TM + i]);
                a[i] = t.x; a[i + 1] = t.y; a[i + 2] = t.z; a[i + 3] = t.w;
            }
#pragma unroll
            for (int j = 0; j < TN; j += 4) {
                float4 t = *reinterpret_cast<const float4*>(&Bs[k][tx * TN + j]);
                b[j] = t.x; b[j + 1] = t.y; b[j + 2] = t.z; b[j + 3] = t.w;
            }
#pragma unroll
            for (int i = 0; i < TM; i++)
#pragma unroll
                for (int j = 0; j < TN; j++)
                    acc[i][j] += a[i] * b[j];
        }
        __syncthreads();
    }

#pragma unroll
    for (int i = 0; i < TM; i++) {
        const int row = rowBase + ty * TM + i;
#pragma unroll
        for (int j = 0; j < TN; j += 4) {
            const int col = colBase + tx * TN + j;
            float4 bv = *reinterpret_cast<const float4*>(bias + col);
            float4 o;
            o.x = acc[i][j + 0] + bv.x;
            o.y = acc[i][j + 1] + bv.y;
            o.z = acc[i][j + 2] + bv.z;
            o.w = acc[i][j + 3] + bv.w;
            if (res) {
                float4 rv = *reinterpret_cast<const float4*>(res + (size_t)row * N + col);
                o.x += rv.x; o.y += rv.y; o.z += rv.z; o.w += rv.w;
            }
            if (RELU) {
                o.x = fmaxf(o.x, 0.f); o.y = fmaxf(o.y, 0.f);
                o.z = fmaxf(o.z, 0.f); o.w = fmaxf(o.w, 0.f);
            }
            *reinterpret_cast<float4*>(Cout + (size_t)row * N + col) = o;
        }
    }
}

// ---------------------------------------------------------------------------
// Deformable sampling: one warp per (q, h). Softmax over L*NP in registers,
// bilinear gather from v[L, Q, NH, HD] (lane d reads element d -> coalesced).
// ---------------------------------------------------------------------------
__device__ __forceinline__ float fetch_corner(const float* __restrict__ vl, int xi, int yi)
{
    if (xi < 0 || xi >= Ww || yi < 0 || yi >= Hh) return 0.f;
    return vl[(yi * Ww + xi) * C];
}

template<int L>
__global__ void sampler_kernel(const float* __restrict__ v,
                               const float* __restrict__ off,
                               const float* __restrict__ awl,
                               const float* __restrict__ ref2d,
                               float* __restrict__ out)
{
    const int w    = (blockIdx.x * blockDim.x + threadIdx.x) >> 5;
    const int lane = threadIdx.x & 31;
    if (w >= Q * NH) return;
    const int q = w / NH;
    const int h = w % NH;

    constexpr int LNP = L * NP;
    float wgt[LNP];
    const float* aw = awl + (size_t)(q * NH + h) * LNP;
    float m = -1e30f;
#pragma unroll
    for (int i = 0; i < LNP; i++) { wgt[i] = aw[i]; m = fmaxf(m, wgt[i]); }
    float s = 0.f;
#pragma unroll
    for (int i = 0; i < LNP; i++) { wgt[i] = __expf(wgt[i] - m); s += wgt[i]; }
    const float inv = 1.f / s;

    const float* offp = off + (size_t)(q * NH + h) * LNP * 2;
    float acc = 0.f;

#pragma unroll
    for (int l = 0; l < L; l++) {
        const float rx = ref2d[(q * LC + l) * 2 + 0];
        const float ry = ref2d[(q * LC + l) * 2 + 1];
        const float* vl = v + ((size_t)l * Q) * C + h * HD + lane;
#pragma unroll
        for (int p = 0; p < NP; p++) {
            const float ox = offp[(l * NP + p) * 2 + 0];
            const float oy = offp[(l * NP + p) * 2 + 1];
            const float x = (rx + ox * (1.f / (float)Ww)) * (float)Ww - 0.5f;
            const float y = (ry + oy * (1.f / (float)Hh)) * (float)Hh - 0.5f;
            const float x0f = floorf(x), y0f = floorf(y);
            const int x0 = (int)x0f, y0 = (int)y0f;
            const float tx = x - x0f, ty = y - y0f;
            const float wp = wgt[l * NP + p] * inv;

            const float c00 = fetch_corner(vl, x0,     y0);
            const float c10 = fetch_corner(vl, x0 + 1, y0);
            const float c01 = fetch_corner(vl, x0,     y0 + 1);
            const float c11 = fetch_corner(vl, x0 + 1, y0 + 1);

            const float top = c00 * (1.f - tx) + c10 * tx;
            const float bot = c01 * (1.f - tx) + c11 * tx;
            acc += wp * (top * (1.f - ty) + bot * ty);
        }
    }
    out[(size_t)q * C + h * HD + lane] = acc;
}

// ---------------------------------------------------------------------------
// LayerNorm: one warp per row of 256.
// ---------------------------------------------------------------------------
__global__ void ln_kernel(const float* __restrict__ x,
                          const float* __restrict__ g,
                          const float* __restrict__ b,
                          float* __restrict__ y)
{
    const int row  = (blockIdx.x * blockDim.x + threadIdx.x) >> 5;
    const int lane = threadIdx.x & 31;
    if (row >= Q) return;
    const float* xr = x + (size_t)row * C;
    float v[8];
    float s = 0.f;
#pragma unroll
    for (int i = 0; i < 8; i++) { v[i] = xr[lane + 32 * i]; s += v[i]; }
#pragma unroll
    for (int o = 16; o; o >>= 1) s += __shfl_xor_sync(0xffffffffu, s, o);
    const float mu = s * (1.f / (float)C);
    float s2 = 0.f;
#pragma unroll
    for (int i = 0; i < 8; i++) { const float d = v[i] - mu; s2 += d * d; }
#pragma unroll
    for (int o = 16; o; o >>= 1) s2 += __shfl_xor_sync(0xffffffffu, s2, o);
    const float rstd = rsqrtf(s2 * (1.f / (float)C) + 1e-5f);
#pragma unroll
    for (int i = 0; i < 8; i++) {
        const int c = lane + 32 * i;
        y[(size_t)row * C + c] = (v[i] - mu) * rstd * g[c] + b[c];
    }
}

__global__ void add_kernel(const float* __restrict__ a, const float* __restrict__ b,
                           float* __restrict__ o, int n)
{
    int i = blockIdx.x * blockDim.x + threadIdx.x;
    if (i < n) o[i] = a[i] + b[i];
}

__global__ void sp_kernel(const int* __restrict__ sp, float* __restrict__ o)
{
    int i = threadIdx.x;
    if (i < 4) o[i] = (float)sp[i];
}

// ---------------------------------------------------------------------------
// Driver
// ---------------------------------------------------------------------------
extern "C" void kernel_launch(void* const* d_in, const int* in_sizes, int n_in,
                              void* d_out, int out_size)
{
    (void)in_sizes; (void)n_in; (void)out_size;

    const float* query     = (const float*)d_in[0];
    const float* query_pos = (const float*)d_in[1];
    const float* value     = (const float*)d_in[2];
    const float* ref2d     = (const float*)d_in[3];
    const int*   spatial   = (const int*)  d_in[4];
    const float* sa_off_w = (const float*)d_in[5];
    const float* sa_off_b = (const float*)d_in[6];
    const float* sa_aw_w  = (const float*)d_in[7];
    const float* sa_aw_b  = (const float*)d_in[8];
    const float* sa_vp_w  = (const float*)d_in[9];
    const float* sa_vp_b  = (const float*)d_in[10];
    const float* sa_op_w  = (const float*)d_in[11];
    const float* sa_op_b  = (const float*)d_in[12];
    const float* ca_off_w = (const float*)d_in[13];
    const float* ca_off_b = (const float*)d_in[14];
    const float* ca_aw_w  = (const float*)d_in[15];
    const float* ca_aw_b  = (const float*)d_in[16];
    const float* ca_vp_w  = (const float*)d_in[17];
    const float* ca_vp_b  = (const float*)d_in[18];
    const float* ca_op_w  = (const float*)d_in[19];
    const float* ca_op_b  = (const float*)d_in[20];
    const float* ffn_w1   = (const float*)d_in[21];
    const float* ffn_b1   = (const float*)d_in[22];
    const float* ffn_w2   = (const float*)d_in[23];
    const float* ffn_b2   = (const float*)d_in[24];
    const float* ln1_g = (const float*)d_in[25];
    const float* ln1_b = (const float*)d_in[26];
    const float* ln2_g = (const float*)d_in[27];
    const float* ln2_b = (const float*)d_in[28];
    const float* ln3_g = (const float*)d_in[29];
    const float* ln3_b = (const float*)d_in[30];

    float *qsum, *v, *off, *aw, *attn, *x, *q1, *q2, *hid;
    cudaGetSymbolAddress((void**)&qsum, g_qsum);
    cudaGetSymbolAddress((void**)&v,    g_v);
    cudaGetSymbolAddress((void**)&off,  g_off);
    cudaGetSymbolAddress((void**)&aw,   g_aw);
    cudaGetSymbolAddress((void**)&attn, g_attn);
    cudaGetSymbolAddress((void**)&x,    g_x);
    cudaGetSymbolAddress((void**)&q1,   g_q1);
    cudaGetSymbolAddress((void**)&q2,   g_q2);
    cudaGetSymbolAddress((void**)&hid,  g_hid);

    float* out = (float*)d_out;
    const int ADDB = (QC + 255) / 256;

    // ---------------- Self deformable attention (L = 1) ----------------
    add_kernel<<<ADDB, 256>>>(query, query_pos, qsum, QC);
    sgemm<128,128,8,8,8,false><<<dim3(2, Q/128), 256>>>(Q, 256, 256, query, sa_vp_w, sa_vp_b, nullptr, v);
    sgemm<128, 64,8,8,4,false><<<dim3(1, Q/128), 256>>>(Q,  64, 256, qsum,  sa_off_w, sa_off_b, nullptr, off);
    sgemm<128, 32,8,8,4,false><<<dim3(1, Q/128), 128>>>(Q,  32, 256, qsum,  sa_aw_w,  sa_aw_b,  nullptr, aw);
    sampler_kernel<1><<<Q*NH/8, 256>>>(v, off, aw, ref2d, attn);
    sgemm<128,128,8,8,8,false><<<dim3(2, Q/128), 256>>>(Q, 256, 256, attn, sa_op_w, sa_op_b, query, x);
    ln_kernel<<<Q/8, 256>>>(x, ln1_g, ln1_b, q1);

    // ---------------- Cross deformable attention (L = 2) ----------------
    add_kernel<<<ADDB, 256>>>(q1, query_pos, qsum, QC);
    sgemm<128,128,8,8,8,false><<<dim3(2, 2*Q/128), 256>>>(2*Q, 256, 256, value, ca_vp_w, ca_vp_b, nullptr, v);
    sgemm<128, 64,8,8,4,false><<<dim3(2, Q/128), 256>>>(Q, 128, 256, qsum, ca_off_w, ca_off_b, nullptr, off);
    sgemm<128, 64,8,8,4,false><<<dim3(1, Q/128), 256>>>(Q,  64, 256, qsum, ca_aw_w,  ca_aw_b,  nullptr, aw);
    sampler_kernel<2><<<Q*NH/8, 256>>>(v, off, aw, ref2d, attn);
    sgemm<128,128,8,8,8,false><<<dim3(2, Q/128), 256>>>(Q, 256, 256, attn, ca_op_w, ca_op_b, q1, x);
    ln_kernel<<<Q/8, 256>>>(x, ln2_g, ln2_b, q2);

    // ---------------- FFN ----------------
    sgemm<128,128,8,8,8,true ><<<dim3(8, Q/128), 256>>>(Q, 1024,  256, q2,  ffn_w1, ffn_b1, nullptr, hid);
    sgemm<128,128,8,8,8,false><<<dim3(2, Q/128), 256>>>(Q,  256, 1024, hid, ffn_w2, ffn_b2, q2, x);
    ln_kernel<<<Q/8, 256>>>(x, ln3_g, ln3_b, out);

    // ---------------- Passthrough outputs ----------------
    cudaMemcpyAsync(out + QC,     query_pos, (size_t)QC * 4,      cudaMemcpyDeviceToDevice, 0);
    cudaMemcpyAsync(out + 2*QC,   value,     (size_t)2 * QC * 4,  cudaMemcpyDeviceToDevice, 0);
    cudaMemcpyAsync(out + 4*QC,   ref2d,     (size_t)Q*LC*2 * 4,  cudaMemcpyDeviceToDevice, 0);
    sp_kernel<<<1, 4>>>(spatial, out + 4*QC + Q*LC*2);
}

// round 6
// speedup vs baseline: 1.6835x; 1.6835x over previous
#include <cuda_runtime.h>
#include <cuda_bf16.h>
#include <cstdint>

// ---------------------------------------------------------------------------
// Problem constants (fixed by setup_inputs)
// ---------------------------------------------------------------------------
constexpr int Hh  = 160;
constexpr int Ww  = 160;
constexpr int Q   = Hh * Ww;      // 25600
constexpr int C   = 256;
constexpr int NH  = 8;
constexpr int HD  = C / NH;       // 32
constexpr int NP  = 4;
constexpr int LC  = 2;
constexpr int QC  = Q * C;        // 6,553,600

// ---------------------------------------------------------------------------
// Scratch (device globals -- no allocations allowed)
// ---------------------------------------------------------------------------
__device__ float g_qsum[QC];
__device__ float g_v[2 * QC];
__device__ float g_off[Q * NH * LC * NP * 2];
__device__ float g_aw [Q * NH * LC * NP];
__device__ float g_attn[QC];
__device__ float g_x [QC];
__device__ float g_q1[QC];
__device__ float g_q2[QC];
__device__ float g_hid[Q * 4 * C];

// ---------------------------------------------------------------------------
// Tensor-core GEMM via mma.sync.m16n8k16.bf16 with 2-term bf16 split
// (hi+lo): acc += Ahi*Bhi + Ahi*Blo + Alo*Bhi  -> ~1e-5 relative accuracy.
//
// C[M,N] = A[M,K] @ B[K,N] + bias[N] (+ res[M,N]) (optional ReLU)
// Block tile 128x128, BK=32, 256 threads = 8 warps (2 M x 4 N), warp = 64x32.
// Requires M%128==0, K%32==0, N%8==0 (guards handle N < gridN*128).
// ---------------------------------------------------------------------------
__device__ __forceinline__ void ldm_x4(uint32_t& r0, uint32_t& r1,
                                       uint32_t& r2, uint32_t& r3, uint32_t addr)
{
    asm volatile("ldmatrix.sync.aligned.m8n8.x4.shared.b16 {%0,%1,%2,%3}, [%4];"
                 : "=r"(r0), "=r"(r1), "=r"(r2), "=r"(r3) : "r"(addr));
}
__device__ __forceinline__ void ldm_x4_t(uint32_t& r0, uint32_t& r1,
                                         uint32_t& r2, uint32_t& r3, uint32_t addr)
{
    asm volatile("ldmatrix.sync.aligned.m8n8.x4.trans.shared.b16 {%0,%1,%2,%3}, [%4];"
                 : "=r"(r0), "=r"(r1), "=r"(r2), "=r"(r3) : "r"(addr));
}
__device__ __forceinline__ void mma_bf16(float* c, uint32_t a0, uint32_t a1,
                                         uint32_t a2, uint32_t a3,
                                         uint32_t b0, uint32_t b1)
{
    asm volatile("mma.sync.aligned.m16n8k16.row.col.f32.bf16.bf16.f32 "
                 "{%0,%1,%2,%3}, {%4,%5,%6,%7}, {%8,%9}, {%0,%1,%2,%3};"
                 : "+f"(c[0]), "+f"(c[1]), "+f"(c[2]), "+f"(c[3])
                 : "r"(a0), "r"(a1), "r"(a2), "r"(a3), "r"(b0), "r"(b1));
}

template<bool RELU>
__global__ void __launch_bounds__(256, 1)
mma_gemm(int M, int N, int K,
         const float* __restrict__ A, const float* __restrict__ B,
         const float* __restrict__ bias, const float* __restrict__ res,
         float* __restrict__ Cout)
{
    // [0] = hi, [1] = lo
    __shared__ __nv_bfloat16 sA[2][128 * 32];
    __shared__ __nv_bfloat16 sB[2][32 * 128];

    const int tid  = threadIdx.x;
    const int lane = tid & 31;
    const int warp = tid >> 5;
    const int wm   = warp >> 2;          // 0..1
    const int wn   = warp & 3;           // 0..3
    const int rowBase = blockIdx.y * 128;
    const int colBase = blockIdx.x * 128;

    const uint32_t aHiB = (uint32_t)__cvta_generic_to_shared(&sA[0][0]);
    const uint32_t aLoB = (uint32_t)__cvta_generic_to_shared(&sA[1][0]);
    const uint32_t bHiB = (uint32_t)__cvta_generic_to_shared(&sB[0][0]);
    const uint32_t bLoB = (uint32_t)__cvta_generic_to_shared(&sB[1][0]);

    float acc[4][4][4];
#pragma unroll
    for (int i = 0; i < 4; i++)
#pragma unroll
        for (int j = 0; j < 4; j++)
#pragma unroll
            for (int k = 0; k < 4; k++) acc[i][j][k] = 0.f;

    for (int kt = 0; kt < K; kt += 32) {
        // ---- stage A tile (128 x 32 fp32 -> bf16 hi/lo, swizzled) ----
#pragma unroll
        for (int j = 0; j < 4; j++) {
            const int idx = tid + j * 256;          // over 128x8 float4 slots
            const int r   = idx >> 3;
            const int c4  = idx & 7;                // col = c4*4
            const float4 va = *reinterpret_cast<const float4*>(
                A + (size_t)(rowBase + r) * K + kt + c4 * 4);
            const int chunk = c4 >> 1;
            const int cs    = chunk ^ ((r >> 1) & 3);
            const int pos   = r * 32 + cs * 8 + (c4 & 1) * 4;
            __nv_bfloat162 h0 = __floats2bfloat162_rn(va.x, va.y);
            __nv_bfloat162 h1 = __floats2bfloat162_rn(va.z, va.w);
            float2 f0 = __bfloat1622float2(h0);
            float2 f1 = __bfloat1622float2(h1);
            __nv_bfloat162 l0 = __floats2bfloat162_rn(va.x - f0.x, va.y - f0.y);
            __nv_bfloat162 l1 = __floats2bfloat162_rn(va.z - f1.x, va.w - f1.y);
            *reinterpret_cast<__nv_bfloat162*>(&sA[0][pos])     = h0;
            *reinterpret_cast<__nv_bfloat162*>(&sA[0][pos + 2]) = h1;
            *reinterpret_cast<__nv_bfloat162*>(&sA[1][pos])     = l0;
            *reinterpret_cast<__nv_bfloat162*>(&sA[1][pos + 2]) = l1;
        }
        // ---- stage B tile (32 x 128 fp32 -> bf16 hi/lo, swizzled, N-guarded) ----
#pragma unroll
        for (int j = 0; j < 4; j++) {
            const int idx = tid + j * 256;          // over 32x32 float4 slots
            const int r   = idx >> 5;
            const int c4  = idx & 31;               // col = c4*4
            const int gc  = colBase + c4 * 4;
            float4 vb = make_float4(0.f, 0.f, 0.f, 0.f);
            if (gc < N)
                vb = *reinterpret_cast<const float4*>(B + (size_t)(kt + r) * N + gc);
            const int chunk = c4 >> 1;
            const int cs    = chunk ^ (r & 7);
            const int pos   = r * 128 + cs * 8 + (c4 & 1) * 4;
            __nv_bfloat162 h0 = __floats2bfloat162_rn(vb.x, vb.y);
            __nv_bfloat162 h1 = __floats2bfloat162_rn(vb.z, vb.w);
            float2 f0 = __bfloat1622float2(h0);
            float2 f1 = __bfloat1622float2(h1);
            __nv_bfloat162 l0 = __floats2bfloat162_rn(vb.x - f0.x, vb.y - f0.y);
            __nv_bfloat162 l1 = __floats2bfloat162_rn(vb.z - f1.x, vb.w - f1.y);
            *reinterpret_cast<__nv_bfloat162*>(&sB[0][pos])     = h0;
            *reinterpret_cast<__nv_bfloat162*>(&sB[0][pos + 2]) = h1;
            *reinterpret_cast<__nv_bfloat162*>(&sB[1][pos])     = l0;
            *reinterpret_cast<__nv_bfloat162*>(&sB[1][pos + 2]) = l1;
        }
        __syncthreads();

#pragma unroll
        for (int s = 0; s < 2; s++) {
            uint32_t af[2][4][4];
            uint32_t bf[2][4][2];
            // A fragments: 4 m-tiles, hi & lo
#pragma unroll
            for (int mt = 0; mt < 4; mt++) {
                const int r  = wm * 64 + mt * 16 + (lane & 15);
                const int c  = s * 2 + (lane >> 4);
                const int cs = c ^ ((r >> 1) & 3);
                const uint32_t off = (uint32_t)(r * 32 + cs * 8) * 2;
                ldm_x4(af[0][mt][0], af[0][mt][1], af[0][mt][2], af[0][mt][3], aHiB + off);
                ldm_x4(af[1][mt][0], af[1][mt][1], af[1][mt][2], af[1][mt][3], aLoB + off);
            }
            // B fragments: 4 n-tiles via 2 x ldmatrix.x4.trans, hi & lo
#pragma unroll
            for (int pi = 0; pi < 2; pi++) {
                const int k  = s * 16 + (lane & 15);
                const int cc = wn * 4 + (lane >> 4) + pi * 2;
                const int cs = cc ^ (k & 7);
                const uint32_t off = (uint32_t)(k * 128 + cs * 8) * 2;
                ldm_x4_t(bf[0][pi*2][0], bf[0][pi*2][1], bf[0][pi*2+1][0], bf[0][pi*2+1][1], bHiB + off);
                ldm_x4_t(bf[1][pi*2][0], bf[1][pi*2][1], bf[1][pi*2+1][0], bf[1][pi*2+1][1], bLoB + off);
            }
            // hi*hi + hi*lo + lo*hi
#pragma unroll
            for (int mt = 0; mt < 4; mt++)
#pragma unroll
                for (int nt = 0; nt < 4; nt++) {
                    mma_bf16(acc[mt][nt], af[0][mt][0], af[0][mt][1], af[0][mt][2], af[0][mt][3],
                             bf[0][nt][0], bf[0][nt][1]);
                    mma_bf16(acc[mt][nt], af[0][mt][0], af[0][mt][1], af[0][mt][2], af[0][mt][3],
                             bf[1][nt][0], bf[1][nt][1]);
                    mma_bf16(acc[mt][nt], af[1][mt][0], af[1][mt][1], af[1][mt][2], af[1][mt][3],
                             bf[0][nt][0], bf[0][nt][1]);
                }
        }
        __syncthreads();
    }

    // ---- epilogue ----
    const int g  = lane >> 2;
    const int t4 = lane & 3;
#pragma unroll
    for (int mt = 0; mt < 4; mt++) {
#pragma unroll
        for (int nt = 0; nt < 4; nt++) {
            const int col = colBase + wn * 32 + nt * 8 + t4 * 2;
            if (col >= N) continue;
            const int r0 = rowBase + wm * 64 + mt * 16 + g;
            const float2 b2 = *reinterpret_cast<const float2*>(bias + col);
            float2 o0 = make_float2(acc[mt][nt][0] + b2.x, acc[mt][nt][1] + b2.y);
            float2 o1 = make_float2(acc[mt][nt][2] + b2.x, acc[mt][nt][3] + b2.y);
            if (res) {
                float2 r2a = *reinterpret_cast<const float2*>(res + (size_t)r0 * N + col);
                float2 r2b = *reinterpret_cast<const float2*>(res + (size_t)(r0 + 8) * N + col);
                o0.x += r2a.x; o0.y += r2a.y; o1.x += r2b.x; o1.y += r2b.y;
            }
            if (RELU) {
                o0.x = fmaxf(o0.x, 0.f); o0.y = fmaxf(o0.y, 0.f);
                o1.x = fmaxf(o1.x, 0.f); o1.y = fmaxf(o1.y, 0.f);
            }
            *reinterpret_cast<float2*>(Cout + (size_t)r0 * N + col) = o0;
            *reinterpret_cast<float2*>(Cout + (size_t)(r0 + 8) * N + col) = o1;
        }
    }
}

// ---------------------------------------------------------------------------
// Deformable sampling: one warp per (q, h).
// ---------------------------------------------------------------------------
__device__ __forceinline__ float fetch_corner(const float* __restrict__ vl, int xi, int yi)
{
    if (xi < 0 || xi >= Ww || yi < 0 || yi >= Hh) return 0.f;
    return vl[(yi * Ww + xi) * C];
}

template<int L>
__global__ void sampler_kernel(const float* __restrict__ v,
                               const float* __restrict__ off,
                               const float* __restrict__ awl,
                               const float* __restrict__ ref2d,
                               float* __restrict__ out)
{
    const int w    = (blockIdx.x * blockDim.x + threadIdx.x) >> 5;
    const int lane = threadIdx.x & 31;
    if (w >= Q * NH) return;
    const int q = w / NH;
    const int h = w % NH;

    constexpr int LNP = L * NP;
    float wgt[LNP];
    const float* aw = awl + (size_t)(q * NH + h) * LNP;
    float m = -1e30f;
#pragma unroll
    for (int i = 0; i < LNP; i++) { wgt[i] = aw[i]; m = fmaxf(m, wgt[i]); }
    float s = 0.f;
#pragma unroll
    for (int i = 0; i < LNP; i++) { wgt[i] = __expf(wgt[i] - m); s += wgt[i]; }
    const float inv = 1.f / s;

    const float* offp = off + (size_t)(q * NH + h) * LNP * 2;
    float acc = 0.f;

#pragma unroll
    for (int l = 0; l < L; l++) {
        const float rx = ref2d[(q * LC + l) * 2 + 0];
        const float ry = ref2d[(q * LC + l) * 2 + 1];
        const float* vl = v + ((size_t)l * Q) * C + h * HD + lane;
#pragma unroll
        for (int p = 0; p < NP; p++) {
            const float ox = offp[(l * NP + p) * 2 + 0];
            const float oy = offp[(l * NP + p) * 2 + 1];
            const float x = (rx + ox * (1.f / (float)Ww)) * (float)Ww - 0.5f;
            const float y = (ry + oy * (1.f / (float)Hh)) * (float)Hh - 0.5f;
            const float x0f = floorf(x), y0f = floorf(y);
            const int x0 = (int)x0f, y0 = (int)y0f;
            const float tx = x - x0f, ty = y - y0f;
            const float wp = wgt[l * NP + p] * inv;

            const float c00 = fetch_corner(vl, x0,     y0);
            const float c10 = fetch_corner(vl, x0 + 1, y0);
            const float c01 = fetch_corner(vl, x0,     y0 + 1);
            const float c11 = fetch_corner(vl, x0 + 1, y0 + 1);

            const float top = c00 * (1.f - tx) + c10 * tx;
            const float bot = c01 * (1.f - tx) + c11 * tx;
            acc += wp * (top * (1.f - ty) + bot * ty);
        }
    }
    out[(size_t)q * C + h * HD + lane] = acc;
}

// ---------------------------------------------------------------------------
// LayerNorm: one warp per row of 256.
// ---------------------------------------------------------------------------
__global__ void ln_kernel(const float* __restrict__ x,
                          const float* __restrict__ g,
                          const float* __restrict__ b,
                          float* __restrict__ y)
{
    const int row  = (blockIdx.x * blockDim.x + threadIdx.x) >> 5;
    const int lane = threadIdx.x & 31;
    if (row >= Q) return;
    const float* xr = x + (size_t)row * C;
    float v[8];
    float s = 0.f;
#pragma unroll
    for (int i = 0; i < 8; i++) { v[i] = xr[lane + 32 * i]; s += v[i]; }
#pragma unroll
    for (int o = 16; o; o >>= 1) s += __shfl_xor_sync(0xffffffffu, s, o);
    const float mu = s * (1.f / (float)C);
    float s2 = 0.f;
#pragma unroll
    for (int i = 0; i < 8; i++) { const float d = v[i] - mu; s2 += d * d; }
#pragma unroll
    for (int o = 16; o; o >>= 1) s2 += __shfl_xor_sync(0xffffffffu, s2, o);
    const float rstd = rsqrtf(s2 * (1.f / (float)C) + 1e-5f);
#pragma unroll
    for (int i = 0; i < 8; i++) {
        const int c = lane + 32 * i;
        y[(size_t)row * C + c] = (v[i] - mu) * rstd * g[c] + b[c];
    }
}

__global__ void add_kernel(const float* __restrict__ a, const float* __restrict__ b,
                           float* __restrict__ o, int n)
{
    int i = blockIdx.x * blockDim.x + threadIdx.x;
    if (i < n) o[i] = a[i] + b[i];
}

__global__ void sp_kernel(const int* __restrict__ sp, float* __restrict__ o)
{
    int i = threadIdx.x;
    if (i < 4) o[i] = (float)sp[i];
}

// ---------------------------------------------------------------------------
// Driver
// ---------------------------------------------------------------------------
extern "C" void kernel_launch(void* const* d_in, const int* in_sizes, int n_in,
                              void* d_out, int out_size)
{
    (void)in_sizes; (void)n_in; (void)out_size;

    const float* query     = (const float*)d_in[0];
    const float* query_pos = (const float*)d_in[1];
    const float* value     = (const float*)d_in[2];
    const float* ref2d     = (const float*)d_in[3];
    const int*   spatial   = (const int*)  d_in[4];
    const float* sa_off_w = (const float*)d_in[5];
    const float* sa_off_b = (const float*)d_in[6];
    const float* sa_aw_w  = (const float*)d_in[7];
    const float* sa_aw_b  = (const float*)d_in[8];
    const float* sa_vp_w  = (const float*)d_in[9];
    const float* sa_vp_b  = (const float*)d_in[10];
    const float* sa_op_w  = (const float*)d_in[11];
    const float* sa_op_b  = (const float*)d_in[12];
    const float* ca_off_w = (const float*)d_in[13];
    const float* ca_off_b = (const float*)d_in[14];
    const float* ca_aw_w  = (const float*)d_in[15];
    const float* ca_aw_b  = (const float*)d_in[16];
    const float* ca_vp_w  = (const float*)d_in[17];
    const float* ca_vp_b  = (const float*)d_in[18];
    const float* ca_op_w  = (const float*)d_in[19];
    const float* ca_op_b  = (const float*)d_in[20];
    const float* ffn_w1   = (const float*)d_in[21];
    const float* ffn_b1   = (const float*)d_in[22];
    const float* ffn_w2   = (const float*)d_in[23];
    const float* ffn_b2   = (const float*)d_in[24];
    const float* ln1_g = (const float*)d_in[25];
    const float* ln1_b = (const float*)d_in[26];
    const float* ln2_g = (const float*)d_in[27];
    const float* ln2_b = (const float*)d_in[28];
    const float* ln3_g = (const float*)d_in[29];
    const float* ln3_b = (const float*)d_in[30];

    float *qsum, *v, *off, *aw, *attn, *x, *q1, *q2, *hid;
    cudaGetSymbolAddress((void**)&qsum, g_qsum);
    cudaGetSymbolAddress((void**)&v,    g_v);
    cudaGetSymbolAddress((void**)&off,  g_off);
    cudaGetSymbolAddress((void**)&aw,   g_aw);
    cudaGetSymbolAddress((void**)&attn, g_attn);
    cudaGetSymbolAddress((void**)&x,    g_x);
    cudaGetSymbolAddress((void**)&q1,   g_q1);
    cudaGetSymbolAddress((void**)&q2,   g_q2);
    cudaGetSymbolAddress((void**)&hid,  g_hid);

    float* out = (float*)d_out;
    const int ADDB = (QC + 255) / 256;

    // ---------------- Self deformable attention (L = 1) ----------------
    add_kernel<<<ADDB, 256>>>(query, query_pos, qsum, QC);
    mma_gemm<false><<<dim3(2, Q/128), 256>>>(Q, 256, 256, query, sa_vp_w, sa_vp_b, nullptr, v);
    mma_gemm<false><<<dim3(1, Q/128), 256>>>(Q,  64, 256, qsum,  sa_off_w, sa_off_b, nullptr, off);
    mma_gemm<false><<<dim3(1, Q/128), 256>>>(Q,  32, 256, qsum,  sa_aw_w,  sa_aw_b,  nullptr, aw);
    sampler_kernel<1><<<Q*NH/8, 256>>>(v, off, aw, ref2d, attn);
    mma_gemm<false><<<dim3(2, Q/128), 256>>>(Q, 256, 256, attn, sa_op_w, sa_op_b, query, x);
    ln_kernel<<<Q/8, 256>>>(x, ln1_g, ln1_b, q1);

    // ---------------- Cross deformable attention (L = 2) ----------------
    add_kernel<<<ADDB, 256>>>(q1, query_pos, qsum, QC);
    mma_gemm<false><<<dim3(2, 2*Q/128), 256>>>(2*Q, 256, 256, value, ca_vp_w, ca_vp_b, nullptr, v);
    mma_gemm<false><<<dim3(1, Q/128), 256>>>(Q, 128, 256, qsum, ca_off_w, ca_off_b, nullptr, off);
    mma_gemm<false><<<dim3(1, Q/128), 256>>>(Q,  64, 256, qsum, ca_aw_w,  ca_aw_b,  nullptr, aw);
    sampler_kernel<2><<<Q*NH/8, 256>>>(v, off, aw, ref2d, attn);
    mma_gemm<false><<<dim3(2, Q/128), 256>>>(Q, 256, 256, attn, ca_op_w, ca_op_b, q1, x);
    ln_kernel<<<Q/8, 256>>>(x, ln2_g, ln2_b, q2);

    // ---------------- FFN ----------------
    mma_gemm<true ><<<dim3(8, Q/128), 256>>>(Q, 1024,  256, q2,  ffn_w1, ffn_b1, nullptr, hid);
    mma_gemm<false><<<dim3(2, Q/128), 256>>>(Q,  256, 1024, hid, ffn_w2, ffn_b2, q2, x);
    ln_kernel<<<Q/8, 256>>>(x, ln3_g, ln3_b, out);

    // ---------------- Passthrough outputs ----------------
    cudaMemcpyAsync(out + QC,     query_pos, (size_t)QC * 4,      cudaMemcpyDeviceToDevice, 0);
    cudaMemcpyAsync(out + 2*QC,   value,     (size_t)2 * QC * 4,  cudaMemcpyDeviceToDevice, 0);
    cudaMemcpyAsync(out + 4*QC,   ref2d,     (size_t)Q*LC*2 * 4,  cudaMemcpyDeviceToDevice, 0);
    sp_kernel<<<1, 4>>>(spatial, out + 4*QC + Q*LC*2);
}

// round 7
// speedup vs baseline: 1.9627x; 1.1659x over previous
#include <cuda_runtime.h>
#include <cuda_bf16.h>
#include <cstdint>

// ---------------------------------------------------------------------------
// Problem constants
// ---------------------------------------------------------------------------
constexpr int Hh  = 160;
constexpr int Ww  = 160;
constexpr int Q   = Hh * Ww;      // 25600
constexpr int C   = 256;
constexpr int NH  = 8;
constexpr int HD  = C / NH;       // 32
constexpr int NP  = 4;
constexpr int LC  = 2;
constexpr int QC  = Q * C;        // 6,553,600

// Weight-plane cumulative offsets (elements)
constexpr int OFF_SA_OFF = 0;            // 256x64
constexpr int OFF_SA_AW  = 16384;        // 256x32
constexpr int OFF_SA_VP  = 24576;        // 256x256
constexpr int OFF_SA_OP  = 90112;        // 256x256
constexpr int OFF_CA_OFF = 155648;       // 256x128
constexpr int OFF_CA_AW  = 188416;       // 256x64
constexpr int OFF_CA_VP  = 204800;       // 256x256
constexpr int OFF_CA_OP  = 270336;       // 256x256
constexpr int OFF_FFN1   = 335872;       // 256x1024
constexpr int OFF_FFN2   = 598016;       // 1024x256
constexpr int W_TOTAL    = 860160;

// ---------------------------------------------------------------------------
// Scratch (device globals -- no allocations allowed)
// ---------------------------------------------------------------------------
__device__ float g_v[2 * QC];
__device__ float g_off[Q * NH * LC * NP * 2];
__device__ float g_aw [Q * NH * LC * NP];
__device__ float g_x [QC];
__device__ float g_q1[QC];
__device__ float g_q2[QC];

__device__ __align__(256) __nv_bfloat16 g_sH[QC],  g_sL[QC];    // qsum planes
__device__ __align__(256) __nv_bfloat16 g_qH[QC],  g_qL[QC];    // query planes
__device__ __align__(256) __nv_bfloat16 g_vH[2*QC], g_vL[2*QC]; // value planes
__device__ __align__(256) __nv_bfloat16 g_aH[QC],  g_aL[QC];    // attn planes
__device__ __align__(256) __nv_bfloat16 g_q2H[QC], g_q2L[QC];   // q2 planes
__device__ __align__(256) __nv_bfloat16 g_hidH[Q*4*C], g_hidL[Q*4*C];
__device__ __align__(256) __nv_bfloat16 g_wH[W_TOTAL], g_wL[W_TOTAL];

// ---------------------------------------------------------------------------
// PTX helpers
// ---------------------------------------------------------------------------
__device__ __forceinline__ void ldm_x4(uint32_t& r0, uint32_t& r1,
                                       uint32_t& r2, uint32_t& r3, uint32_t addr)
{
    asm volatile("ldmatrix.sync.aligned.m8n8.x4.shared.b16 {%0,%1,%2,%3}, [%4];"
                 : "=r"(r0), "=r"(r1), "=r"(r2), "=r"(r3) : "r"(addr));
}
__device__ __forceinline__ void ldm_x4_t(uint32_t& r0, uint32_t& r1,
                                         uint32_t& r2, uint32_t& r3, uint32_t addr)
{
    asm volatile("ldmatrix.sync.aligned.m8n8.x4.trans.shared.b16 {%0,%1,%2,%3}, [%4];"
                 : "=r"(r0), "=r"(r1), "=r"(r2), "=r"(r3) : "r"(addr));
}
__device__ __forceinline__ void mma_bf16(float* c, uint32_t a0, uint32_t a1,
                                         uint32_t a2, uint32_t a3,
                                         uint32_t b0, uint32_t b1)
{
    asm volatile("mma.sync.aligned.m16n8k16.row.col.f32.bf16.bf16.f32 "
                 "{%0,%1,%2,%3}, {%4,%5,%6,%7}, {%8,%9}, {%0,%1,%2,%3};"
                 : "+f"(c[0]), "+f"(c[1]), "+f"(c[2]), "+f"(c[3])
                 : "r"(a0), "r"(a1), "r"(a2), "r"(a3), "r"(b0), "r"(b1));
}
__device__ __forceinline__ void cp16(uint32_t s, const void* g)
{
    asm volatile("cp.async.cg.shared.global [%0], [%1], 16;" :: "r"(s), "l"(g));
}
__device__ __forceinline__ void cp16z(uint32_t s, const void* g, bool valid)
{
    int sz = valid ? 16 : 0;
    asm volatile("cp.async.cg.shared.global [%0], [%1], 16, %2;"
                 :: "r"(s), "l"(g), "r"(sz));
}
__device__ __forceinline__ void cp_commit()
{
    asm volatile("cp.async.commit_group;");
}
__device__ __forceinline__ void cp_wait2()
{
    asm volatile("cp.async.wait_group 2;");
}

// ---------------------------------------------------------------------------
// Tensor-core GEMM on pre-split bf16 planes. 3-term split accumulate:
//   acc += Ahi*Bhi + Ahi*Blo + Alo*Bhi
// Block 128x128x32, 256 thr = 8 warps (2M x 4N), 3-stage cp.async pipeline.
// Dynamic smem: 3 stages * (A 2x128x32 + B 2x32x128) bf16 = 96 KB.
// ---------------------------------------------------------------------------
constexpr int NSTAGE = 3;
constexpr int SMEM_BYTES = NSTAGE * 16384 * 2 * sizeof(__nv_bfloat16); // 96 KB? (see below)
// per stage: A planes 2*4096 + B planes 2*4096 = 16384 elts -> 32 KB; 3 stages = 96 KB
constexpr int GEMM_SMEM = NSTAGE * 16384 * (int)sizeof(__nv_bfloat16);

template<bool RELU, bool SPLIT_OUT>
__global__ void __launch_bounds__(256, 1)
mma_gemm(int M, int N, int K,
         const __nv_bfloat16* __restrict__ Ahi, const __nv_bfloat16* __restrict__ Alo,
         const __nv_bfloat16* __restrict__ Bhi, const __nv_bfloat16* __restrict__ Blo,
         const float* __restrict__ bias, const float* __restrict__ res,
         float* __restrict__ Cout,
         __nv_bfloat16* __restrict__ outHi, __nv_bfloat16* __restrict__ outLo)
{
    extern __shared__ __nv_bfloat16 sh[];
    const uint32_t shBase = (uint32_t)__cvta_generic_to_shared(sh);

    const int tid  = threadIdx.x;
    const int lane = tid & 31;
    const int warp = tid >> 5;
    const int wm   = warp >> 2;
    const int wn   = warp & 3;
    const int rowBase = blockIdx.y * 128;
    const int colBase = blockIdx.x * 128;

    const __nv_bfloat16* Ap[2] = { Ahi, Alo };
    const __nv_bfloat16* Bp[2] = { Bhi, Blo };

    float acc[4][4][4];
#pragma unroll
    for (int i = 0; i < 4; i++)
#pragma unroll
        for (int j = 0; j < 4; j++)
#pragma unroll
            for (int k = 0; k < 4; k++) acc[i][j][k] = 0.f;

    const int ntiles = K / 32;

    // ---- stage loader ----
    auto load_stage = [&](int ktile, int buf) {
        const int kt = ktile * 32;
#pragma unroll
        for (int p = 0; p < 2; p++) {
            const uint32_t aB = shBase + (uint32_t)((buf * 2 + p) * 4096) * 2;
#pragma unroll
            for (int j = 0; j < 2; j++) {
                const int idx = tid + j * 256;       // 0..511 over 128x4 chunks
                const int r   = idx >> 2;
                const int c8  = idx & 3;
                const int cs  = c8 ^ ((r >> 1) & 3);
                cp16(aB + (uint32_t)(r * 32 + cs * 8) * 2,
                     Ap[p] + (size_t)(rowBase + r) * K + kt + c8 * 8);
            }
        }
#pragma unroll
        for (int p = 0; p < 2; p++) {
            const uint32_t bB = shBase + (uint32_t)(NSTAGE * 8192 + (buf * 2 + p) * 4096) * 2;
#pragma unroll
            for (int j = 0; j < 2; j++) {
                const int idx = tid + j * 256;       // 0..511 over 32x16 chunks
                const int r   = idx >> 4;
                const int c8  = idx & 15;
                const int gc  = colBase + c8 * 8;
                const int cs  = c8 ^ (r & 7);
                cp16z(bB + (uint32_t)(r * 128 + cs * 8) * 2,
                      Bp[p] + (size_t)(kt + r) * N + gc, gc < N);
            }
        }
    };

    // prologue: stages 0 .. NSTAGE-2
    const int pre = ntiles < (NSTAGE - 1) ? ntiles : (NSTAGE - 1);
    for (int s = 0; s < pre; s++) { load_stage(s, s); cp_commit(); }

    for (int kt = 0; kt < ntiles; kt++) {
        const int nx = kt + NSTAGE - 1;
        if (nx < ntiles) load_stage(nx, nx % NSTAGE);
        cp_commit();                       // always commit (empty groups keep count)
        cp_wait2();                        // stage kt resident
        __syncthreads();

        const int buf = kt % NSTAGE;
        const uint32_t aHiB = shBase + (uint32_t)((buf * 2 + 0) * 4096) * 2;
        const uint32_t aLoB = shBase + (uint32_t)((buf * 2 + 1) * 4096) * 2;
        const uint32_t bHiB = shBase + (uint32_t)(NSTAGE * 8192 + (buf * 2 + 0) * 4096) * 2;
        const uint32_t bLoB = shBase + (uint32_t)(NSTAGE * 8192 + (buf * 2 + 1) * 4096) * 2;

#pragma unroll
        for (int s = 0; s < 2; s++) {
            uint32_t af[2][4][4];
            uint32_t bf[2][4][2];
#pragma unroll
            for (int mt = 0; mt < 4; mt++) {
                const int r  = wm * 64 + mt * 16 + (lane & 15);
                const int c  = s * 2 + (lane >> 4);
                const int cs = c ^ ((r >> 1) & 3);
                const uint32_t off = (uint32_t)(r * 32 + cs * 8) * 2;
                ldm_x4(af[0][mt][0], af[0][mt][1], af[0][mt][2], af[0][mt][3], aHiB + off);
                ldm_x4(af[1][mt][0], af[1][mt][1], af[1][mt][2], af[1][mt][3], aLoB + off);
            }
#pragma unroll
            for (int pi = 0; pi < 2; pi++) {
                const int k  = s * 16 + (lane & 15);
                const int cc = wn * 4 + (lane >> 4) + pi * 2;
                const int cs = cc ^ (k & 7);
                const uint32_t off = (uint32_t)(k * 128 + cs * 8) * 2;
                ldm_x4_t(bf[0][pi*2][0], bf[0][pi*2][1], bf[0][pi*2+1][0], bf[0][pi*2+1][1], bHiB + off);
                ldm_x4_t(bf[1][pi*2][0], bf[1][pi*2][1], bf[1][pi*2+1][0], bf[1][pi*2+1][1], bLoB + off);
            }
#pragma unroll
            for (int mt = 0; mt < 4; mt++)
#pragma unroll
                for (int nt = 0; nt < 4; nt++) {
                    mma_bf16(acc[mt][nt], af[0][mt][0], af[0][mt][1], af[0][mt][2], af[0][mt][3],
                             bf[0][nt][0], bf[0][nt][1]);
                    mma_bf16(acc[mt][nt], af[0][mt][0], af[0][mt][1], af[0][mt][2], af[0][mt][3],
                             bf[1][nt][0], bf[1][nt][1]);
                    mma_bf16(acc[mt][nt], af[1][mt][0], af[1][mt][1], af[1][mt][2], af[1][mt][3],
                             bf[0][nt][0], bf[0][nt][1]);
                }
        }
        __syncthreads();
    }

    // ---- epilogue ----
    const int g  = lane >> 2;
    const int t4 = lane & 3;
#pragma unroll
    for (int mt = 0; mt < 4; mt++) {
#pragma unroll
        for (int nt = 0; nt < 4; nt++) {
            const int col = colBase + wn * 32 + nt * 8 + t4 * 2;
            if (col >= N) continue;
            const int r0 = rowBase + wm * 64 + mt * 16 + g;
            const float2 b2 = *reinterpret_cast<const float2*>(bias + col);
            float2 o0 = make_float2(acc[mt][nt][0] + b2.x, acc[mt][nt][1] + b2.y);
            float2 o1 = make_float2(acc[mt][nt][2] + b2.x, acc[mt][nt][3] + b2.y);
            if (res) {
                float2 r2a = *reinterpret_cast<const float2*>(res + (size_t)r0 * N + col);
                float2 r2b = *reinterpret_cast<const float2*>(res + (size_t)(r0 + 8) * N + col);
                o0.x += r2a.x; o0.y += r2a.y; o1.x += r2b.x; o1.y += r2b.y;
            }
            if (RELU) {
                o0.x = fmaxf(o0.x, 0.f); o0.y = fmaxf(o0.y, 0.f);
                o1.x = fmaxf(o1.x, 0.f); o1.y = fmaxf(o1.y, 0.f);
            }
            if (SPLIT_OUT) {
                __nv_bfloat162 h0 = __floats2bfloat162_rn(o0.x, o0.y);
                __nv_bfloat162 h1 = __floats2bfloat162_rn(o1.x, o1.y);
                float2 f0 = __bfloat1622float2(h0);
                float2 f1 = __bfloat1622float2(h1);
                __nv_bfloat162 l0 = __floats2bfloat162_rn(o0.x - f0.x, o0.y - f0.y);
                __nv_bfloat162 l1 = __floats2bfloat162_rn(o1.x - f1.x, o1.y - f1.y);
                *reinterpret_cast<__nv_bfloat162*>(outHi + (size_t)r0 * N + col) = h0;
                *reinterpret_cast<__nv_bfloat162*>(outHi + (size_t)(r0 + 8) * N + col) = h1;
                *reinterpret_cast<__nv_bfloat162*>(outLo + (size_t)r0 * N + col) = l0;
                *reinterpret_cast<__nv_bfloat162*>(outLo + (size_t)(r0 + 8) * N + col) = l1;
            } else {
                *reinterpret_cast<float2*>(Cout + (size_t)r0 * N + col) = o0;
                *reinterpret_cast<float2*>(Cout + (size_t)(r0 + 8) * N + col) = o1;
            }
        }
    }
}

// ---------------------------------------------------------------------------
// fp32 -> bf16 hi/lo split helpers
// ---------------------------------------------------------------------------
__device__ __forceinline__ void split_store(__nv_bfloat16* hi, __nv_bfloat16* lo,
                                            size_t i2, float a, float b)
{
    __nv_bfloat162 h = __floats2bfloat162_rn(a, b);
    float2 f = __bfloat1622float2(h);
    __nv_bfloat162 l = __floats2bfloat162_rn(a - f.x, b - f.y);
    reinterpret_cast<__nv_bfloat162*>(hi)[i2] = h;
    reinterpret_cast<__nv_bfloat162*>(lo)[i2] = l;
}

__global__ void convert_split(const float* __restrict__ src,
                              __nv_bfloat16* __restrict__ hi,
                              __nv_bfloat16* __restrict__ lo, int n4)
{
    int i = blockIdx.x * blockDim.x + threadIdx.x;
    if (i >= n4) return;
    float4 v = reinterpret_cast<const float4*>(src)[i];
    split_store(hi, lo, (size_t)i * 2,     v.x, v.y);
    split_store(hi, lo, (size_t)i * 2 + 1, v.z, v.w);
}

__global__ void add_split(const float* __restrict__ a, const float* __restrict__ b,
                          __nv_bfloat16* __restrict__ hi, __nv_bfloat16* __restrict__ lo,
                          int n4)
{
    int i = blockIdx.x * blockDim.x + threadIdx.x;
    if (i >= n4) return;
    float4 va = reinterpret_cast<const float4*>(a)[i];
    float4 vb = reinterpret_cast<const float4*>(b)[i];
    split_store(hi, lo, (size_t)i * 2,     va.x + vb.x, va.y + vb.y);
    split_store(hi, lo, (size_t)i * 2 + 1, va.z + vb.z, va.w + vb.w);
}

__global__ void convert_weights(const float* w0, const float* w1, const float* w2,
                                const float* w3, const float* w4, const float* w5,
                                const float* w6, const float* w7, const float* w8,
                                const float* w9,
                                __nv_bfloat16* __restrict__ hi,
                                __nv_bfloat16* __restrict__ lo)
{
    int e = (blockIdx.x * blockDim.x + threadIdx.x) * 4;
    if (e >= W_TOTAL) return;
    const float* src; int base;
    if      (e < OFF_SA_AW)  { src = w0; base = OFF_SA_OFF; }
    else if (e < OFF_SA_VP)  { src = w1; base = OFF_SA_AW;  }
    else if (e < OFF_SA_OP)  { src = w2; base = OFF_SA_VP;  }
    else if (e < OFF_CA_OFF) { src = w3; base = OFF_SA_OP;  }
    else if (e < OFF_CA_AW)  { src = w4; base = OFF_CA_OFF; }
    else if (e < OFF_CA_VP)  { src = w5; base = OFF_CA_AW;  }
    else if (e < OFF_CA_OP)  { src = w6; base = OFF_CA_VP;  }
    else if (e < OFF_FFN1)   { src = w7; base = OFF_CA_OP;  }
    else if (e < OFF_FFN2)   { src = w8; base = OFF_FFN1;   }
    else                     { src = w9; base = OFF_FFN2;   }
    float4 v = *reinterpret_cast<const float4*>(src + (e - base));
    split_store(hi, lo, (size_t)e / 2,     v.x, v.y);
    split_store(hi, lo, (size_t)e / 2 + 1, v.z, v.w);
}

// ---------------------------------------------------------------------------
// Deformable sampling: one warp per (q, h); emits bf16 hi/lo planes.
// ---------------------------------------------------------------------------
__device__ __forceinline__ float fetch_corner(const float* __restrict__ vl, int xi, int yi)
{
    if (xi < 0 || xi >= Ww || yi < 0 || yi >= Hh) return 0.f;
    return vl[(yi * Ww + xi) * C];
}

template<int L>
__global__ void sampler_kernel(const float* __restrict__ v,
                               const float* __restrict__ off,
                               const float* __restrict__ awl,
                               const float* __restrict__ ref2d,
                               __nv_bfloat16* __restrict__ outHi,
                               __nv_bfloat16* __restrict__ outLo)
{
    const int w    = (blockIdx.x * blockDim.x + threadIdx.x) >> 5;
    const int lane = threadIdx.x & 31;
    if (w >= Q * NH) return;
    const int q = w / NH;
    const int h = w % NH;

    constexpr int LNP = L * NP;
    float wgt[LNP];
    const float* aw = awl + (size_t)(q * NH + h) * LNP;
    float m = -1e30f;
#pragma unroll
    for (int i = 0; i < LNP; i++) { wgt[i] = aw[i]; m = fmaxf(m, wgt[i]); }
    float s = 0.f;
#pragma unroll
    for (int i = 0; i < LNP; i++) { wgt[i] = __expf(wgt[i] - m); s += wgt[i]; }
    const float inv = 1.f / s;

    const float* offp = off + (size_t)(q * NH + h) * LNP * 2;
    float acc = 0.f;

#pragma unroll
    for (int l = 0; l < L; l++) {
        const float rx = ref2d[(q * LC + l) * 2 + 0];
        const float ry = ref2d[(q * LC + l) * 2 + 1];
        const float* vl = v + ((size_t)l * Q) * C + h * HD + lane;
#pragma unroll
        for (int p = 0; p < NP; p++) {
            const float ox = offp[(l * NP + p) * 2 + 0];
            const float oy = offp[(l * NP + p) * 2 + 1];
            const float x = (rx + ox * (1.f / (float)Ww)) * (float)Ww - 0.5f;
            const float y = (ry + oy * (1.f / (float)Hh)) * (float)Hh - 0.5f;
            const float x0f = floorf(x), y0f = floorf(y);
            const int x0 = (int)x0f, y0 = (int)y0f;
            const float tx = x - x0f, ty = y - y0f;
            const float wp = wgt[l * NP + p] * inv;

            const float c00 = fetch_corner(vl, x0,     y0);
            const float c10 = fetch_corner(vl, x0 + 1, y0);
            const float c01 = fetch_corner(vl, x0,     y0 + 1);
            const float c11 = fetch_corner(vl, x0 + 1, y0 + 1);

            const float top = c00 * (1.f - tx) + c10 * tx;
            const float bot = c01 * (1.f - tx) + c11 * tx;
            acc += wp * (top * (1.f - ty) + bot * ty);
        }
    }
    const size_t idx = (size_t)q * C + h * HD + lane;
    __nv_bfloat16 hb = __float2bfloat16(acc);
    outHi[idx] = hb;
    outLo[idx] = __float2bfloat16(acc - __bfloat162float(hb));
}

// ---------------------------------------------------------------------------
// LayerNorm: one warp per row of 256; optional bf16 split emit.
// ---------------------------------------------------------------------------
__global__ void ln_kernel(const float* __restrict__ x,
                          const float* __restrict__ g,
                          const float* __restrict__ b,
                          float* __restrict__ y,
                          __nv_bfloat16* __restrict__ yH,
                          __nv_bfloat16* __restrict__ yL)
{
    const int row  = (blockIdx.x * blockDim.x + threadIdx.x) >> 5;
    const int lane = threadIdx.x & 31;
    if (row >= Q) return;
    const float* xr = x + (size_t)row * C;
    float v[8];
    float s = 0.f;
#pragma unroll
    for (int i = 0; i < 8; i++) { v[i] = xr[lane + 32 * i]; s += v[i]; }
#pragma unroll
    for (int o = 16; o; o >>= 1) s += __shfl_xor_sync(0xffffffffu, s, o);
    const float mu = s * (1.f / (float)C);
    float s2 = 0.f;
#pragma unroll
    for (int i = 0; i < 8; i++) { const float d = v[i] - mu; s2 += d * d; }
#pragma unroll
    for (int o = 16; o; o >>= 1) s2 += __shfl_xor_sync(0xffffffffu, s2, o);
    const float rstd = rsqrtf(s2 * (1.f / (float)C) + 1e-5f);
#pragma unroll
    for (int i = 0; i < 8; i++) {
        const int c = lane + 32 * i;
        const float o = (v[i] - mu) * rstd * g[c] + b[c];
        y[(size_t)row * C + c] = o;
        if (yH) {
            __nv_bfloat16 hb = __float2bfloat16(o);
            yH[(size_t)row * C + c] = hb;
            yL[(size_t)row * C + c] = __float2bfloat16(o - __bfloat162float(hb));
        }
    }
}

__global__ void sp_kernel(const int* __restrict__ sp, float* __restrict__ o)
{
    int i = threadIdx.x;
    if (i < 4) o[i] = (float)sp[i];
}

// ---------------------------------------------------------------------------
// Driver
// ---------------------------------------------------------------------------
extern "C" void kernel_launch(void* const* d_in, const int* in_sizes, int n_in,
                              void* d_out, int out_size)
{
    (void)in_sizes; (void)n_in; (void)out_size;

    const float* query     = (const float*)d_in[0];
    const float* query_pos = (const float*)d_in[1];
    const float* value     = (const float*)d_in[2];
    const float* ref2d     = (const float*)d_in[3];
    const int*   spatial   = (const int*)  d_in[4];
    const float* sa_off_w = (const float*)d_in[5];
    const float* sa_off_b = (const float*)d_in[6];
    const float* sa_aw_w  = (const float*)d_in[7];
    const float* sa_aw_b  = (const float*)d_in[8];
    const float* sa_vp_w  = (const float*)d_in[9];
    const float* sa_vp_b  = (const float*)d_in[10];
    const float* sa_op_w  = (const float*)d_in[11];
    const float* sa_op_b  = (const float*)d_in[12];
    const float* ca_off_w = (const float*)d_in[13];
    const float* ca_off_b = (const float*)d_in[14];
    const float* ca_aw_w  = (const float*)d_in[15];
    const float* ca_aw_b  = (const float*)d_in[16];
    const float* ca_vp_w  = (const float*)d_in[17];
    const float* ca_vp_b  = (const float*)d_in[18];
    const float* ca_op_w  = (const float*)d_in[19];
    const float* ca_op_b  = (const float*)d_in[20];
    const float* ffn_w1   = (const float*)d_in[21];
    const float* ffn_b1   = (const float*)d_in[22];
    const float* ffn_w2   = (const float*)d_in[23];
    const float* ffn_b2   = (const float*)d_in[24];
    const float* ln1_g = (const float*)d_in[25];
    const float* ln1_b = (const float*)d_in[26];
    const float* ln2_g = (const float*)d_in[27];
    const float* ln2_b = (const float*)d_in[28];
    const float* ln3_g = (const float*)d_in[29];
    const float* ln3_b = (const float*)d_in[30];

    static bool attr_done = false;
    if (!attr_done) {
        cudaFuncSetAttribute(mma_gemm<false,false>,
                             cudaFuncAttributeMaxDynamicSharedMemorySize, GEMM_SMEM);
        cudaFuncSetAttribute(mma_gemm<true,true>,
                             cudaFuncAttributeMaxDynamicSharedMemorySize, GEMM_SMEM);
        attr_done = true;
    }

    float *v, *off, *aw, *x, *q1, *q2;
    __nv_bfloat16 *sH, *sL, *qH, *qL, *vH, *vL, *aH, *aL, *q2H, *q2L, *hidH, *hidL, *wH, *wL;
    cudaGetSymbolAddress((void**)&v,    g_v);
    cudaGetSymbolAddress((void**)&off,  g_off);
    cudaGetSymbolAddress((void**)&aw,   g_aw);
    cudaGetSymbolAddress((void**)&x,    g_x);
    cudaGetSymbolAddress((void**)&q1,   g_q1);
    cudaGetSymbolAddress((void**)&q2,   g_q2);
    cudaGetSymbolAddress((void**)&sH,   g_sH);   cudaGetSymbolAddress((void**)&sL, g_sL);
    cudaGetSymbolAddress((void**)&qH,   g_qH);   cudaGetSymbolAddress((void**)&qL, g_qL);
    cudaGetSymbolAddress((void**)&vH,   g_vH);   cudaGetSymbolAddress((void**)&vL, g_vL);
    cudaGetSymbolAddress((void**)&aH,   g_aH);   cudaGetSymbolAddress((void**)&aL, g_aL);
    cudaGetSymbolAddress((void**)&q2H,  g_q2H);  cudaGetSymbolAddress((void**)&q2L, g_q2L);
    cudaGetSymbolAddress((void**)&hidH, g_hidH); cudaGetSymbolAddress((void**)&hidL, g_hidL);
    cudaGetSymbolAddress((void**)&wH,   g_wH);   cudaGetSymbolAddress((void**)&wL, g_wL);

    float* out = (float*)d_out;
    const int N4 = QC / 4;
    const int CB = (N4 + 255) / 256;

    // ---------------- one-shot conversions ----------------
    convert_weights<<<(W_TOTAL/4 + 255)/256, 256>>>(
        sa_off_w, sa_aw_w, sa_vp_w, sa_op_w, ca_off_w, ca_aw_w, ca_vp_w, ca_op_w,
        ffn_w1, ffn_w2, wH, wL);
    convert_split<<<CB, 256>>>(query, qH, qL, N4);
    convert_split<<<2*CB, 256>>>(value, vH, vL, 2*N4);

    // ---------------- Self deformable attention (L = 1) ----------------
    add_split<<<CB, 256>>>(query, query_pos, sH, sL, N4);
    mma_gemm<false,false><<<dim3(2, Q/128), 256, GEMM_SMEM>>>(Q, 256, 256,
        qH, qL, wH+OFF_SA_VP, wL+OFF_SA_VP, sa_vp_b, nullptr, v, nullptr, nullptr);
    mma_gemm<false,false><<<dim3(1, Q/128), 256, GEMM_SMEM>>>(Q, 64, 256,
        sH, sL, wH+OFF_SA_OFF, wL+OFF_SA_OFF, sa_off_b, nullptr, off, nullptr, nullptr);
    mma_gemm<false,false><<<dim3(1, Q/128), 256, GEMM_SMEM>>>(Q, 32, 256,
        sH, sL, wH+OFF_SA_AW, wL+OFF_SA_AW, sa_aw_b, nullptr, aw, nullptr, nullptr);
    sampler_kernel<1><<<Q*NH/8, 256>>>(v, off, aw, ref2d, aH, aL);
    mma_gemm<false,false><<<dim3(2, Q/128), 256, GEMM_SMEM>>>(Q, 256, 256,
        aH, aL, wH+OFF_SA_OP, wL+OFF_SA_OP, sa_op_b, query, x, nullptr, nullptr);
    ln_kernel<<<Q/8, 256>>>(x, ln1_g, ln1_b, q1, nullptr, nullptr);

    // ---------------- Cross deformable attention (L = 2) ----------------
    add_split<<<CB, 256>>>(q1, query_pos, sH, sL, N4);
    mma_gemm<false,false><<<dim3(2, 2*Q/128), 256, GEMM_SMEM>>>(2*Q, 256, 256,
        vH, vL, wH+OFF_CA_VP, wL+OFF_CA_VP, ca_vp_b, nullptr, v, nullptr, nullptr);
    mma_gemm<false,false><<<dim3(1, Q/128), 256, GEMM_SMEM>>>(Q, 128, 256,
        sH, sL, wH+OFF_CA_OFF, wL+OFF_CA_OFF, ca_off_b, nullptr, off, nullptr, nullptr);
    mma_gemm<false,false><<<dim3(1, Q/128), 256, GEMM_SMEM>>>(Q, 64, 256,
        sH, sL, wH+OFF_CA_AW, wL+OFF_CA_AW, ca_aw_b, nullptr, aw, nullptr, nullptr);
    sampler_kernel<2><<<Q*NH/8, 256>>>(v, off, aw, ref2d, aH, aL);
    mma_gemm<false,false><<<dim3(2, Q/128), 256, GEMM_SMEM>>>(Q, 256, 256,
        aH, aL, wH+OFF_CA_OP, wL+OFF_CA_OP, ca_op_b, q1, x, nullptr, nullptr);
    ln_kernel<<<Q/8, 256>>>(x, ln2_g, ln2_b, q2, q2H, q2L);

    // ---------------- FFN ----------------
    mma_gemm<true,true><<<dim3(8, Q/128), 256, GEMM_SMEM>>>(Q, 1024, 256,
        q2H, q2L, wH+OFF_FFN1, wL+OFF_FFN1, ffn_b1, nullptr, nullptr, hidH, hidL);
    mma_gemm<false,false><<<dim3(2, Q/128), 256, GEMM_SMEM>>>(Q, 256, 1024,
        hidH, hidL, wH+OFF_FFN2, wL+OFF_FFN2, ffn_b2, q2, x, nullptr, nullptr);
    ln_kernel<<<Q/8, 256>>>(x, ln3_g, ln3_b, out, nullptr, nullptr);

    // ---------------- Passthrough outputs ----------------
    cudaMemcpyAsync(out + QC,   query_pos, (size_t)QC * 4,     cudaMemcpyDeviceToDevice, 0);
    cudaMemcpyAsync(out + 2*QC, value,     (size_t)2 * QC * 4, cudaMemcpyDeviceToDevice, 0);
    cudaMemcpyAsync(out + 4*QC, ref2d,     (size_t)Q*LC*2 * 4, cudaMemcpyDeviceToDevice, 0);
    sp_kernel<<<1, 4>>>(spatial, out + 4*QC + Q*LC*2);
}

// round 11
// speedup vs baseline: 2.4619x; 1.2543x over previous
#include <cuda_runtime.h>
#include <cuda_fp16.h>
#include <cstdint>

// ---------------------------------------------------------------------------
// Problem constants
// ---------------------------------------------------------------------------
constexpr int Hh  = 160;
constexpr int Ww  = 160;
constexpr int Q   = Hh * Ww;      // 25600
constexpr int C   = 256;
constexpr int NH  = 8;
constexpr int HD  = C / NH;       // 32
constexpr int NP  = 4;
constexpr int LC  = 2;
constexpr int QC  = Q * C;        // 6,553,600

// Packed weight-plane offsets (elements)
constexpr int OFF_SA_OFFAW = 0;          // [256, 96]  (off 64 | aw 32)
constexpr int OFF_SA_VP    = 24576;      // [256, 256]
constexpr int OFF_SA_OP    = 90112;      // [256, 256]
constexpr int OFF_CA_OFFAW = 155648;     // [256, 192] (off 128 | aw 64)
constexpr int OFF_CA_VP    = 204800;     // [256, 256]
constexpr int OFF_CA_OP    = 270336;     // [256, 256]
constexpr int OFF_FFN1     = 335872;     // [256, 1024]
constexpr int OFF_FFN2     = 598016;     // [1024, 256]
constexpr int W_TOTAL      = 860160;

// ---------------------------------------------------------------------------
// Scratch (device globals -- no allocations allowed)
// ---------------------------------------------------------------------------
__device__ float g_v[2 * QC];                    // projected values (fp32)
__device__ float g_offaw[Q * 192];               // packed off|aw GEMM output
__device__ float g_x [QC];
__device__ float g_q1[QC];
__device__ float g_q2[QC];
__device__ float g_biasPack[288];                // [96 SA | 192 CA]

__device__ __align__(256) __half g_qF[QC];       // fp16(query)
__device__ __align__(256) __half g_sF[QC];       // fp16(q + query_pos)
__device__ __align__(256) __half g_vF[2 * QC];   // fp16(value)
__device__ __align__(256) __half g_aF[QC];       // fp16(attn sampled)
__device__ __align__(256) __half g_q2F[QC];
__device__ __align__(256) __half g_hidF[Q * 4 * C];
__device__ __align__(256) __half g_wH[W_TOTAL], g_wL[W_TOTAL];

// ---------------------------------------------------------------------------
// PTX helpers
// ---------------------------------------------------------------------------
__device__ __forceinline__ void ldm_x4(uint32_t& r0, uint32_t& r1,
                                       uint32_t& r2, uint32_t& r3, uint32_t addr)
{
    asm volatile("ldmatrix.sync.aligned.m8n8.x4.shared.b16 {%0,%1,%2,%3}, [%4];"
                 : "=r"(r0), "=r"(r1), "=r"(r2), "=r"(r3) : "r"(addr));
}
__device__ __forceinline__ void ldm_x4_t(uint32_t& r0, uint32_t& r1,
                                         uint32_t& r2, uint32_t& r3, uint32_t addr)
{
    asm volatile("ldmatrix.sync.aligned.m8n8.x4.trans.shared.b16 {%0,%1,%2,%3}, [%4];"
                 : "=r"(r0), "=r"(r1), "=r"(r2), "=r"(r3) : "r"(addr));
}
__device__ __forceinline__ void mma_f16(float* c, uint32_t a0, uint32_t a1,
                                        uint32_t a2, uint32_t a3,
                                        uint32_t b0, uint32_t b1)
{
    asm volatile("mma.sync.aligned.m16n8k16.row.col.f32.f16.f16.f32 "
                 "{%0,%1,%2,%3}, {%4,%5,%6,%7}, {%8,%9}, {%0,%1,%2,%3};"
                 : "+f"(c[0]), "+f"(c[1]), "+f"(c[2]), "+f"(c[3])
                 : "r"(a0), "r"(a1), "r"(a2), "r"(a3), "r"(b0), "r"(b1));
}
__device__ __forceinline__ void cp16(uint32_t s, const void* g)
{
    asm volatile("cp.async.cg.shared.global [%0], [%1], 16;" :: "r"(s), "l"(g));
}
__device__ __forceinline__ void cp16z(uint32_t s, const void* g, bool valid)
{
    int sz = valid ? 16 : 0;
    asm volatile("cp.async.cg.shared.global [%0], [%1], 16, %2;"
                 :: "r"(s), "l"(g), "r"(sz));
}
__device__ __forceinline__ void cp_commit() { asm volatile("cp.async.commit_group;"); }
__device__ __forceinline__ void cp_wait2()  { asm volatile("cp.async.wait_group 2;"); }

// ---------------------------------------------------------------------------
// Tensor-core GEMM: A fp16 single plane, B fp16 hi+lo planes.
//   acc += A*Bhi + A*Blo   (exact weights, activations rounded once: ~1e-4)
// Block 128x128x32, 256 thr = 8 warps (2M x 4N), 3-stage cp.async pipeline.
// smem per stage: A 128x32 (8KB) + B 2x 32x128 (16KB) = 24KB; 3 stages = 72KB.
// ---------------------------------------------------------------------------
constexpr int NSTAGE = 3;
constexpr int GEMM_SMEM = NSTAGE * (4096 + 8192) * (int)sizeof(__half); // 73728

template<bool RELU, bool F16OUT>
__global__ void __launch_bounds__(256, 1)
mma_gemm(int M, int N, int K,
         const __half* __restrict__ A,
         const __half* __restrict__ Bhi, const __half* __restrict__ Blo,
         const float* __restrict__ bias, const float* __restrict__ res,
         float* __restrict__ Cout, __half* __restrict__ outF)
{
    extern __shared__ __half sh[];
    const uint32_t shBase = (uint32_t)__cvta_generic_to_shared(sh);

    const int tid  = threadIdx.x;
    const int lane = tid & 31;
    const int warp = tid >> 5;
    const int wm   = warp >> 2;
    const int wn   = warp & 3;
    const int rowBase = blockIdx.y * 128;
    const int colBase = blockIdx.x * 128;

    const __half* Bp[2] = { Bhi, Blo };

    float acc[4][4][4];
#pragma unroll
    for (int i = 0; i < 4; i++)
#pragma unroll
        for (int j = 0; j < 4; j++)
#pragma unroll
            for (int k = 0; k < 4; k++) acc[i][j][k] = 0.f;

    const int ntiles = K / 32;

    auto load_stage = [&](int ktile, int buf) {
        const int kt = ktile * 32;
        const uint32_t aB = shBase + (uint32_t)(buf * 4096) * 2;
#pragma unroll
        for (int j = 0; j < 2; j++) {
            const int idx = tid + j * 256;        // 512 chunks over 128x4
            const int r   = idx >> 2;
            const int c8  = idx & 3;
            const int cs  = c8 ^ ((r >> 1) & 3);
            cp16(aB + (uint32_t)(r * 32 + cs * 8) * 2,
                 A + (size_t)(rowBase + r) * K + kt + c8 * 8);
        }
#pragma unroll
        for (int p = 0; p < 2; p++) {
            const uint32_t bB = shBase + (uint32_t)(NSTAGE * 4096 + buf * 8192 + p * 4096) * 2;
#pragma unroll
            for (int j = 0; j < 2; j++) {
                const int idx = tid + j * 256;    // 512 chunks over 32x16
                const int r   = idx >> 4;
                const int c8  = idx & 15;
                const int gc  = colBase + c8 * 8;
                const int cs  = c8 ^ (r & 7);
                cp16z(bB + (uint32_t)(r * 128 + cs * 8) * 2,
                      Bp[p] + (size_t)(kt + r) * N + gc, gc < N);
            }
        }
    };

    const int pre = ntiles < (NSTAGE - 1) ? ntiles : (NSTAGE - 1);
    for (int s = 0; s < pre; s++) { load_stage(s, s); cp_commit(); }

    for (int kt = 0; kt < ntiles; kt++) {
        const int nx = kt + NSTAGE - 1;
        if (nx < ntiles) load_stage(nx, nx % NSTAGE);
        cp_commit();
        cp_wait2();
        __syncthreads();

        const int buf = kt % NSTAGE;
        const uint32_t aB   = shBase + (uint32_t)(buf * 4096) * 2;
        const uint32_t bHiB = shBase + (uint32_t)(NSTAGE * 4096 + buf * 8192) * 2;
        const uint32_t bLoB = bHiB + 4096 * 2;

#pragma unroll
        for (int s = 0; s < 2; s++) {
            uint32_t af[4][4];
            uint32_t bf[2][4][2];
#pragma unroll
            for (int mt = 0; mt < 4; mt++) {
                const int r  = wm * 64 + mt * 16 + (lane & 15);
                const int c  = s * 2 + (lane >> 4);
                const int cs = c ^ ((r >> 1) & 3);
                ldm_x4(af[mt][0], af[mt][1], af[mt][2], af[mt][3],
                       aB + (uint32_t)(r * 32 + cs * 8) * 2);
            }
#pragma unroll
            for (int pi = 0; pi < 2; pi++) {
                const int k  = s * 16 + (lane & 15);
                const int cc = wn * 4 + (lane >> 4) + pi * 2;
                const int cs = cc ^ (k & 7);
                const uint32_t off = (uint32_t)(k * 128 + cs * 8) * 2;
                ldm_x4_t(bf[0][pi*2][0], bf[0][pi*2][1], bf[0][pi*2+1][0], bf[0][pi*2+1][1], bHiB + off);
                ldm_x4_t(bf[1][pi*2][0], bf[1][pi*2][1], bf[1][pi*2+1][0], bf[1][pi*2+1][1], bLoB + off);
            }
#pragma unroll
            for (int mt = 0; mt < 4; mt++)
#pragma unroll
                for (int nt = 0; nt < 4; nt++) {
                    mma_f16(acc[mt][nt], af[mt][0], af[mt][1], af[mt][2], af[mt][3],
                            bf[0][nt][0], bf[0][nt][1]);
                    mma_f16(acc[mt][nt], af[mt][0], af[mt][1], af[mt][2], af[mt][3],
                            bf[1][nt][0], bf[1][nt][1]);
                }
        }
        __syncthreads();
    }

    // ---- epilogue ----
    const int g  = lane >> 2;
    const int t4 = lane & 3;
#pragma unroll
    for (int mt = 0; mt < 4; mt++) {
#pragma unroll
        for (int nt = 0; nt < 4; nt++) {
            const int col = colBase + wn * 32 + nt * 8 + t4 * 2;
            if (col >= N) continue;
            const int r0 = rowBase + wm * 64 + mt * 16 + g;
            const float2 b2 = *reinterpret_cast<const float2*>(bias + col);
            float2 o0 = make_float2(acc[mt][nt][0] + b2.x, acc[mt][nt][1] + b2.y);
            float2 o1 = make_float2(acc[mt][nt][2] + b2.x, acc[mt][nt][3] + b2.y);
            if (res) {
                float2 r2a = *reinterpret_cast<const float2*>(res + (size_t)r0 * N + col);
                float2 r2b = *reinterpret_cast<const float2*>(res + (size_t)(r0 + 8) * N + col);
                o0.x += r2a.x; o0.y += r2a.y; o1.x += r2b.x; o1.y += r2b.y;
            }
            if (RELU) {
                o0.x = fmaxf(o0.x, 0.f); o0.y = fmaxf(o0.y, 0.f);
                o1.x = fmaxf(o1.x, 0.f); o1.y = fmaxf(o1.y, 0.f);
            }
            if (F16OUT) {
                *reinterpret_cast<__half2*>(outF + (size_t)r0 * N + col) = __float22half2_rn(o0);
                *reinterpret_cast<__half2*>(outF + (size_t)(r0 + 8) * N + col) = __float22half2_rn(o1);
            } else {
                *reinterpret_cast<float2*>(Cout + (size_t)r0 * N + col) = o0;
                *reinterpret_cast<float2*>(Cout + (size_t)(r0 + 8) * N + col) = o1;
            }
        }
    }
}

// ---------------------------------------------------------------------------
// Weight conversion: fp32 -> packed fp16 hi/lo planes (per-element, one pass).
// ---------------------------------------------------------------------------
__global__ void convert_weights(const float* __restrict__ sa_off_w, const float* __restrict__ sa_aw_w,
                                const float* __restrict__ sa_vp_w,  const float* __restrict__ sa_op_w,
                                const float* __restrict__ ca_off_w, const float* __restrict__ ca_aw_w,
                                const float* __restrict__ ca_vp_w,  const float* __restrict__ ca_op_w,
                                const float* __restrict__ ffn_w1,   const float* __restrict__ ffn_w2,
                                __half* __restrict__ hi, __half* __restrict__ lo)
{
    int e = blockIdx.x * blockDim.x + threadIdx.x;
    if (e >= W_TOTAL) return;
    float val;
    if (e < OFF_SA_VP) {                       // SA off|aw packed [256,96]
        int r = e / 96, c = e % 96;
        val = (c < 64) ? sa_off_w[r * 64 + c] : sa_aw_w[r * 32 + (c - 64)];
    } else if (e < OFF_SA_OP)    val = sa_vp_w[e - OFF_SA_VP];
    else if (e < OFF_CA_OFFAW)   val = sa_op_w[e - OFF_SA_OP];
    else if (e < OFF_CA_VP) {                  // CA off|aw packed [256,192]
        int t = e - OFF_CA_OFFAW;
        int r = t / 192, c = t % 192;
        val = (c < 128) ? ca_off_w[r * 128 + c] : ca_aw_w[r * 64 + (c - 128)];
    } else if (e < OFF_CA_OP)    val = ca_vp_w[e - OFF_CA_VP];
    else if (e < OFF_FFN1)       val = ca_op_w[e - OFF_CA_OP];
    else if (e < OFF_FFN2)       val = ffn_w1[e - OFF_FFN1];
    else                         val = ffn_w2[e - OFF_FFN2];
    __half h = __float2half_rn(val);
    hi[e] = h;
    lo[e] = __float2half_rn(val - __half2float(h));
}

__global__ void pack_bias(const float* __restrict__ sa_off_b, const float* __restrict__ sa_aw_b,
                          const float* __restrict__ ca_off_b, const float* __restrict__ ca_aw_b,
                          float* __restrict__ bp)
{
    int i = threadIdx.x;
    if (i < 64)        bp[i] = sa_off_b[i];
    else if (i < 96)   bp[i] = sa_aw_b[i - 64];
    else if (i < 224)  bp[i] = ca_off_b[i - 96];
    else if (i < 288)  bp[i] = ca_aw_b[i - 224];
}

// query -> fp16, (query + query_pos) -> fp16
__global__ void prep_qsum(const float* __restrict__ a, const float* __restrict__ b,
                          __half* __restrict__ qF, __half* __restrict__ sF, int n4)
{
    int i = blockIdx.x * blockDim.x + threadIdx.x;
    if (i >= n4) return;
    float4 va = reinterpret_cast<const float4*>(a)[i];
    float4 vb = reinterpret_cast<const float4*>(b)[i];
    __half2* q2 = reinterpret_cast<__half2*>(qF);
    __half2* s2 = reinterpret_cast<__half2*>(sF);
    q2[i*2]   = __float22half2_rn(make_float2(va.x, va.y));
    q2[i*2+1] = __float22half2_rn(make_float2(va.z, va.w));
    s2[i*2]   = __float22half2_rn(make_float2(va.x + vb.x, va.y + vb.y));
    s2[i*2+1] = __float22half2_rn(make_float2(va.z + vb.z, va.w + vb.w));
}

__global__ void convert_f16(const float* __restrict__ src, __half* __restrict__ dst, int n4)
{
    int i = blockIdx.x * blockDim.x + threadIdx.x;
    if (i >= n4) return;
    float4 v = reinterpret_cast<const float4*>(src)[i];
    __half2* d2 = reinterpret_cast<__half2*>(dst);
    d2[i*2]   = __float22half2_rn(make_float2(v.x, v.y));
    d2[i*2+1] = __float22half2_rn(make_float2(v.z, v.w));
}

// ---------------------------------------------------------------------------
// Deformable sampling: one warp per (q, h), packed off|aw input, fp16 output.
// ---------------------------------------------------------------------------
__device__ __forceinline__ float fetch_corner(const float* __restrict__ vl, int xi, int yi)
{
    if (xi < 0 || xi >= Ww || yi < 0 || yi >= Hh) return 0.f;
    return vl[(yi * Ww + xi) * C];
}

template<int L>
__global__ void sampler_kernel(const float* __restrict__ v,
                               const float* __restrict__ offaw,   // [Q, 96L?] packed
                               const float* __restrict__ ref2d,
                               __half* __restrict__ outF)
{
    const int w    = (blockIdx.x * blockDim.x + threadIdx.x) >> 5;
    const int lane = threadIdx.x & 31;
    if (w >= Q * NH) return;
    const int q = w / NH;
    const int h = w % NH;

    constexpr int LNP = L * NP;
    constexpr int RS  = L * 96;          // row stride: 96 (SA) / 192 (CA)
    const float* row = offaw + (size_t)q * RS;
    const float* awp = row + 64 * L + h * LNP;
    const float* offp = row + h * LNP * 2;

    float wgt[LNP];
    float m = -1e30f;
#pragma unroll
    for (int i = 0; i < LNP; i++) { wgt[i] = awp[i]; m = fmaxf(m, wgt[i]); }
    float s = 0.f;
#pragma unroll
    for (int i = 0; i < LNP; i++) { wgt[i] = __expf(wgt[i] - m); s += wgt[i]; }
    const float inv = 1.f / s;

    float acc = 0.f;
#pragma unroll
    for (int l = 0; l < L; l++) {
        const float rx = ref2d[(q * LC + l) * 2 + 0];
        const float ry = ref2d[(q * LC + l) * 2 + 1];
        const float* vl = v + ((size_t)l * Q) * C + h * HD + lane;
#pragma unroll
        for (int p = 0; p < NP; p++) {
            const float ox = offp[(l * NP + p) * 2 + 0];
            const float oy = offp[(l * NP + p) * 2 + 1];
            const float x = (rx + ox * (1.f / (float)Ww)) * (float)Ww - 0.5f;
            const float y = (ry + oy * (1.f / (float)Hh)) * (float)Hh - 0.5f;
            const float x0f = floorf(x), y0f = floorf(y);
            const int x0 = (int)x0f, y0 = (int)y0f;
            const float tx = x - x0f, ty = y - y0f;
            const float wp = wgt[l * NP + p] * inv;

            const float c00 = fetch_corner(vl, x0,     y0);
            const float c10 = fetch_corner(vl, x0 + 1, y0);
            const float c01 = fetch_corner(vl, x0,     y0 + 1);
            const float c11 = fetch_corner(vl, x0 + 1, y0 + 1);

            const float top = c00 * (1.f - tx) + c10 * tx;
            const float bot = c01 * (1.f - tx) + c11 * tx;
            acc += wp * (top * (1.f - ty) + bot * ty);
        }
    }
    outF[(size_t)q * C + h * HD + lane] = __float2half_rn(acc);
}

// ---------------------------------------------------------------------------
// LayerNorm: one warp per row; optional fused (y + addIn) -> fp16 plane.
// ---------------------------------------------------------------------------
__global__ void ln_kernel(const float* __restrict__ x,
                          const float* __restrict__ g,
                          const float* __restrict__ b,
                          float* __restrict__ y,
                          const float* __restrict__ addIn,
                          __half* __restrict__ yF)
{
    const int row  = (blockIdx.x * blockDim.x + threadIdx.x) >> 5;
    const int lane = threadIdx.x & 31;
    if (row >= Q) return;
    const float* xr = x + (size_t)row * C;
    float v[8];
    float s = 0.f;
#pragma unroll
    for (int i = 0; i < 8; i++) { v[i] = xr[lane + 32 * i]; s += v[i]; }
#pragma unroll
    for (int o = 16; o; o >>= 1) s += __shfl_xor_sync(0xffffffffu, s, o);
    const float mu = s * (1.f / (float)C);
    float s2 = 0.f;
#pragma unroll
    for (int i = 0; i < 8; i++) { const float d = v[i] - mu; s2 += d * d; }
#pragma unroll
    for (int o = 16; o; o >>= 1) s2 += __shfl_xor_sync(0xffffffffu, s2, o);
    const float rstd = rsqrtf(s2 * (1.f / (float)C) + 1e-5f);
#pragma unroll
    for (int i = 0; i < 8; i++) {
        const int c = lane + 32 * i;
        const float o = (v[i] - mu) * rstd * g[c] + b[c];
        y[(size_t)row * C + c] = o;
        if (yF) {
            const float a = addIn ? addIn[(size_t)row * C + c] : 0.f;
            yF[(size_t)row * C + c] = __float2half_rn(o + a);
        }
    }
}

__global__ void sp_kernel(const int* __restrict__ sp, float* __restrict__ o)
{
    int i = threadIdx.x;
    if (i < 4) o[i] = (float)sp[i];
}

// ---------------------------------------------------------------------------
// Driver
// ---------------------------------------------------------------------------
extern "C" void kernel_launch(void* const* d_in, const int* in_sizes, int n_in,
                              void* d_out, int out_size)
{
    (void)in_sizes; (void)n_in; (void)out_size;

    const float* query     = (const float*)d_in[0];
    const float* query_pos = (const float*)d_in[1];
    const float* value     = (const float*)d_in[2];
    const float* ref2d     = (const float*)d_in[3];
    const int*   spatial   = (const int*)  d_in[4];
    const float* sa_off_w = (const float*)d_in[5];
    const float* sa_off_b = (const float*)d_in[6];
    const float* sa_aw_w  = (const float*)d_in[7];
    const float* sa_aw_b  = (const float*)d_in[8];
    const float* sa_vp_w  = (const float*)d_in[9];
    const float* sa_vp_b  = (const float*)d_in[10];
    const float* sa_op_w  = (const float*)d_in[11];
    const float* sa_op_b  = (const float*)d_in[12];
    const float* ca_off_w = (const float*)d_in[13];
    const float* ca_off_b = (const float*)d_in[14];
    const float* ca_aw_w  = (const float*)d_in[15];
    const float* ca_aw_b  = (const float*)d_in[16];
    const float* ca_vp_w  = (const float*)d_in[17];
    const float* ca_vp_b  = (const float*)d_in[18];
    const float* ca_op_w  = (const float*)d_in[19];
    const float* ca_op_b  = (const float*)d_in[20];
    const float* ffn_w1   = (const float*)d_in[21];
    const float* ffn_b1   = (const float*)d_in[22];
    const float* ffn_w2   = (const float*)d_in[23];
    const float* ffn_b2   = (const float*)d_in[24];
    const float* ln1_g = (const float*)d_in[25];
    const float* ln1_b = (const float*)d_in[26];
    const float* ln2_g = (const float*)d_in[27];
    const float* ln2_b = (const float*)d_in[28];
    const float* ln3_g = (const float*)d_in[29];
    const float* ln3_b = (const float*)d_in[30];

    static bool attr_done = false;
    if (!attr_done) {
        cudaFuncSetAttribute(mma_gemm<false,false>,
                             cudaFuncAttributeMaxDynamicSharedMemorySize, GEMM_SMEM);
        cudaFuncSetAttribute(mma_gemm<false,true>,
                             cudaFuncAttributeMaxDynamicSharedMemorySize, GEMM_SMEM);
        cudaFuncSetAttribute(mma_gemm<true,true>,
                             cudaFuncAttributeMaxDynamicSharedMemorySize, GEMM_SMEM);
        attr_done = true;
    }

    float *v, *offaw, *x, *q1, *q2, *biasP;
    __half *qF, *sF, *vF, *aF, *q2F, *hidF, *wH, *wL;
    cudaGetSymbolAddress((void**)&v,     g_v);
    cudaGetSymbolAddress((void**)&offaw, g_offaw);
    cudaGetSymbolAddress((void**)&x,     g_x);
    cudaGetSymbolAddress((void**)&q1,    g_q1);
    cudaGetSymbolAddress((void**)&q2,    g_q2);
    cudaGetSymbolAddress((void**)&biasP, g_biasPack);
    cudaGetSymbolAddress((void**)&qF,    g_qF);
    cudaGetSymbolAddress((void**)&sF,    g_sF);
    cudaGetSymbolAddress((void**)&vF,    g_vF);
    cudaGetSymbolAddress((void**)&aF,    g_aF);
    cudaGetSymbolAddress((void**)&q2F,   g_q2F);
    cudaGetSymbolAddress((void**)&hidF,  g_hidF);
    cudaGetSymbolAddress((void**)&wH,    g_wH);
    cudaGetSymbolAddress((void**)&wL,    g_wL);

    float* out = (float*)d_out;
    const int N4 = QC / 4;
    const int CB = (N4 + 255) / 256;

    // ---------------- conversions ----------------
    convert_weights<<<(W_TOTAL + 255)/256, 256>>>(
        sa_off_w, sa_aw_w, sa_vp_w, sa_op_w, ca_off_w, ca_aw_w, ca_vp_w, ca_op_w,
        ffn_w1, ffn_w2, wH, wL);
    pack_bias<<<1, 288>>>(sa_off_b, sa_aw_b, ca_off_b, ca_aw_b, biasP);
    prep_qsum<<<CB, 256>>>(query, query_pos, qF, sF, N4);
    convert_f16<<<2*CB, 256>>>(value, vF, 2*N4);

    // ---------------- Self deformable attention (L = 1) ----------------
    mma_gemm<false,false><<<dim3(2, Q/128), 256, GEMM_SMEM>>>(Q, 256, 256,
        qF, wH+OFF_SA_VP, wL+OFF_SA_VP, sa_vp_b, nullptr, v, nullptr);
    mma_gemm<false,false><<<dim3(1, Q/128), 256, GEMM_SMEM>>>(Q, 96, 256,
        sF, wH+OFF_SA_OFFAW, wL+OFF_SA_OFFAW, biasP, nullptr, offaw, nullptr);
    sampler_kernel<1><<<Q*NH/8, 256>>>(v, offaw, ref2d, aF);
    mma_gemm<false,false><<<dim3(2, Q/128), 256, GEMM_SMEM>>>(Q, 256, 256,
        aF, wH+OFF_SA_OP, wL+OFF_SA_OP, sa_op_b, query, x, nullptr);
    ln_kernel<<<Q/8, 256>>>(x, ln1_g, ln1_b, q1, query_pos, sF);

    // ---------------- Cross deformable attention (L = 2) ----------------
    mma_gemm<false,false><<<dim3(2, 2*Q/128), 256, GEMM_SMEM>>>(2*Q, 256, 256,
        vF, wH+OFF_CA_VP, wL+OFF_CA_VP, ca_vp_b, nullptr, v, nullptr);
    mma_gemm<false,false><<<dim3(2, Q/128), 256, GEMM_SMEM>>>(Q, 192, 256,
        sF, wH+OFF_CA_OFFAW, wL+OFF_CA_OFFAW, biasP + 96, nullptr, offaw, nullptr);
    sampler_kernel<2><<<Q*NH/8, 256>>>(v, offaw, ref2d, aF);
    mma_gemm<false,false><<<dim3(2, Q/128), 256, GEMM_SMEM>>>(Q, 256, 256,
        aF, wH+OFF_CA_OP, wL+OFF_CA_OP, ca_op_b, q1, x, nullptr);
    ln_kernel<<<Q/8, 256>>>(x, ln2_g, ln2_b, q2, nullptr, q2F);

    // ---------------- FFN ----------------
    mma_gemm<true,true><<<dim3(8, Q/128), 256, GEMM_SMEM>>>(Q, 1024, 256,
        q2F, wH+OFF_FFN1, wL+OFF_FFN1, ffn_b1, nullptr, nullptr, hidF);
    mma_gemm<false,false><<<dim3(2, Q/128), 256, GEMM_SMEM>>>(Q, 256, 1024,
        hidF, wH+OFF_FFN2, wL+OFF_FFN2, ffn_b2, q2, x, nullptr);
    ln_kernel<<<Q/8, 256>>>(x, ln3_g, ln3_b, out, nullptr, nullptr);

    // ---------------- Passthrough outputs ----------------
    cudaMemcpyAsync(out + QC,   query_pos, (size_t)QC * 4,     cudaMemcpyDeviceToDevice, 0);
    cudaMemcpyAsync(out + 2*QC, value,     (size_t)2 * QC * 4, cudaMemcpyDeviceToDevice, 0);
    cudaMemcpyAsync(out + 4*QC, ref2d,     (size_t)Q*LC*2 * 4, cudaMemcpyDeviceToDevice, 0);
    sp_kernel<<<1, 4>>>(spatial, out + 4*QC + Q*LC*2);
}

// round 12
// speedup vs baseline: 2.8731x; 1.1670x over previous
#include <cuda_runtime.h>
#include <cuda_fp16.h>
#include <cstdint>

// ---------------------------------------------------------------------------
// Problem constants
// ---------------------------------------------------------------------------
constexpr int Hh  = 160;
constexpr int Ww  = 160;
constexpr int Q   = Hh * Ww;      // 25600
constexpr int C   = 256;
constexpr int NH  = 8;
constexpr int HD  = C / NH;       // 32
constexpr int NP  = 4;
constexpr int LC  = 2;
constexpr int QC  = Q * C;        // 6,553,600

// Packed weight-plane offsets (elements)
constexpr int OFF_SA_OFFAW = 0;          // [256, 96]  (off 64 | aw 32)
constexpr int OFF_SA_VP    = 24576;      // [256, 256]
constexpr int OFF_SA_OP    = 90112;      // [256, 256]
constexpr int OFF_CA_OFFAW = 155648;     // [256, 192] (off 128 | aw 64)
constexpr int OFF_CA_VP    = 204800;     // [256, 256]
constexpr int OFF_CA_OP    = 270336;     // [256, 256]
constexpr int OFF_FFN1     = 335872;     // [256, 1024]
constexpr int OFF_FFN2     = 598016;     // [1024, 256]
constexpr int W_TOTAL      = 860160;

// ---------------------------------------------------------------------------
// Scratch (device globals -- no allocations allowed)
// ---------------------------------------------------------------------------
__device__ float g_offaw[Q * 192];               // packed off|aw GEMM output
__device__ float g_x [QC];
__device__ float g_q1[QC];
__device__ float g_q2[QC];
__device__ float g_biasPack[288];                // [96 SA | 192 CA]

__device__ __align__(256) __half g_qF[QC];       // fp16(query)
__device__ __align__(256) __half g_sF[QC];       // fp16(q + query_pos)
__device__ __align__(256) __half g_vF[2 * QC];   // fp16(value)
__device__ __align__(256) __half g_vpF[2 * QC];  // fp16(projected value)
__device__ __align__(256) __half g_aF[QC];       // fp16(attn sampled)
__device__ __align__(256) __half g_q2F[QC];
__device__ __align__(256) __half g_hidF[Q * 4 * C];
__device__ __align__(256) __half g_wF[W_TOTAL];

// ---------------------------------------------------------------------------
// PTX helpers
// ---------------------------------------------------------------------------
__device__ __forceinline__ void ldm_x4(uint32_t& r0, uint32_t& r1,
                                       uint32_t& r2, uint32_t& r3, uint32_t addr)
{
    asm volatile("ldmatrix.sync.aligned.m8n8.x4.shared.b16 {%0,%1,%2,%3}, [%4];"
                 : "=r"(r0), "=r"(r1), "=r"(r2), "=r"(r3) : "r"(addr));
}
__device__ __forceinline__ void ldm_x4_t(uint32_t& r0, uint32_t& r1,
                                         uint32_t& r2, uint32_t& r3, uint32_t addr)
{
    asm volatile("ldmatrix.sync.aligned.m8n8.x4.trans.shared.b16 {%0,%1,%2,%3}, [%4];"
                 : "=r"(r0), "=r"(r1), "=r"(r2), "=r"(r3) : "r"(addr));
}
__device__ __forceinline__ void mma_f16(float* c, uint32_t a0, uint32_t a1,
                                        uint32_t a2, uint32_t a3,
                                        uint32_t b0, uint32_t b1)
{
    asm volatile("mma.sync.aligned.m16n8k16.row.col.f32.f16.f16.f32 "
                 "{%0,%1,%2,%3}, {%4,%5,%6,%7}, {%8,%9}, {%0,%1,%2,%3};"
                 : "+f"(c[0]), "+f"(c[1]), "+f"(c[2]), "+f"(c[3])
                 : "r"(a0), "r"(a1), "r"(a2), "r"(a3), "r"(b0), "r"(b1));
}
__device__ __forceinline__ void cp16(uint32_t s, const void* g)
{
    asm volatile("cp.async.cg.shared.global [%0], [%1], 16;" :: "r"(s), "l"(g));
}
__device__ __forceinline__ void cp16z(uint32_t s, const void* g, bool valid)
{
    int sz = valid ? 16 : 0;
    asm volatile("cp.async.cg.shared.global [%0], [%1], 16, %2;"
                 :: "r"(s), "l"(g), "r"(sz));
}
__device__ __forceinline__ void cp_commit() { asm volatile("cp.async.commit_group;"); }
__device__ __forceinline__ void cp_wait3()  { asm volatile("cp.async.wait_group 3;"); }

// ---------------------------------------------------------------------------
// Tensor-core GEMM: A fp16, B fp16 (single planes).
// Block 128x128x32, 256 thr = 8 warps (2M x 4N), 4-stage cp.async pipeline.
// smem per stage: A 128x32 (8KB) + B 32x128 (8KB); 4 stages = 64KB.
// ---------------------------------------------------------------------------
constexpr int NSTAGE = 4;
constexpr int GEMM_SMEM = NSTAGE * 8192 * (int)sizeof(__half); // 65536

template<bool RELU, bool F16OUT>
__global__ void __launch_bounds__(256, 1)
mma_gemm(int M, int N, int K,
         const __half* __restrict__ A, const __half* __restrict__ B,
         const float* __restrict__ bias, const float* __restrict__ res,
         float* __restrict__ Cout, __half* __restrict__ outF)
{
    extern __shared__ __half sh[];
    const uint32_t shBase = (uint32_t)__cvta_generic_to_shared(sh);

    const int tid  = threadIdx.x;
    const int lane = tid & 31;
    const int warp = tid >> 5;
    const int wm   = warp >> 2;
    const int wn   = warp & 3;
    const int rowBase = blockIdx.y * 128;
    const int colBase = blockIdx.x * 128;

    float acc[4][4][4];
#pragma unroll
    for (int i = 0; i < 4; i++)
#pragma unroll
        for (int j = 0; j < 4; j++)
#pragma unroll
            for (int k = 0; k < 4; k++) acc[i][j][k] = 0.f;

    const int ntiles = K / 32;

    auto load_stage = [&](int ktile, int buf) {
        const int kt = ktile * 32;
        const uint32_t aB = shBase + (uint32_t)(buf * 4096) * 2;
#pragma unroll
        for (int j = 0; j < 2; j++) {
            const int idx = tid + j * 256;        // 512 chunks over 128x4
            const int r   = idx >> 2;
            const int c8  = idx & 3;
            const int cs  = c8 ^ ((r >> 1) & 3);
            cp16(aB + (uint32_t)(r * 32 + cs * 8) * 2,
                 A + (size_t)(rowBase + r) * K + kt + c8 * 8);
        }
        const uint32_t bB = shBase + (uint32_t)(NSTAGE * 4096 + buf * 4096) * 2;
#pragma unroll
        for (int j = 0; j < 2; j++) {
            const int idx = tid + j * 256;        // 512 chunks over 32x16
            const int r   = idx >> 4;
            const int c8  = idx & 15;
            const int gc  = colBase + c8 * 8;
            const int cs  = c8 ^ (r & 7);
            cp16z(bB + (uint32_t)(r * 128 + cs * 8) * 2,
                  B + (size_t)(kt + r) * N + gc, gc < N);
        }
    };

    const int pre = ntiles < (NSTAGE - 1) ? ntiles : (NSTAGE - 1);
    for (int s = 0; s < pre; s++) { load_stage(s, s); cp_commit(); }

    for (int kt = 0; kt < ntiles; kt++) {
        const int nx = kt + NSTAGE - 1;
        if (nx < ntiles) load_stage(nx, nx % NSTAGE);
        cp_commit();
        cp_wait3();
        __syncthreads();

        const int buf = kt % NSTAGE;
        const uint32_t aB = shBase + (uint32_t)(buf * 4096) * 2;
        const uint32_t bB = shBase + (uint32_t)(NSTAGE * 4096 + buf * 4096) * 2;

#pragma unroll
        for (int s = 0; s < 2; s++) {
            uint32_t af[4][4];
            uint32_t bf[4][2];
#pragma unroll
            for (int mt = 0; mt < 4; mt++) {
                const int r  = wm * 64 + mt * 16 + (lane & 15);
                const int c  = s * 2 + (lane >> 4);
                const int cs = c ^ ((r >> 1) & 3);
                ldm_x4(af[mt][0], af[mt][1], af[mt][2], af[mt][3],
                       aB + (uint32_t)(r * 32 + cs * 8) * 2);
            }
#pragma unroll
            for (int pi = 0; pi < 2; pi++) {
                const int k  = s * 16 + (lane & 15);
                const int cc = wn * 4 + (lane >> 4) + pi * 2;
                const int cs = cc ^ (k & 7);
                ldm_x4_t(bf[pi*2][0], bf[pi*2][1], bf[pi*2+1][0], bf[pi*2+1][1],
                         bB + (uint32_t)(k * 128 + cs * 8) * 2);
            }
#pragma unroll
            for (int mt = 0; mt < 4; mt++)
#pragma unroll
                for (int nt = 0; nt < 4; nt++)
                    mma_f16(acc[mt][nt], af[mt][0], af[mt][1], af[mt][2], af[mt][3],
                            bf[nt][0], bf[nt][1]);
        }
        __syncthreads();
    }

    // ---- epilogue ----
    const int g  = lane >> 2;
    const int t4 = lane & 3;
#pragma unroll
    for (int mt = 0; mt < 4; mt++) {
#pragma unroll
        for (int nt = 0; nt < 4; nt++) {
            const int col = colBase + wn * 32 + nt * 8 + t4 * 2;
            if (col >= N) continue;
            const int r0 = rowBase + wm * 64 + mt * 16 + g;
            const float2 b2 = *reinterpret_cast<const float2*>(bias + col);
            float2 o0 = make_float2(acc[mt][nt][0] + b2.x, acc[mt][nt][1] + b2.y);
            float2 o1 = make_float2(acc[mt][nt][2] + b2.x, acc[mt][nt][3] + b2.y);
            if (res) {
                float2 r2a = *reinterpret_cast<const float2*>(res + (size_t)r0 * N + col);
                float2 r2b = *reinterpret_cast<const float2*>(res + (size_t)(r0 + 8) * N + col);
                o0.x += r2a.x; o0.y += r2a.y; o1.x += r2b.x; o1.y += r2b.y;
            }
            if (RELU) {
                o0.x = fmaxf(o0.x, 0.f); o0.y = fmaxf(o0.y, 0.f);
                o1.x = fmaxf(o1.x, 0.f); o1.y = fmaxf(o1.y, 0.f);
            }
            if (F16OUT) {
                *reinterpret_cast<__half2*>(outF + (size_t)r0 * N + col) = __float22half2_rn(o0);
                *reinterpret_cast<__half2*>(outF + (size_t)(r0 + 8) * N + col) = __float22half2_rn(o1);
            } else {
                *reinterpret_cast<float2*>(Cout + (size_t)r0 * N + col) = o0;
                *reinterpret_cast<float2*>(Cout + (size_t)(r0 + 8) * N + col) = o1;
            }
        }
    }
}

// ---------------------------------------------------------------------------
// Weight conversion: fp32 -> packed fp16 plane.
// ---------------------------------------------------------------------------
__global__ void convert_weights(const float* __restrict__ sa_off_w, const float* __restrict__ sa_aw_w,
                                const float* __restrict__ sa_vp_w,  const float* __restrict__ sa_op_w,
                                const float* __restrict__ ca_off_w, const float* __restrict__ ca_aw_w,
                                const float* __restrict__ ca_vp_w,  const float* __restrict__ ca_op_w,
                                const float* __restrict__ ffn_w1,   const float* __restrict__ ffn_w2,
                                __half* __restrict__ wf)
{
    int e = blockIdx.x * blockDim.x + threadIdx.x;
    if (e >= W_TOTAL) return;
    float val;
    if (e < OFF_SA_VP) {                       // SA off|aw packed [256,96]
        int r = e / 96, c = e % 96;
        val = (c < 64) ? sa_off_w[r * 64 + c] : sa_aw_w[r * 32 + (c - 64)];
    } else if (e < OFF_SA_OP)    val = sa_vp_w[e - OFF_SA_VP];
    else if (e < OFF_CA_OFFAW)   val = sa_op_w[e - OFF_SA_OP];
    else if (e < OFF_CA_VP) {                  // CA off|aw packed [256,192]
        int t = e - OFF_CA_OFFAW;
        int r = t / 192, c = t % 192;
        val = (c < 128) ? ca_off_w[r * 128 + c] : ca_aw_w[r * 64 + (c - 128)];
    } else if (e < OFF_CA_OP)    val = ca_vp_w[e - OFF_CA_VP];
    else if (e < OFF_FFN1)       val = ca_op_w[e - OFF_CA_OP];
    else if (e < OFF_FFN2)       val = ffn_w1[e - OFF_FFN1];
    else                         val = ffn_w2[e - OFF_FFN2];
    wf[e] = __float2half_rn(val);
}

__global__ void pack_bias(const float* __restrict__ sa_off_b, const float* __restrict__ sa_aw_b,
                          const float* __restrict__ ca_off_b, const float* __restrict__ ca_aw_b,
                          float* __restrict__ bp)
{
    int i = threadIdx.x;
    if (i < 64)        bp[i] = sa_off_b[i];
    else if (i < 96)   bp[i] = sa_aw_b[i - 64];
    else if (i < 224)  bp[i] = ca_off_b[i - 96];
    else if (i < 288)  bp[i] = ca_aw_b[i - 224];
}

// query -> fp16, (query + query_pos) -> fp16
__global__ void prep_qsum(const float* __restrict__ a, const float* __restrict__ b,
                          __half* __restrict__ qF, __half* __restrict__ sF, int n4)
{
    int i = blockIdx.x * blockDim.x + threadIdx.x;
    if (i >= n4) return;
    float4 va = reinterpret_cast<const float4*>(a)[i];
    float4 vb = reinterpret_cast<const float4*>(b)[i];
    __half2* q2 = reinterpret_cast<__half2*>(qF);
    __half2* s2 = reinterpret_cast<__half2*>(sF);
    q2[i*2]   = __float22half2_rn(make_float2(va.x, va.y));
    q2[i*2+1] = __float22half2_rn(make_float2(va.z, va.w));
    s2[i*2]   = __float22half2_rn(make_float2(va.x + vb.x, va.y + vb.y));
    s2[i*2+1] = __float22half2_rn(make_float2(va.z + vb.z, va.w + vb.w));
}

__global__ void convert_f16(const float* __restrict__ src, __half* __restrict__ dst, int n4)
{
    int i = blockIdx.x * blockDim.x + threadIdx.x;
    if (i >= n4) return;
    float4 v = reinterpret_cast<const float4*>(src)[i];
    __half2* d2 = reinterpret_cast<__half2*>(dst);
    d2[i*2]   = __float22half2_rn(make_float2(v.x, v.y));
    d2[i*2+1] = __float22half2_rn(make_float2(v.z, v.w));
}

// ---------------------------------------------------------------------------
// Deformable sampling: one warp per (q, h), fp16 value planes, fp16 output.
// ---------------------------------------------------------------------------
__device__ __forceinline__ float fetch_corner(const __half* __restrict__ vl, int xi, int yi)
{
    if (xi < 0 || xi >= Ww || yi < 0 || yi >= Hh) return 0.f;
    return __half2float(vl[(yi * Ww + xi) * C]);
}

template<int L>
__global__ void sampler_kernel(const __half* __restrict__ v,
                               const float* __restrict__ offaw,
                               const float* __restrict__ ref2d,
                               __half* __restrict__ outF)
{
    const int w    = (blockIdx.x * blockDim.x + threadIdx.x) >> 5;
    const int lane = threadIdx.x & 31;
    if (w >= Q * NH) return;
    const int q = w / NH;
    const int h = w % NH;

    constexpr int LNP = L * NP;
    constexpr int RS  = L * 96;          // row stride: 96 (SA) / 192 (CA)
    const float* row = offaw + (size_t)q * RS;
    const float* awp = row + 64 * L + h * LNP;
    const float* offp = row + h * LNP * 2;

    float wgt[LNP];
    float m = -1e30f;
#pragma unroll
    for (int i = 0; i < LNP; i++) { wgt[i] = awp[i]; m = fmaxf(m, wgt[i]); }
    float s = 0.f;
#pragma unroll
    for (int i = 0; i < LNP; i++) { wgt[i] = __expf(wgt[i] - m); s += wgt[i]; }
    const float inv = 1.f / s;

    float acc = 0.f;
#pragma unroll
    for (int l = 0; l < L; l++) {
        const float rx = ref2d[(q * LC + l) * 2 + 0];
        const float ry = ref2d[(q * LC + l) * 2 + 1];
        const __half* vl = v + ((size_t)l * Q) * C + h * HD + lane;
#pragma unroll
        for (int p = 0; p < NP; p++) {
            const float ox = offp[(l * NP + p) * 2 + 0];
            const float oy = offp[(l * NP + p) * 2 + 1];
            const float x = (rx + ox * (1.f / (float)Ww)) * (float)Ww - 0.5f;
            const float y = (ry + oy * (1.f / (float)Hh)) * (float)Hh - 0.5f;
            const float x0f = floorf(x), y0f = floorf(y);
            const int x0 = (int)x0f, y0 = (int)y0f;
            const float tx = x - x0f, ty = y - y0f;
            const float wp = wgt[l * NP + p] * inv;

            const float c00 = fetch_corner(vl, x0,     y0);
            const float c10 = fetch_corner(vl, x0 + 1, y0);
            const float c01 = fetch_corner(vl, x0,     y0 + 1);
            const float c11 = fetch_corner(vl, x0 + 1, y0 + 1);

            const float top = c00 * (1.f - tx) + c10 * tx;
            const float bot = c01 * (1.f - tx) + c11 * tx;
            acc += wp * (top * (1.f - ty) + bot * ty);
        }
    }
    outF[(size_t)q * C + h * HD + lane] = __float2half_rn(acc);
}

// ---------------------------------------------------------------------------
// LayerNorm: one warp per row; optional fused (y + addIn) -> fp16 plane.
// ---------------------------------------------------------------------------
__global__ void ln_kernel(const float* __restrict__ x,
                          const float* __restrict__ g,
                          const float* __restrict__ b,
                          float* __restrict__ y,
                          const float* __restrict__ addIn,
                          __half* __restrict__ yF)
{
    const int row  = (blockIdx.x * blockDim.x + threadIdx.x) >> 5;
    const int lane = threadIdx.x & 31;
    if (row >= Q) return;
    const float* xr = x + (size_t)row * C;
    float v[8];
    float s = 0.f;
#pragma unroll
    for (int i = 0; i < 8; i++) { v[i] = xr[lane + 32 * i]; s += v[i]; }
#pragma unroll
    for (int o = 16; o; o >>= 1) s += __shfl_xor_sync(0xffffffffu, s, o);
    const float mu = s * (1.f / (float)C);
    float s2 = 0.f;
#pragma unroll
    for (int i = 0; i < 8; i++) { const float d = v[i] - mu; s2 += d * d; }
#pragma unroll
    for (int o = 16; o; o >>= 1) s2 += __shfl_xor_sync(0xffffffffu, s2, o);
    const float rstd = rsqrtf(s2 * (1.f / (float)C) + 1e-5f);
#pragma unroll
    for (int i = 0; i < 8; i++) {
        const int c = lane + 32 * i;
        const float o = (v[i] - mu) * rstd * g[c] + b[c];
        y[(size_t)row * C + c] = o;
        if (yF) {
            const float a = addIn ? addIn[(size_t)row * C + c] : 0.f;
            yF[(size_t)row * C + c] = __float2half_rn(o + a);
        }
    }
}

__global__ void sp_kernel(const int* __restrict__ sp, float* __restrict__ o)
{
    int i = threadIdx.x;
    if (i < 4) o[i] = (float)sp[i];
}

// ---------------------------------------------------------------------------
// Driver
// ---------------------------------------------------------------------------
extern "C" void kernel_launch(void* const* d_in, const int* in_sizes, int n_in,
                              void* d_out, int out_size)
{
    (void)in_sizes; (void)n_in; (void)out_size;

    const float* query     = (const float*)d_in[0];
    const float* query_pos = (const float*)d_in[1];
    const float* value     = (const float*)d_in[2];
    const float* ref2d     = (const float*)d_in[3];
    const int*   spatial   = (const int*)  d_in[4];
    const float* sa_off_w = (const float*)d_in[5];
    const float* sa_off_b = (const float*)d_in[6];
    const float* sa_aw_w  = (const float*)d_in[7];
    const float* sa_aw_b  = (const float*)d_in[8];
    const float* sa_vp_w  = (const float*)d_in[9];
    const float* sa_vp_b  = (const float*)d_in[10];
    const float* sa_op_w  = (const float*)d_in[11];
    const float* sa_op_b  = (const float*)d_in[12];
    const float* ca_off_w = (const float*)d_in[13];
    const float* ca_off_b = (const float*)d_in[14];
    const float* ca_aw_w  = (const float*)d_in[15];
    const float* ca_aw_b  = (const float*)d_in[16];
    const float* ca_vp_w  = (const float*)d_in[17];
    const float* ca_vp_b  = (const float*)d_in[18];
    const float* ca_op_w  = (const float*)d_in[19];
    const float* ca_op_b  = (const float*)d_in[20];
    const float* ffn_w1   = (const float*)d_in[21];
    const float* ffn_b1   = (const float*)d_in[22];
    const float* ffn_w2   = (const float*)d_in[23];
    const float* ffn_b2   = (const float*)d_in[24];
    const float* ln1_g = (const float*)d_in[25];
    const float* ln1_b = (const float*)d_in[26];
    const float* ln2_g = (const float*)d_in[27];
    const float* ln2_b = (const float*)d_in[28];
    const float* ln3_g = (const float*)d_in[29];
    const float* ln3_b = (const float*)d_in[30];

    static bool attr_done = false;
    if (!attr_done) {
        cudaFuncSetAttribute(mma_gemm<false,false>,
                             cudaFuncAttributeMaxDynamicSharedMemorySize, GEMM_SMEM);
        cudaFuncSetAttribute(mma_gemm<false,true>,
                             cudaFuncAttributeMaxDynamicSharedMemorySize, GEMM_SMEM);
        cudaFuncSetAttribute(mma_gemm<true,true>,
                             cudaFuncAttributeMaxDynamicSharedMemorySize, GEMM_SMEM);
        attr_done = true;
    }

    float *offaw, *x, *q1, *q2, *biasP;
    __half *qF, *sF, *vF, *vpF, *aF, *q2F, *hidF, *wF;
    cudaGetSymbolAddress((void**)&offaw, g_offaw);
    cudaGetSymbolAddress((void**)&x,     g_x);
    cudaGetSymbolAddress((void**)&q1,    g_q1);
    cudaGetSymbolAddress((void**)&q2,    g_q2);
    cudaGetSymbolAddress((void**)&biasP, g_biasPack);
    cudaGetSymbolAddress((void**)&qF,    g_qF);
    cudaGetSymbolAddress((void**)&sF,    g_sF);
    cudaGetSymbolAddress((void**)&vF,    g_vF);
    cudaGetSymbolAddress((void**)&vpF,   g_vpF);
    cudaGetSymbolAddress((void**)&aF,    g_aF);
    cudaGetSymbolAddress((void**)&q2F,   g_q2F);
    cudaGetSymbolAddress((void**)&hidF,  g_hidF);
    cudaGetSymbolAddress((void**)&wF,    g_wF);

    float* out = (float*)d_out;
    const int N4 = QC / 4;
    const int CB = (N4 + 255) / 256;

    // ---------------- conversions ----------------
    convert_weights<<<(W_TOTAL + 255)/256, 256>>>(
        sa_off_w, sa_aw_w, sa_vp_w, sa_op_w, ca_off_w, ca_aw_w, ca_vp_w, ca_op_w,
        ffn_w1, ffn_w2, wF);
    pack_bias<<<1, 288>>>(sa_off_b, sa_aw_b, ca_off_b, ca_aw_b, biasP);
    prep_qsum<<<CB, 256>>>(query, query_pos, qF, sF, N4);
    convert_f16<<<2*CB, 256>>>(value, vF, 2*N4);

    // ---------------- Self deformable attention (L = 1) ----------------
    mma_gemm<false,true><<<dim3(2, Q/128), 256, GEMM_SMEM>>>(Q, 256, 256,
        qF, wF+OFF_SA_VP, sa_vp_b, nullptr, nullptr, vpF);
    mma_gemm<false,false><<<dim3(1, Q/128), 256, GEMM_SMEM>>>(Q, 96, 256,
        sF, wF+OFF_SA_OFFAW, biasP, nullptr, offaw, nullptr);
    sampler_kernel<1><<<Q*NH/8, 256>>>(vpF, offaw, ref2d, aF);
    mma_gemm<false,false><<<dim3(2, Q/128), 256, GEMM_SMEM>>>(Q, 256, 256,
        aF, wF+OFF_SA_OP, sa_op_b, query, x, nullptr);
    ln_kernel<<<Q/8, 256>>>(x, ln1_g, ln1_b, q1, query_pos, sF);

    // ---------------- Cross deformable attention (L = 2) ----------------
    mma_gemm<false,true><<<dim3(2, 2*Q/128), 256, GEMM_SMEM>>>(2*Q, 256, 256,
        vF, wF+OFF_CA_VP, ca_vp_b, nullptr, nullptr, vpF);
    mma_gemm<false,false><<<dim3(2, Q/128), 256, GEMM_SMEM>>>(Q, 192, 256,
        sF, wF+OFF_CA_OFFAW, biasP + 96, nullptr, offaw, nullptr);
    sampler_kernel<2><<<Q*NH/8, 256>>>(vpF, offaw, ref2d, aF);
    mma_gemm<false,false><<<dim3(2, Q/128), 256, GEMM_SMEM>>>(Q, 256, 256,
        aF, wF+OFF_CA_OP, ca_op_b, q1, x, nullptr);
    ln_kernel<<<Q/8, 256>>>(x, ln2_g, ln2_b, q2, nullptr, q2F);

    // ---------------- FFN ----------------
    mma_gemm<true,true><<<dim3(8, Q/128), 256, GEMM_SMEM>>>(Q, 1024, 256,
        q2F, wF+OFF_FFN1, ffn_b1, nullptr, nullptr, hidF);
    mma_gemm<false,false><<<dim3(2, Q/128), 256, GEMM_SMEM>>>(Q, 256, 1024,
        hidF, wF+OFF_FFN2, ffn_b2, q2, x, nullptr);
    ln_kernel<<<Q/8, 256>>>(x, ln3_g, ln3_b, out, nullptr, nullptr);

    // ---------------- Passthrough outputs ----------------
    cudaMemcpyAsync(out + QC,   query_pos, (size_t)QC * 4,     cudaMemcpyDeviceToDevice, 0);
    cudaMemcpyAsync(out + 2*QC, value,     (size_t)2 * QC * 4, cudaMemcpyDeviceToDevice, 0);
    cudaMemcpyAsync(out + 4*QC, ref2d,     (size_t)Q*LC*2 * 4, cudaMemcpyDeviceToDevice, 0);
    sp_kernel<<<1, 4>>>(spatial, out + 4*QC + Q*LC*2);
}

// round 13
// speedup vs baseline: 3.4172x; 1.1894x over previous
#include <cuda_runtime.h>
#include <cuda_fp16.h>
#include <cstdint>

// ---------------------------------------------------------------------------
// Problem constants
// ---------------------------------------------------------------------------
constexpr int Hh  = 160;
constexpr int Ww  = 160;
constexpr int Q   = Hh * Ww;      // 25600
constexpr int C   = 256;
constexpr int NH  = 8;
constexpr int HD  = C / NH;       // 32
constexpr int NP  = 4;
constexpr int LC  = 2;
constexpr int QC  = Q * C;        // 6,553,600

// Packed weight-plane offsets (elements)
constexpr int OFF_SA_OFFAW = 0;          // [256, 96]  (off 64 | aw 32)
constexpr int OFF_SA_VP    = 24576;      // [256, 256]
constexpr int OFF_SA_OP    = 90112;      // [256, 256]
constexpr int OFF_CA_OFFAW = 155648;     // [256, 192] (off 128 | aw 64)
constexpr int OFF_CA_VP    = 204800;     // [256, 256]
constexpr int OFF_CA_OP    = 270336;     // [256, 256]
constexpr int OFF_FFN1     = 335872;     // [256, 1024]
constexpr int OFF_FFN2     = 598016;     // [1024, 256]
constexpr int W_TOTAL      = 860160;

// ---------------------------------------------------------------------------
// Scratch (device globals -- no allocations allowed)
// ---------------------------------------------------------------------------
__device__ float g_offaw[Q * 192];               // packed off|aw GEMM output
__device__ float g_x [QC];
__device__ float g_q1[QC];
__device__ float g_q2[QC];
__device__ float g_biasPack[288];                // [96 SA | 192 CA]

__device__ __align__(256) __half g_qF[QC];       // fp16(query)
__device__ __align__(256) __half g_sF[QC];       // fp16(q + query_pos)
__device__ __align__(256) __half g_vF[2 * QC];   // fp16(value)
__device__ __align__(256) __half g_vpF[2 * QC];  // fp16(projected value)
__device__ __align__(256) __half g_aF[QC];       // fp16(attn sampled)
__device__ __align__(256) __half g_q2F[QC];
__device__ __align__(256) __half g_hidF[Q * 4 * C];
__device__ __align__(256) __half g_wF[W_TOTAL];

// ---------------------------------------------------------------------------
// PTX helpers
// ---------------------------------------------------------------------------
__device__ __forceinline__ void ldm_x4(uint32_t& r0, uint32_t& r1,
                                       uint32_t& r2, uint32_t& r3, uint32_t addr)
{
    asm volatile("ldmatrix.sync.aligned.m8n8.x4.shared.b16 {%0,%1,%2,%3}, [%4];"
                 : "=r"(r0), "=r"(r1), "=r"(r2), "=r"(r3) : "r"(addr));
}
__device__ __forceinline__ void ldm_x4_t(uint32_t& r0, uint32_t& r1,
                                         uint32_t& r2, uint32_t& r3, uint32_t addr)
{
    asm volatile("ldmatrix.sync.aligned.m8n8.x4.trans.shared.b16 {%0,%1,%2,%3}, [%4];"
                 : "=r"(r0), "=r"(r1), "=r"(r2), "=r"(r3) : "r"(addr));
}
__device__ __forceinline__ void mma_f16(float* c, uint32_t a0, uint32_t a1,
                                        uint32_t a2, uint32_t a3,
                                        uint32_t b0, uint32_t b1)
{
    asm volatile("mma.sync.aligned.m16n8k16.row.col.f32.f16.f16.f32 "
                 "{%0,%1,%2,%3}, {%4,%5,%6,%7}, {%8,%9}, {%0,%1,%2,%3};"
                 : "+f"(c[0]), "+f"(c[1]), "+f"(c[2]), "+f"(c[3])
                 : "r"(a0), "r"(a1), "r"(a2), "r"(a3), "r"(b0), "r"(b1));
}
__device__ __forceinline__ void cp16(uint32_t s, const void* g)
{
    asm volatile("cp.async.cg.shared.global [%0], [%1], 16;" :: "r"(s), "l"(g));
}
__device__ __forceinline__ void cp16z(uint32_t s, const void* g, bool valid)
{
    int sz = valid ? 16 : 0;
    asm volatile("cp.async.cg.shared.global [%0], [%1], 16, %2;"
                 :: "r"(s), "l"(g), "r"(sz));
}
__device__ __forceinline__ void cp_commit() { asm volatile("cp.async.commit_group;"); }

// ---------------------------------------------------------------------------
// Tensor-core GEMM: A fp16, B fp16 (single planes).
// Block 128x128x64, 256 thr = 8 warps (2M x 4N), double-buffered cp.async.
// smem per stage: A 128x64 (16KB) + B 64x128 (16KB); 2 stages = 64KB.
// __launch_bounds__(256, 2) -> 2 CTAs/SM to hide sync/wait bubbles.
// ---------------------------------------------------------------------------
constexpr int NSTAGE = 2;
constexpr int BK     = 64;
constexpr int GEMM_SMEM = NSTAGE * (8192 + 8192) * (int)sizeof(__half); // 65536

template<bool RELU, bool F16OUT>
__global__ void __launch_bounds__(256, 2)
mma_gemm(int M, int N, int K,
         const __half* __restrict__ A, const __half* __restrict__ B,
         const float* __restrict__ bias, const float* __restrict__ res,
         float* __restrict__ Cout, __half* __restrict__ outF)
{
    extern __shared__ __half sh[];
    const uint32_t shBase = (uint32_t)__cvta_generic_to_shared(sh);

    const int tid  = threadIdx.x;
    const int lane = tid & 31;
    const int warp = tid >> 5;
    const int wm   = warp >> 2;
    const int wn   = warp & 3;
    const int rowBase = blockIdx.y * 128;
    const int colBase = blockIdx.x * 128;

    float acc[4][4][4];
#pragma unroll
    for (int i = 0; i < 4; i++)
#pragma unroll
        for (int j = 0; j < 4; j++)
#pragma unroll
            for (int k = 0; k < 4; k++) acc[i][j][k] = 0.f;

    const int ntiles = K / BK;

    auto load_stage = [&](int ktile, int buf) {
        const int kt = ktile * BK;
        const uint32_t aB = shBase + (uint32_t)(buf * 8192) * 2;
#pragma unroll
        for (int j = 0; j < 4; j++) {
            const int idx = tid + j * 256;        // 1024 chunks over 128 rows x 8
            const int r   = idx >> 3;
            const int c8  = idx & 7;
            const int cs  = c8 ^ (r & 7);
            cp16(aB + (uint32_t)(r * 64 + cs * 8) * 2,
                 A + (size_t)(rowBase + r) * K + kt + c8 * 8);
        }
        const uint32_t bB = shBase + (uint32_t)(NSTAGE * 8192 + buf * 8192) * 2;
#pragma unroll
        for (int j = 0; j < 4; j++) {
            const int idx = tid + j * 256;        // 1024 chunks over 64 rows x 16
            const int r   = idx >> 4;
            const int c8  = idx & 15;
            const int gc  = colBase + c8 * 8;
            const int cs  = c8 ^ (r & 7);
            cp16z(bB + (uint32_t)(r * 128 + cs * 8) * 2,
                  B + (size_t)(kt + r) * N + gc, gc < N);
        }
    };

    load_stage(0, 0);
    cp_commit();

    for (int kt = 0; kt < ntiles; kt++) {
        if (kt + 1 < ntiles) {
            load_stage(kt + 1, (kt + 1) & 1);
            cp_commit();
            asm volatile("cp.async.wait_group 1;");
        } else {
            asm volatile("cp.async.wait_group 0;");
        }
        __syncthreads();

        const int buf = kt & 1;
        const uint32_t aB = shBase + (uint32_t)(buf * 8192) * 2;
        const uint32_t bB = shBase + (uint32_t)(NSTAGE * 8192 + buf * 8192) * 2;

#pragma unroll
        for (int s = 0; s < 4; s++) {
            uint32_t af[4][4];
            uint32_t bf[4][2];
#pragma unroll
            for (int mt = 0; mt < 4; mt++) {
                const int r  = wm * 64 + mt * 16 + (lane & 15);
                const int c  = s * 2 + (lane >> 4);
                const int cs = c ^ (r & 7);
                ldm_x4(af[mt][0], af[mt][1], af[mt][2], af[mt][3],
                       aB + (uint32_t)(r * 64 + cs * 8) * 2);
            }
#pragma unroll
            for (int pi = 0; pi < 2; pi++) {
                const int k  = s * 16 + (lane & 15);
                const int cc = wn * 4 + (lane >> 4) + pi * 2;
                const int cs = cc ^ (k & 7);
                ldm_x4_t(bf[pi*2][0], bf[pi*2][1], bf[pi*2+1][0], bf[pi*2+1][1],
                         bB + (uint32_t)(k * 128 + cs * 8) * 2);
            }
#pragma unroll
            for (int mt = 0; mt < 4; mt++)
#pragma unroll
                for (int nt = 0; nt < 4; nt++)
                    mma_f16(acc[mt][nt], af[mt][0], af[mt][1], af[mt][2], af[mt][3],
                            bf[nt][0], bf[nt][1]);
        }
        __syncthreads();
    }

    // ---- epilogue ----
    const int g  = lane >> 2;
    const int t4 = lane & 3;
#pragma unroll
    for (int mt = 0; mt < 4; mt++) {
#pragma unroll
        for (int nt = 0; nt < 4; nt++) {
            const int col = colBase + wn * 32 + nt * 8 + t4 * 2;
            if (col >= N) continue;
            const int r0 = rowBase + wm * 64 + mt * 16 + g;
            const float2 b2 = *reinterpret_cast<const float2*>(bias + col);
            float2 o0 = make_float2(acc[mt][nt][0] + b2.x, acc[mt][nt][1] + b2.y);
            float2 o1 = make_float2(acc[mt][nt][2] + b2.x, acc[mt][nt][3] + b2.y);
            if (res) {
                float2 r2a = *reinterpret_cast<const float2*>(res + (size_t)r0 * N + col);
                float2 r2b = *reinterpret_cast<const float2*>(res + (size_t)(r0 + 8) * N + col);
                o0.x += r2a.x; o0.y += r2a.y; o1.x += r2b.x; o1.y += r2b.y;
            }
            if (RELU) {
                o0.x = fmaxf(o0.x, 0.f); o0.y = fmaxf(o0.y, 0.f);
                o1.x = fmaxf(o1.x, 0.f); o1.y = fmaxf(o1.y, 0.f);
            }
            if (F16OUT) {
                *reinterpret_cast<__half2*>(outF + (size_t)r0 * N + col) = __float22half2_rn(o0);
                *reinterpret_cast<__half2*>(outF + (size_t)(r0 + 8) * N + col) = __float22half2_rn(o1);
            } else {
                *reinterpret_cast<float2*>(Cout + (size_t)r0 * N + col) = o0;
                *reinterpret_cast<float2*>(Cout + (size_t)(r0 + 8) * N + col) = o1;
            }
        }
    }
}

// ---------------------------------------------------------------------------
// Weight conversion: fp32 -> packed fp16 plane.
// ---------------------------------------------------------------------------
__global__ void convert_weights(const float* __restrict__ sa_off_w, const float* __restrict__ sa_aw_w,
                                const float* __restrict__ sa_vp_w,  const float* __restrict__ sa_op_w,
                                const float* __restrict__ ca_off_w, const float* __restrict__ ca_aw_w,
                                const float* __restrict__ ca_vp_w,  const float* __restrict__ ca_op_w,
                                const float* __restrict__ ffn_w1,   const float* __restrict__ ffn_w2,
                                __half* __restrict__ wf)
{
    int e = blockIdx.x * blockDim.x + threadIdx.x;
    if (e >= W_TOTAL) return;
    float val;
    if (e < OFF_SA_VP) {                       // SA off|aw packed [256,96]
        int r = e / 96, c = e % 96;
        val = (c < 64) ? sa_off_w[r * 64 + c] : sa_aw_w[r * 32 + (c - 64)];
    } else if (e < OFF_SA_OP)    val = sa_vp_w[e - OFF_SA_VP];
    else if (e < OFF_CA_OFFAW)   val = sa_op_w[e - OFF_SA_OP];
    else if (e < OFF_CA_VP) {                  // CA off|aw packed [256,192]
        int t = e - OFF_CA_OFFAW;
        int r = t / 192, c = t % 192;
        val = (c < 128) ? ca_off_w[r * 128 + c] : ca_aw_w[r * 64 + (c - 128)];
    } else if (e < OFF_CA_OP)    val = ca_vp_w[e - OFF_CA_VP];
    else if (e < OFF_FFN1)       val = ca_op_w[e - OFF_CA_OP];
    else if (e < OFF_FFN2)       val = ffn_w1[e - OFF_FFN1];
    else                         val = ffn_w2[e - OFF_FFN2];
    wf[e] = __float2half_rn(val);
}

__global__ void pack_bias(const float* __restrict__ sa_off_b, const float* __restrict__ sa_aw_b,
                          const float* __restrict__ ca_off_b, const float* __restrict__ ca_aw_b,
                          float* __restrict__ bp)
{
    int i = threadIdx.x;
    if (i < 64)        bp[i] = sa_off_b[i];
    else if (i < 96)   bp[i] = sa_aw_b[i - 64];
    else if (i < 224)  bp[i] = ca_off_b[i - 96];
    else if (i < 288)  bp[i] = ca_aw_b[i - 224];
}

// query -> fp16, (query + query_pos) -> fp16
__global__ void prep_qsum(const float* __restrict__ a, const float* __restrict__ b,
                          __half* __restrict__ qF, __half* __restrict__ sF, int n4)
{
    int i = blockIdx.x * blockDim.x + threadIdx.x;
    if (i >= n4) return;
    float4 va = reinterpret_cast<const float4*>(a)[i];
    float4 vb = reinterpret_cast<const float4*>(b)[i];
    __half2* q2 = reinterpret_cast<__half2*>(qF);
    __half2* s2 = reinterpret_cast<__half2*>(sF);
    q2[i*2]   = __float22half2_rn(make_float2(va.x, va.y));
    q2[i*2+1] = __float22half2_rn(make_float2(va.z, va.w));
    s2[i*2]   = __float22half2_rn(make_float2(va.x + vb.x, va.y + vb.y));
    s2[i*2+1] = __float22half2_rn(make_float2(va.z + vb.z, va.w + vb.w));
}

__global__ void convert_f16(const float* __restrict__ src, __half* __restrict__ dst, int n4)
{
    int i = blockIdx.x * blockDim.x + threadIdx.x;
    if (i >= n4) return;
    float4 v = reinterpret_cast<const float4*>(src)[i];
    __half2* d2 = reinterpret_cast<__half2*>(dst);
    d2[i*2]   = __float22half2_rn(make_float2(v.x, v.y));
    d2[i*2+1] = __float22half2_rn(make_float2(v.z, v.w));
}

// ---------------------------------------------------------------------------
// Deformable sampling: one warp per (q, h), fp16 value planes, fp16 output.
// ---------------------------------------------------------------------------
__device__ __forceinline__ float fetch_corner(const __half* __restrict__ vl, int xi, int yi)
{
    if (xi < 0 || xi >= Ww || yi < 0 || yi >= Hh) return 0.f;
    return __half2float(vl[(yi * Ww + xi) * C]);
}

template<int L>
__global__ void sampler_kernel(const __half* __restrict__ v,
                               const float* __restrict__ offaw,
                               const float* __restrict__ ref2d,
                               __half* __restrict__ outF)
{
    const int w    = (blockIdx.x * blockDim.x + threadIdx.x) >> 5;
    const int lane = threadIdx.x & 31;
    if (w >= Q * NH) return;
    const int q = w / NH;
    const int h = w % NH;

    constexpr int LNP = L * NP;
    constexpr int RS  = L * 96;          // row stride: 96 (SA) / 192 (CA)
    const float* row = offaw + (size_t)q * RS;
    const float* awp = row + 64 * L + h * LNP;
    const float* offp = row + h * LNP * 2;

    float wgt[LNP];
    float m = -1e30f;
#pragma unroll
    for (int i = 0; i < LNP; i++) { wgt[i] = awp[i]; m = fmaxf(m, wgt[i]); }
    float s = 0.f;
#pragma unroll
    for (int i = 0; i < LNP; i++) { wgt[i] = __expf(wgt[i] - m); s += wgt[i]; }
    const float inv = 1.f / s;

    float acc = 0.f;
#pragma unroll
    for (int l = 0; l < L; l++) {
        const float rx = ref2d[(q * LC + l) * 2 + 0];
        const float ry = ref2d[(q * LC + l) * 2 + 1];
        const __half* vl = v + ((size_t)l * Q) * C + h * HD + lane;
#pragma unroll
        for (int p = 0; p < NP; p++) {
            const float ox = offp[(l * NP + p) * 2 + 0];
            const float oy = offp[(l * NP + p) * 2 + 1];
            const float x = (rx + ox * (1.f / (float)Ww)) * (float)Ww - 0.5f;
            const float y = (ry + oy * (1.f / (float)Hh)) * (float)Hh - 0.5f;
            const float x0f = floorf(x), y0f = floorf(y);
            const int x0 = (int)x0f, y0 = (int)y0f;
            const float tx = x - x0f, ty = y - y0f;
            const float wp = wgt[l * NP + p] * inv;

            const float c00 = fetch_corner(vl, x0,     y0);
            const float c10 = fetch_corner(vl, x0 + 1, y0);
            const float c01 = fetch_corner(vl, x0,     y0 + 1);
            const float c11 = fetch_corner(vl, x0 + 1, y0 + 1);

            const float top = c00 * (1.f - tx) + c10 * tx;
            const float bot = c01 * (1.f - tx) + c11 * tx;
            acc += wp * (top * (1.f - ty) + bot * ty);
        }
    }
    outF[(size_t)q * C + h * HD + lane] = __float2half_rn(acc);
}

// ---------------------------------------------------------------------------
// LayerNorm: one warp per row; optional fused (y + addIn) -> fp16 plane.
// ---------------------------------------------------------------------------
__global__ void ln_kernel(const float* __restrict__ x,
                          const float* __restrict__ g,
                          const float* __restrict__ b,
                          float* __restrict__ y,
                          const float* __restrict__ addIn,
                          __half* __restrict__ yF)
{
    const int row  = (blockIdx.x * blockDim.x + threadIdx.x) >> 5;
    const int lane = threadIdx.x & 31;
    if (row >= Q) return;
    const float* xr = x + (size_t)row * C;
    float v[8];
    float s = 0.f;
#pragma unroll
    for (int i = 0; i < 8; i++) { v[i] = xr[lane + 32 * i]; s += v[i]; }
#pragma unroll
    for (int o = 16; o; o >>= 1) s += __shfl_xor_sync(0xffffffffu, s, o);
    const float mu = s * (1.f / (float)C);
    float s2 = 0.f;
#pragma unroll
    for (int i = 0; i < 8; i++) { const float d = v[i] - mu; s2 += d * d; }
#pragma unroll
    for (int o = 16; o; o >>= 1) s2 += __shfl_xor_sync(0xffffffffu, s2, o);
    const float rstd = rsqrtf(s2 * (1.f / (float)C) + 1e-5f);
#pragma unroll
    for (int i = 0; i < 8; i++) {
        const int c = lane + 32 * i;
        const float o = (v[i] - mu) * rstd * g[c] + b[c];
        y[(size_t)row * C + c] = o;
        if (yF) {
            const float a = addIn ? addIn[(size_t)row * C + c] : 0.f;
            yF[(size_t)row * C + c] = __float2half_rn(o + a);
        }
    }
}

__global__ void sp_kernel(const int* __restrict__ sp, float* __restrict__ o)
{
    int i = threadIdx.x;
    if (i < 4) o[i] = (float)sp[i];
}

// ---------------------------------------------------------------------------
// Driver
// ---------------------------------------------------------------------------
extern "C" void kernel_launch(void* const* d_in, const int* in_sizes, int n_in,
                              void* d_out, int out_size)
{
    (void)in_sizes; (void)n_in; (void)out_size;

    const float* query     = (const float*)d_in[0];
    const float* query_pos = (const float*)d_in[1];
    const float* value     = (const float*)d_in[2];
    const float* ref2d     = (const float*)d_in[3];
    const int*   spatial   = (const int*)  d_in[4];
    const float* sa_off_w = (const float*)d_in[5];
    const float* sa_off_b = (const float*)d_in[6];
    const float* sa_aw_w  = (const float*)d_in[7];
    const float* sa_aw_b  = (const float*)d_in[8];
    const float* sa_vp_w  = (const float*)d_in[9];
    const float* sa_vp_b  = (const float*)d_in[10];
    const float* sa_op_w  = (const float*)d_in[11];
    const float* sa_op_b  = (const float*)d_in[12];
    const float* ca_off_w = (const float*)d_in[13];
    const float* ca_off_b = (const float*)d_in[14];
    const float* ca_aw_w  = (const float*)d_in[15];
    const float* ca_aw_b  = (const float*)d_in[16];
    const float* ca_vp_w  = (const float*)d_in[17];
    const float* ca_vp_b  = (const float*)d_in[18];
    const float* ca_op_w  = (const float*)d_in[19];
    const float* ca_op_b  = (const float*)d_in[20];
    const float* ffn_w1   = (const float*)d_in[21];
    const float* ffn_b1   = (const float*)d_in[22];
    const float* ffn_w2   = (const float*)d_in[23];
    const float* ffn_b2   = (const float*)d_in[24];
    const float* ln1_g = (const float*)d_in[25];
    const float* ln1_b = (const float*)d_in[26];
    const float* ln2_g = (const float*)d_in[27];
    const float* ln2_b = (const float*)d_in[28];
    const float* ln3_g = (const float*)d_in[29];
    const float* ln3_b = (const float*)d_in[30];

    static bool attr_done = false;
    if (!attr_done) {
        cudaFuncSetAttribute(mma_gemm<false,false>,
                             cudaFuncAttributeMaxDynamicSharedMemorySize, GEMM_SMEM);
        cudaFuncSetAttribute(mma_gemm<false,true>,
                             cudaFuncAttributeMaxDynamicSharedMemorySize, GEMM_SMEM);
        cudaFuncSetAttribute(mma_gemm<true,true>,
                             cudaFuncAttributeMaxDynamicSharedMemorySize, GEMM_SMEM);
        attr_done = true;
    }

    float *offaw, *x, *q1, *q2, *biasP;
    __half *qF, *sF, *vF, *vpF, *aF, *q2F, *hidF, *wF;
    cudaGetSymbolAddress((void**)&offaw, g_offaw);
    cudaGetSymbolAddress((void**)&x,     g_x);
    cudaGetSymbolAddress((void**)&q1,    g_q1);
    cudaGetSymbolAddress((void**)&q2,    g_q2);
    cudaGetSymbolAddress((void**)&biasP, g_biasPack);
    cudaGetSymbolAddress((void**)&qF,    g_qF);
    cudaGetSymbolAddress((void**)&sF,    g_sF);
    cudaGetSymbolAddress((void**)&vF,    g_vF);
    cudaGetSymbolAddress((void**)&vpF,   g_vpF);
    cudaGetSymbolAddress((void**)&aF,    g_aF);
    cudaGetSymbolAddress((void**)&q2F,   g_q2F);
    cudaGetSymbolAddress((void**)&hidF,  g_hidF);
    cudaGetSymbolAddress((void**)&wF,    g_wF);

    float* out = (float*)d_out;
    const int N4 = QC / 4;
    const int CB = (N4 + 255) / 256;

    // ---------------- conversions ----------------
    convert_weights<<<(W_TOTAL + 255)/256, 256>>>(
        sa_off_w, sa_aw_w, sa_vp_w, sa_op_w, ca_off_w, ca_aw_w, ca_vp_w, ca_op_w,
        ffn_w1, ffn_w2, wF);
    pack_bias<<<1, 288>>>(sa_off_b, sa_aw_b, ca_off_b, ca_aw_b, biasP);
    prep_qsum<<<CB, 256>>>(query, query_pos, qF, sF, N4);
    convert_f16<<<2*CB, 256>>>(value, vF, 2*N4);

    // ---------------- Self deformable attention (L = 1) ----------------
    mma_gemm<false,true><<<dim3(2, Q/128), 256, GEMM_SMEM>>>(Q, 256, 256,
        qF, wF+OFF_SA_VP, sa_vp_b, nullptr, nullptr, vpF);
    mma_gemm<false,false><<<dim3(1, Q/128), 256, GEMM_SMEM>>>(Q, 96, 256,
        sF, wF+OFF_SA_OFFAW, biasP, nullptr, offaw, nullptr);
    sampler_kernel<1><<<Q*NH/8, 256>>>(vpF, offaw, ref2d, aF);
    mma_gemm<false,false><<<dim3(2, Q/128), 256, GEMM_SMEM>>>(Q, 256, 256,
        aF, wF+OFF_SA_OP, sa_op_b, query, x, nullptr);
    ln_kernel<<<Q/8, 256>>>(x, ln1_g, ln1_b, q1, query_pos, sF);

    // ---------------- Cross deformable attention (L = 2) ----------------
    mma_gemm<false,true><<<dim3(2, 2*Q/128), 256, GEMM_SMEM>>>(2*Q, 256, 256,
        vF, wF+OFF_CA_VP, ca_vp_b, nullptr, nullptr, vpF);
    mma_gemm<false,false><<<dim3(2, Q/128), 256, GEMM_SMEM>>>(Q, 192, 256,
        sF, wF+OFF_CA_OFFAW, biasP + 96, nullptr, offaw, nullptr);
    sampler_kernel<2><<<Q*NH/8, 256>>>(vpF, offaw, ref2d, aF);
    mma_gemm<false,false><<<dim3(2, Q/128), 256, GEMM_SMEM>>>(Q, 256, 256,
        aF, wF+OFF_CA_OP, ca_op_b, q1, x, nullptr);
    ln_kernel<<<Q/8, 256>>>(x, ln2_g, ln2_b, q2, nullptr, q2F);

    // ---------------- FFN ----------------
    mma_gemm<true,true><<<dim3(8, Q/128), 256, GEMM_SMEM>>>(Q, 1024, 256,
        q2F, wF+OFF_FFN1, ffn_b1, nullptr, nullptr, hidF);
    mma_gemm<false,false><<<dim3(2, Q/128), 256, GEMM_SMEM>>>(Q, 256, 1024,
        hidF, wF+OFF_FFN2, ffn_b2, q2, x, nullptr);
    ln_kernel<<<Q/8, 256>>>(x, ln3_g, ln3_b, out, nullptr, nullptr);

    // ---------------- Passthrough outputs ----------------
    cudaMemcpyAsync(out + QC,   query_pos, (size_t)QC * 4,     cudaMemcpyDeviceToDevice, 0);
    cudaMemcpyAsync(out + 2*QC, value,     (size_t)2 * QC * 4, cudaMemcpyDeviceToDevice, 0);
    cudaMemcpyAsync(out + 4*QC, ref2d,     (size_t)Q*LC*2 * 4, cudaMemcpyDeviceToDevice, 0);
    sp_kernel<<<1, 4>>>(spatial, out + 4*QC + Q*LC*2);
}

// round 14
// speedup vs baseline: 3.5374x; 1.0352x over previous
#include <cuda_runtime.h>
#include <cuda_fp16.h>
#include <cstdint>

// ---------------------------------------------------------------------------
// Problem constants
// ---------------------------------------------------------------------------
constexpr int Hh  = 160;
constexpr int Ww  = 160;
constexpr int Q   = Hh * Ww;      // 25600
constexpr int C   = 256;
constexpr int NH  = 8;
constexpr int HD  = C / NH;       // 32
constexpr int NP  = 4;
constexpr int LC  = 2;
constexpr int QC  = Q * C;        // 6,553,600

// Packed weight-plane offsets (elements)
constexpr int OFF_SA_OFFAW = 0;          // [256, 96]  (off 64 | aw 32)
constexpr int OFF_SA_VP    = 24576;      // [256, 256]
constexpr int OFF_SA_OP    = 90112;      // [256, 256]
constexpr int OFF_CA_OFFAW = 155648;     // [256, 192] (off 128 | aw 64)
constexpr int OFF_CA_VP    = 204800;     // [256, 256]
constexpr int OFF_CA_OP    = 270336;     // [256, 256]
constexpr int OFF_FFN1     = 335872;     // [256, 1024]
constexpr int OFF_FFN2     = 598016;     // [1024, 256]
constexpr int W_TOTAL      = 860160;

// ---------------------------------------------------------------------------
// Scratch (device globals -- no allocations allowed)
// ---------------------------------------------------------------------------
__device__ float g_offaw[Q * 192];               // packed off|aw GEMM output
__device__ float g_x [QC];
__device__ float g_q1[QC];
__device__ float g_q2[QC];
__device__ float g_biasPack[288];                // [96 SA | 192 CA]

__device__ __align__(256) __half g_qF[QC];       // fp16(query)
__device__ __align__(256) __half g_sF[QC];       // fp16(q + query_pos)
__device__ __align__(256) __half g_vF[2 * QC];   // fp16(value)
__device__ __align__(256) __half g_vpF[2 * QC];  // fp16(projected value)
__device__ __align__(256) __half g_aF[QC];       // fp16(attn sampled)
__device__ __align__(256) __half g_q2F[QC];
__device__ __align__(256) __half g_hidF[Q * 4 * C];
__device__ __align__(256) __half g_wF[W_TOTAL];

// ---------------------------------------------------------------------------
// PTX helpers
// ---------------------------------------------------------------------------
__device__ __forceinline__ void ldm_x4(uint32_t& r0, uint32_t& r1,
                                       uint32_t& r2, uint32_t& r3, uint32_t addr)
{
    asm volatile("ldmatrix.sync.aligned.m8n8.x4.shared.b16 {%0,%1,%2,%3}, [%4];"
                 : "=r"(r0), "=r"(r1), "=r"(r2), "=r"(r3) : "r"(addr));
}
__device__ __forceinline__ void ldm_x4_t(uint32_t& r0, uint32_t& r1,
                                         uint32_t& r2, uint32_t& r3, uint32_t addr)
{
    asm volatile("ldmatrix.sync.aligned.m8n8.x4.trans.shared.b16 {%0,%1,%2,%3}, [%4];"
                 : "=r"(r0), "=r"(r1), "=r"(r2), "=r"(r3) : "r"(addr));
}
__device__ __forceinline__ void mma_f16(float* c, uint32_t a0, uint32_t a1,
                                        uint32_t a2, uint32_t a3,
                                        uint32_t b0, uint32_t b1)
{
    asm volatile("mma.sync.aligned.m16n8k16.row.col.f32.f16.f16.f32 "
                 "{%0,%1,%2,%3}, {%4,%5,%6,%7}, {%8,%9}, {%0,%1,%2,%3};"
                 : "+f"(c[0]), "+f"(c[1]), "+f"(c[2]), "+f"(c[3])
                 : "r"(a0), "r"(a1), "r"(a2), "r"(a3), "r"(b0), "r"(b1));
}
__device__ __forceinline__ void cp16(uint32_t s, const void* g)
{
    asm volatile("cp.async.cg.shared.global [%0], [%1], 16;" :: "r"(s), "l"(g));
}
__device__ __forceinline__ void cp16z(uint32_t s, const void* g, bool valid)
{
    int sz = valid ? 16 : 0;
    asm volatile("cp.async.cg.shared.global [%0], [%1], 16, %2;"
                 :: "r"(s), "l"(g), "r"(sz));
}
__device__ __forceinline__ void cp_commit() { asm volatile("cp.async.commit_group;"); }

// ---------------------------------------------------------------------------
// Tensor-core GEMM: A fp16, B fp16 (single planes).
// Block 128x128x64, 256 thr = 8 warps (2M x 4N), 3-stage cp.async pipeline
// with ONE __syncthreads per k-tile (loads issued after the barrier).
// smem: 3 stages x (A 16KB + B 16KB) = 96KB; 2 CTAs/SM (192KB).
// ---------------------------------------------------------------------------
constexpr int NSTAGE = 3;
constexpr int BK     = 64;
constexpr int GEMM_SMEM = NSTAGE * (8192 + 8192) * (int)sizeof(__half); // 98304

template<bool RELU, bool F16OUT>
__global__ void __launch_bounds__(256, 2)
mma_gemm(int M, int N, int K,
         const __half* __restrict__ A, const __half* __restrict__ B,
         const float* __restrict__ bias, const float* __restrict__ res,
         float* __restrict__ Cout, __half* __restrict__ outF)
{
    extern __shared__ __half sh[];
    const uint32_t shBase = (uint32_t)__cvta_generic_to_shared(sh);

    const int tid  = threadIdx.x;
    const int lane = tid & 31;
    const int warp = tid >> 5;
    const int wm   = warp >> 2;
    const int wn   = warp & 3;
    const int rowBase = blockIdx.y * 128;
    const int colBase = blockIdx.x * 128;

    float acc[4][4][4];
#pragma unroll
    for (int i = 0; i < 4; i++)
#pragma unroll
        for (int j = 0; j < 4; j++)
#pragma unroll
            for (int k = 0; k < 4; k++) acc[i][j][k] = 0.f;

    const int ntiles = K / BK;

    auto load_stage = [&](int ktile, int buf) {
        const int kt = ktile * BK;
        const uint32_t aB = shBase + (uint32_t)(buf * 8192) * 2;
#pragma unroll
        for (int j = 0; j < 4; j++) {
            const int idx = tid + j * 256;        // 1024 chunks over 128 rows x 8
            const int r   = idx >> 3;
            const int c8  = idx & 7;
            const int cs  = c8 ^ (r & 7);
            cp16(aB + (uint32_t)(r * 64 + cs * 8) * 2,
                 A + (size_t)(rowBase + r) * K + kt + c8 * 8);
        }
        const uint32_t bB = shBase + (uint32_t)(NSTAGE * 8192 + buf * 8192) * 2;
#pragma unroll
        for (int j = 0; j < 4; j++) {
            const int idx = tid + j * 256;        // 1024 chunks over 64 rows x 16
            const int r   = idx >> 4;
            const int c8  = idx & 15;
            const int gc  = colBase + c8 * 8;
            const int cs  = c8 ^ (r & 7);
            cp16z(bB + (uint32_t)(r * 128 + cs * 8) * 2,
                  B + (size_t)(kt + r) * N + gc, gc < N);
        }
    };

    // prologue: stages 0, 1
    load_stage(0, 0); cp_commit();
    if (ntiles > 1) { load_stage(1, 1); cp_commit(); }

    for (int kt = 0; kt < ntiles; kt++) {
        if (kt == ntiles - 1) asm volatile("cp.async.wait_group 0;");
        else                  asm volatile("cp.async.wait_group 1;");
        __syncthreads();

        // issue next stage AFTER the barrier: the buffer it overwrites was
        // last read in iteration kt-1, which every warp has now completed.
        if (kt + 2 < ntiles) { load_stage(kt + 2, (kt + 2) % NSTAGE); cp_commit(); }

        const int buf = kt % NSTAGE;
        const uint32_t aB = shBase + (uint32_t)(buf * 8192) * 2;
        const uint32_t bB = shBase + (uint32_t)(NSTAGE * 8192 + buf * 8192) * 2;

#pragma unroll
        for (int s = 0; s < 4; s++) {
            uint32_t af[4][4];
            uint32_t bf[4][2];
#pragma unroll
            for (int mt = 0; mt < 4; mt++) {
                const int r  = wm * 64 + mt * 16 + (lane & 15);
                const int c  = s * 2 + (lane >> 4);
                const int cs = c ^ (r & 7);
                ldm_x4(af[mt][0], af[mt][1], af[mt][2], af[mt][3],
                       aB + (uint32_t)(r * 64 + cs * 8) * 2);
            }
#pragma unroll
            for (int pi = 0; pi < 2; pi++) {
                const int k  = s * 16 + (lane & 15);
                const int cc = wn * 4 + (lane >> 4) + pi * 2;
                const int cs = cc ^ (k & 7);
                ldm_x4_t(bf[pi*2][0], bf[pi*2][1], bf[pi*2+1][0], bf[pi*2+1][1],
                         bB + (uint32_t)(k * 128 + cs * 8) * 2);
            }
#pragma unroll
            for (int mt = 0; mt < 4; mt++)
#pragma unroll
                for (int nt = 0; nt < 4; nt++)
                    mma_f16(acc[mt][nt], af[mt][0], af[mt][1], af[mt][2], af[mt][3],
                            bf[nt][0], bf[nt][1]);
        }
    }

    // ---- epilogue ----
    const int g  = lane >> 2;
    const int t4 = lane & 3;
#pragma unroll
    for (int mt = 0; mt < 4; mt++) {
#pragma unroll
        for (int nt = 0; nt < 4; nt++) {
            const int col = colBase + wn * 32 + nt * 8 + t4 * 2;
            if (col >= N) continue;
            const int r0 = rowBase + wm * 64 + mt * 16 + g;
            const float2 b2 = *reinterpret_cast<const float2*>(bias + col);
            float2 o0 = make_float2(acc[mt][nt][0] + b2.x, acc[mt][nt][1] + b2.y);
            float2 o1 = make_float2(acc[mt][nt][2] + b2.x, acc[mt][nt][3] + b2.y);
            if (res) {
                float2 r2a = *reinterpret_cast<const float2*>(res + (size_t)r0 * N + col);
                float2 r2b = *reinterpret_cast<const float2*>(res + (size_t)(r0 + 8) * N + col);
                o0.x += r2a.x; o0.y += r2a.y; o1.x += r2b.x; o1.y += r2b.y;
            }
            if (RELU) {
                o0.x = fmaxf(o0.x, 0.f); o0.y = fmaxf(o0.y, 0.f);
                o1.x = fmaxf(o1.x, 0.f); o1.y = fmaxf(o1.y, 0.f);
            }
            if (F16OUT) {
                *reinterpret_cast<__half2*>(outF + (size_t)r0 * N + col) = __float22half2_rn(o0);
                *reinterpret_cast<__half2*>(outF + (size_t)(r0 + 8) * N + col) = __float22half2_rn(o1);
            } else {
                *reinterpret_cast<float2*>(Cout + (size_t)r0 * N + col) = o0;
                *reinterpret_cast<float2*>(Cout + (size_t)(r0 + 8) * N + col) = o1;
            }
        }
    }
}

// ---------------------------------------------------------------------------
// Weight conversion: fp32 -> packed fp16 plane.
// ---------------------------------------------------------------------------
__global__ void convert_weights(const float* __restrict__ sa_off_w, const float* __restrict__ sa_aw_w,
                                const float* __restrict__ sa_vp_w,  const float* __restrict__ sa_op_w,
                                const float* __restrict__ ca_off_w, const float* __restrict__ ca_aw_w,
                                const float* __restrict__ ca_vp_w,  const float* __restrict__ ca_op_w,
                                const float* __restrict__ ffn_w1,   const float* __restrict__ ffn_w2,
                                __half* __restrict__ wf)
{
    int e = blockIdx.x * blockDim.x + threadIdx.x;
    if (e >= W_TOTAL) return;
    float val;
    if (e < OFF_SA_VP) {                       // SA off|aw packed [256,96]
        int r = e / 96, c = e % 96;
        val = (c < 64) ? sa_off_w[r * 64 + c] : sa_aw_w[r * 32 + (c - 64)];
    } else if (e < OFF_SA_OP)    val = sa_vp_w[e - OFF_SA_VP];
    else if (e < OFF_CA_OFFAW)   val = sa_op_w[e - OFF_SA_OP];
    else if (e < OFF_CA_VP) {                  // CA off|aw packed [256,192]
        int t = e - OFF_CA_OFFAW;
        int r = t / 192, c = t % 192;
        val = (c < 128) ? ca_off_w[r * 128 + c] : ca_aw_w[r * 64 + (c - 128)];
    } else if (e < OFF_CA_OP)    val = ca_vp_w[e - OFF_CA_VP];
    else if (e < OFF_FFN1)       val = ca_op_w[e - OFF_CA_OP];
    else if (e < OFF_FFN2)       val = ffn_w1[e - OFF_FFN1];
    else                         val = ffn_w2[e - OFF_FFN2];
    wf[e] = __float2half_rn(val);
}

__global__ void pack_bias(const float* __restrict__ sa_off_b, const float* __restrict__ sa_aw_b,
                          const float* __restrict__ ca_off_b, const float* __restrict__ ca_aw_b,
                          float* __restrict__ bp)
{
    int i = threadIdx.x;
    if (i < 64)        bp[i] = sa_off_b[i];
    else if (i < 96)   bp[i] = sa_aw_b[i - 64];
    else if (i < 224)  bp[i] = ca_off_b[i - 96];
    else if (i < 288)  bp[i] = ca_aw_b[i - 224];
}

// query -> fp16, (query + query_pos) -> fp16, query_pos -> out (passthrough)
__global__ void prep_qsum(const float* __restrict__ a, const float* __restrict__ b,
                          __half* __restrict__ qF, __half* __restrict__ sF,
                          float* __restrict__ qpOut, int n4)
{
    int i = blockIdx.x * blockDim.x + threadIdx.x;
    if (i >= n4) return;
    float4 va = reinterpret_cast<const float4*>(a)[i];
    float4 vb = reinterpret_cast<const float4*>(b)[i];
    reinterpret_cast<float4*>(qpOut)[i] = vb;
    __half2* q2 = reinterpret_cast<__half2*>(qF);
    __half2* s2 = reinterpret_cast<__half2*>(sF);
    q2[i*2]   = __float22half2_rn(make_float2(va.x, va.y));
    q2[i*2+1] = __float22half2_rn(make_float2(va.z, va.w));
    s2[i*2]   = __float22half2_rn(make_float2(va.x + vb.x, va.y + vb.y));
    s2[i*2+1] = __float22half2_rn(make_float2(va.z + vb.z, va.w + vb.w));
}

// value -> fp16 plus passthrough copy to out
__global__ void convert_val(const float* __restrict__ src, __half* __restrict__ dst,
                            float* __restrict__ passOut, int n4)
{
    int i = blockIdx.x * blockDim.x + threadIdx.x;
    if (i >= n4) return;
    float4 v = reinterpret_cast<const float4*>(src)[i];
    reinterpret_cast<float4*>(passOut)[i] = v;
    __half2* d2 = reinterpret_cast<__half2*>(dst);
    d2[i*2]   = __float22half2_rn(make_float2(v.x, v.y));
    d2[i*2+1] = __float22half2_rn(make_float2(v.z, v.w));
}

// ref2d + spatial_shapes passthrough
__global__ void copy_tail(const float* __restrict__ ref2d, const int* __restrict__ sp,
                          float* __restrict__ outRef, float* __restrict__ outSp)
{
    int i = blockIdx.x * blockDim.x + threadIdx.x;   // over Q*LC*2/4 float4s
    reinterpret_cast<float4*>(outRef)[i] = reinterpret_cast<const float4*>(ref2d)[i];
    if (blockIdx.x == 0 && threadIdx.x < 4) outSp[threadIdx.x] = (float)sp[threadIdx.x];
}

// ---------------------------------------------------------------------------
// Deformable sampling: one warp per (q, h), fp16 value planes, fp16 output.
// ---------------------------------------------------------------------------
__device__ __forceinline__ float fetch_corner(const __half* __restrict__ vl, int xi, int yi)
{
    if (xi < 0 || xi >= Ww || yi < 0 || yi >= Hh) return 0.f;
    return __half2float(vl[(yi * Ww + xi) * C]);
}

template<int L>
__global__ void sampler_kernel(const __half* __restrict__ v,
                               const float* __restrict__ offaw,
                               const float* __restrict__ ref2d,
                               __half* __restrict__ outF)
{
    const int w    = (blockIdx.x * blockDim.x + threadIdx.x) >> 5;
    const int lane = threadIdx.x & 31;
    if (w >= Q * NH) return;
    const int q = w / NH;
    const int h = w % NH;

    constexpr int LNP = L * NP;
    constexpr int RS  = L * 96;          // row stride: 96 (SA) / 192 (CA)
    const float* row = offaw + (size_t)q * RS;
    const float* awp = row + 64 * L + h * LNP;
    const float* offp = row + h * LNP * 2;

    float wgt[LNP];
    float m = -1e30f;
#pragma unroll
    for (int i = 0; i < LNP; i++) { wgt[i] = awp[i]; m = fmaxf(m, wgt[i]); }
    float s = 0.f;
#pragma unroll
    for (int i = 0; i < LNP; i++) { wgt[i] = __expf(wgt[i] - m); s += wgt[i]; }
    const float inv = 1.f / s;

    float acc = 0.f;
#pragma unroll
    for (int l = 0; l < L; l++) {
        const float rx = ref2d[(q * LC + l) * 2 + 0];
        const float ry = ref2d[(q * LC + l) * 2 + 1];
        const __half* vl = v + ((size_t)l * Q) * C + h * HD + lane;
#pragma unroll
        for (int p = 0; p < NP; p++) {
            const float ox = offp[(l * NP + p) * 2 + 0];
            const float oy = offp[(l * NP + p) * 2 + 1];
            const float x = (rx + ox * (1.f / (float)Ww)) * (float)Ww - 0.5f;
            const float y = (ry + oy * (1.f / (float)Hh)) * (float)Hh - 0.5f;
            const float x0f = floorf(x), y0f = floorf(y);
            const int x0 = (int)x0f, y0 = (int)y0f;
            const float tx = x - x0f, ty = y - y0f;
            const float wp = wgt[l * NP + p] * inv;

            const float c00 = fetch_corner(vl, x0,     y0);
            const float c10 = fetch_corner(vl, x0 + 1, y0);
            const float c01 = fetch_corner(vl, x0,     y0 + 1);
            const float c11 = fetch_corner(vl, x0 + 1, y0 + 1);

            const float top = c00 * (1.f - tx) + c10 * tx;
            const float bot = c01 * (1.f - tx) + c11 * tx;
            acc += wp * (top * (1.f - ty) + bot * ty);
        }
    }
    outF[(size_t)q * C + h * HD + lane] = __float2half_rn(acc);
}

// ---------------------------------------------------------------------------
// LayerNorm: one warp per row; optional fused (y + addIn) -> fp16 plane.
// ---------------------------------------------------------------------------
__global__ void ln_kernel(const float* __restrict__ x,
                          const float* __restrict__ g,
                          const float* __restrict__ b,
                          float* __restrict__ y,
                          const float* __restrict__ addIn,
                          __half* __restrict__ yF)
{
    const int row  = (blockIdx.x * blockDim.x + threadIdx.x) >> 5;
    const int lane = threadIdx.x & 31;
    if (row >= Q) return;
    const float* xr = x + (size_t)row * C;
    float v[8];
    float s = 0.f;
#pragma unroll
    for (int i = 0; i < 8; i++) { v[i] = xr[lane + 32 * i]; s += v[i]; }
#pragma unroll
    for (int o = 16; o; o >>= 1) s += __shfl_xor_sync(0xffffffffu, s, o);
    const float mu = s * (1.f / (float)C);
    float s2 = 0.f;
#pragma unroll
    for (int i = 0; i < 8; i++) { const float d = v[i] - mu; s2 += d * d; }
#pragma unroll
    for (int o = 16; o; o >>= 1) s2 += __shfl_xor_sync(0xffffffffu, s2, o);
    const float rstd = rsqrtf(s2 * (1.f / (float)C) + 1e-5f);
#pragma unroll
    for (int i = 0; i < 8; i++) {
        const int c = lane + 32 * i;
        const float o = (v[i] - mu) * rstd * g[c] + b[c];
        y[(size_t)row * C + c] = o;
        if (yF) {
            const float a = addIn ? addIn[(size_t)row * C + c] : 0.f;
            yF[(size_t)row * C + c] = __float2half_rn(o + a);
        }
    }
}

// ---------------------------------------------------------------------------
// Driver
// ---------------------------------------------------------------------------
extern "C" void kernel_launch(void* const* d_in, const int* in_sizes, int n_in,
                              void* d_out, int out_size)
{
    (void)in_sizes; (void)n_in; (void)out_size;

    const float* query     = (const float*)d_in[0];
    const float* query_pos = (const float*)d_in[1];
    const float* value     = (const float*)d_in[2];
    const float* ref2d     = (const float*)d_in[3];
    const int*   spatial   = (const int*)  d_in[4];
    const float* sa_off_w = (const float*)d_in[5];
    const float* sa_off_b = (const float*)d_in[6];
    const float* sa_aw_w  = (const float*)d_in[7];
    const float* sa_aw_b  = (const float*)d_in[8];
    const float* sa_vp_w  = (const float*)d_in[9];
    const float* sa_vp_b  = (const float*)d_in[10];
    const float* sa_op_w  = (const float*)d_in[11];
    const float* sa_op_b  = (const float*)d_in[12];
    const float* ca_off_w = (const float*)d_in[13];
    const float* ca_off_b = (const float*)d_in[14];
    const float* ca_aw_w  = (const float*)d_in[15];
    const float* ca_aw_b  = (const float*)d_in[16];
    const float* ca_vp_w  = (const float*)d_in[17];
    const float* ca_vp_b  = (const float*)d_in[18];
    const float* ca_op_w  = (const float*)d_in[19];
    const float* ca_op_b  = (const float*)d_in[20];
    const float* ffn_w1   = (const float*)d_in[21];
    const float* ffn_b1   = (const float*)d_in[22];
    const float* ffn_w2   = (const float*)d_in[23];
    const float* ffn_b2   = (const float*)d_in[24];
    const float* ln1_g = (const float*)d_in[25];
    const float* ln1_b = (const float*)d_in[26];
    const float* ln2_g = (const float*)d_in[27];
    const float* ln2_b = (const float*)d_in[28];
    const float* ln3_g = (const float*)d_in[29];
    const float* ln3_b = (const float*)d_in[30];

    static bool attr_done = false;
    if (!attr_done) {
        cudaFuncSetAttribute(mma_gemm<false,false>,
                             cudaFuncAttributeMaxDynamicSharedMemorySize, GEMM_SMEM);
        cudaFuncSetAttribute(mma_gemm<false,true>,
                             cudaFuncAttributeMaxDynamicSharedMemorySize, GEMM_SMEM);
        cudaFuncSetAttribute(mma_gemm<true,true>,
                             cudaFuncAttributeMaxDynamicSharedMemorySize, GEMM_SMEM);
        attr_done = true;
    }

    float *offaw, *x, *q1, *q2, *biasP;
    __half *qF, *sF, *vF, *vpF, *aF, *q2F, *hidF, *wF;
    cudaGetSymbolAddress((void**)&offaw, g_offaw);
    cudaGetSymbolAddress((void**)&x,     g_x);
    cudaGetSymbolAddress((void**)&q1,    g_q1);
    cudaGetSymbolAddress((void**)&q2,    g_q2);
    cudaGetSymbolAddress((void**)&biasP, g_biasPack);
    cudaGetSymbolAddress((void**)&qF,    g_qF);
    cudaGetSymbolAddress((void**)&sF,    g_sF);
    cudaGetSymbolAddress((void**)&vF,    g_vF);
    cudaGetSymbolAddress((void**)&vpF,   g_vpF);
    cudaGetSymbolAddress((void**)&aF,    g_aF);
    cudaGetSymbolAddress((void**)&q2F,   g_q2F);
    cudaGetSymbolAddress((void**)&hidF,  g_hidF);
    cudaGetSymbolAddress((void**)&wF,    g_wF);

    float* out = (float*)d_out;
    const int N4 = QC / 4;
    const int CB = (N4 + 255) / 256;

    // ---------------- conversions + fused passthrough ----------------
    convert_weights<<<(W_TOTAL + 255)/256, 256>>>(
        sa_off_w, sa_aw_w, sa_vp_w, sa_op_w, ca_off_w, ca_aw_w, ca_vp_w, ca_op_w,
        ffn_w1, ffn_w2, wF);
    pack_bias<<<1, 288>>>(sa_off_b, sa_aw_b, ca_off_b, ca_aw_b, biasP);
    prep_qsum<<<CB, 256>>>(query, query_pos, qF, sF, out + QC, N4);
    convert_val<<<2*CB, 256>>>(value, vF, out + 2*QC, 2*N4);
    copy_tail<<<Q*LC*2/4/256, 256>>>(ref2d, spatial, out + 4*QC, out + 4*QC + Q*LC*2);

    // ---------------- Self deformable attention (L = 1) ----------------
    mma_gemm<false,true><<<dim3(2, Q/128), 256, GEMM_SMEM>>>(Q, 256, 256,
        qF, wF+OFF_SA_VP, sa_vp_b, nullptr, nullptr, vpF);
    mma_gemm<false,false><<<dim3(1, Q/128), 256, GEMM_SMEM>>>(Q, 96, 256,
        sF, wF+OFF_SA_OFFAW, biasP, nullptr, offaw, nullptr);
    sampler_kernel<1><<<Q*NH/8, 256>>>(vpF, offaw, ref2d, aF);
    mma_gemm<false,false><<<dim3(2, Q/128), 256, GEMM_SMEM>>>(Q, 256, 256,
        aF, wF+OFF_SA_OP, sa_op_b, query, x, nullptr);
    ln_kernel<<<Q/8, 256>>>(x, ln1_g, ln1_b, q1, query_pos, sF);

    // ---------------- Cross deformable attention (L = 2) ----------------
    mma_gemm<false,true><<<dim3(2, 2*Q/128), 256, GEMM_SMEM>>>(2*Q, 256, 256,
        vF, wF+OFF_CA_VP, ca_vp_b, nullptr, nullptr, vpF);
    mma_gemm<false,false><<<dim3(2, Q/128), 256, GEMM_SMEM>>>(Q, 192, 256,
        sF, wF+OFF_CA_OFFAW, biasP + 96, nullptr, offaw, nullptr);
    sampler_kernel<2><<<Q*NH/8, 256>>>(vpF, offaw, ref2d, aF);
    mma_gemm<false,false><<<dim3(2, Q/128), 256, GEMM_SMEM>>>(Q, 256, 256,
        aF, wF+OFF_CA_OP, ca_op_b, q1, x, nullptr);
    ln_kernel<<<Q/8, 256>>>(x, ln2_g, ln2_b, q2, nullptr, q2F);

    // ---------------- FFN ----------------
    mma_gemm<true,true><<<dim3(8, Q/128), 256, GEMM_SMEM>>>(Q, 1024, 256,
        q2F, wF+OFF_FFN1, ffn_b1, nullptr, nullptr, hidF);
    mma_gemm<false,false><<<dim3(2, Q/128), 256, GEMM_SMEM>>>(Q, 256, 1024,
        hidF, wF+OFF_FFN2, ffn_b2, q2, x, nullptr);
    ln_kernel<<<Q/8, 256>>>(x, ln3_g, ln3_b, out, nullptr, nullptr);
}

// round 15
// speedup vs baseline: 3.5797x; 1.0120x over previous
#include <cuda_runtime.h>
#include <cuda_fp16.h>
#include <cstdint>

// ---------------------------------------------------------------------------
// Problem constants
// ---------------------------------------------------------------------------
constexpr int Hh  = 160;
constexpr int Ww  = 160;
constexpr int Q   = Hh * Ww;      // 25600
constexpr int C   = 256;
constexpr int NH  = 8;
constexpr int HD  = C / NH;       // 32
constexpr int NP  = 4;
constexpr int LC  = 2;
constexpr int QC  = Q * C;        // 6,553,600

// Packed weight-plane offsets (elements)
constexpr int OFF_SA_OFFAW = 0;          // [256, 96]  (off 64 | aw 32)
constexpr int OFF_SA_VP    = 24576;      // [256, 256]
constexpr int OFF_SA_OP    = 90112;      // [256, 256]
constexpr int OFF_CA_OFFAW = 155648;     // [256, 192] (off 128 | aw 64)
constexpr int OFF_CA_VP    = 204800;     // [256, 256]
constexpr int OFF_CA_OP    = 270336;     // [256, 256]
constexpr int OFF_FFN1     = 335872;     // [256, 1024]
constexpr int OFF_FFN2     = 598016;     // [1024, 256]
constexpr int W_TOTAL      = 860160;

// prep_all block partition
constexpr int PB_W    = (W_TOTAL + 255) / 256;   // 3360
constexpr int PB_QS   = QC / 4 / 256;            // 6400
constexpr int PB_VAL  = 2 * QC / 4 / 256;        // 12800
constexpr int PB_TAIL = Q * LC * 2 / 4 / 256;    // 100
constexpr int PB_BIAS = 2;
constexpr int PB_TOT  = PB_W + PB_QS + PB_VAL + PB_TAIL + PB_BIAS;

// ---------------------------------------------------------------------------
// Scratch (device globals -- no allocations allowed)
// ---------------------------------------------------------------------------
__device__ float g_offaw[Q * 192];
__device__ float g_x [QC];
__device__ float g_q1[QC];
__device__ float g_q2[QC];
__device__ float g_biasPack[288];

__device__ __align__(256) __half g_qF[QC];
__device__ __align__(256) __half g_sF[QC];
__device__ __align__(256) __half g_vF[2 * QC];
__device__ __align__(256) __half g_vpF[2 * QC];
__device__ __align__(256) __half g_aF[QC];
__device__ __align__(256) __half g_q2F[QC];
__device__ __align__(256) __half g_hidF[Q * 4 * C];
__device__ __align__(256) __half g_wF[W_TOTAL];

// ---------------------------------------------------------------------------
// PTX helpers
// ---------------------------------------------------------------------------
__device__ __forceinline__ void ldm_x4(uint32_t& r0, uint32_t& r1,
                                       uint32_t& r2, uint32_t& r3, uint32_t addr)
{
    asm volatile("ldmatrix.sync.aligned.m8n8.x4.shared.b16 {%0,%1,%2,%3}, [%4];"
                 : "=r"(r0), "=r"(r1), "=r"(r2), "=r"(r3) : "r"(addr));
}
__device__ __forceinline__ void ldm_x4_t(uint32_t& r0, uint32_t& r1,
                                         uint32_t& r2, uint32_t& r3, uint32_t addr)
{
    asm volatile("ldmatrix.sync.aligned.m8n8.x4.trans.shared.b16 {%0,%1,%2,%3}, [%4];"
                 : "=r"(r0), "=r"(r1), "=r"(r2), "=r"(r3) : "r"(addr));
}
__device__ __forceinline__ void mma_f16(float* c, uint32_t a0, uint32_t a1,
                                        uint32_t a2, uint32_t a3,
                                        uint32_t b0, uint32_t b1)
{
    asm volatile("mma.sync.aligned.m16n8k16.row.col.f32.f16.f16.f32 "
                 "{%0,%1,%2,%3}, {%4,%5,%6,%7}, {%8,%9}, {%0,%1,%2,%3};"
                 : "+f"(c[0]), "+f"(c[1]), "+f"(c[2]), "+f"(c[3])
                 : "r"(a0), "r"(a1), "r"(a2), "r"(a3), "r"(b0), "r"(b1));
}
__device__ __forceinline__ void cp16(uint32_t s, const void* g)
{
    asm volatile("cp.async.cg.shared.global [%0], [%1], 16;" :: "r"(s), "l"(g));
}
__device__ __forceinline__ void cp16z(uint32_t s, const void* g, bool valid)
{
    int sz = valid ? 16 : 0;
    asm volatile("cp.async.cg.shared.global [%0], [%1], 16, %2;"
                 :: "r"(s), "l"(g), "r"(sz));
}
__device__ __forceinline__ void cp_commit() { asm volatile("cp.async.commit_group;"); }

// ---------------------------------------------------------------------------
// Dual-problem tensor-core GEMM (runtime flags). Per problem:
//   C = A[M,K] @ B[K,N] + bias (+ res) (ReLU?), out fp32 or fp16.
// Block 128x128x64, 8 warps, 3-stage cp.async, one sync per k-tile.
// 1-D grid: blocks [0, ctas0) -> problem 0, rest -> problem 1.
// ---------------------------------------------------------------------------
constexpr int NSTAGE = 3;
constexpr int BK     = 64;
constexpr int GEMM_SMEM = NSTAGE * (8192 + 8192) * (int)sizeof(__half); // 98304

struct GemmP {
    const __half* A; const __half* B;
    const float* bias; const float* res;
    float* Cout; __half* outF;
    int M, N, K, relu, nctaX;
};

__global__ void __launch_bounds__(256, 2)
mma_gemm2(GemmP p0, GemmP p1, int ctas0)
{
    extern __shared__ __half sh[];
    const uint32_t shBase = (uint32_t)__cvta_generic_to_shared(sh);

    const bool first = ((int)blockIdx.x < ctas0);
    const GemmP p = first ? p0 : p1;
    const int idx = first ? blockIdx.x : (blockIdx.x - ctas0);
    const int rowBase = (idx / p.nctaX) * 128;
    const int colBase = (idx % p.nctaX) * 128;
    const int N = p.N, K = p.K;
    const __half* __restrict__ A = p.A;
    const __half* __restrict__ B = p.B;

    const int tid  = threadIdx.x;
    const int lane = tid & 31;
    const int warp = tid >> 5;
    const int wm   = warp >> 2;
    const int wn   = warp & 3;

    float acc[4][4][4];
#pragma unroll
    for (int i = 0; i < 4; i++)
#pragma unroll
        for (int j = 0; j < 4; j++)
#pragma unroll
            for (int k = 0; k < 4; k++) acc[i][j][k] = 0.f;

    const int ntiles = K / BK;

    auto load_stage = [&](int ktile, int buf) {
        const int kt = ktile * BK;
        const uint32_t aB = shBase + (uint32_t)(buf * 8192) * 2;
#pragma unroll
        for (int j = 0; j < 4; j++) {
            const int i2 = tid + j * 256;
            const int r  = i2 >> 3;
            const int c8 = i2 & 7;
            const int cs = c8 ^ (r & 7);
            cp16(aB + (uint32_t)(r * 64 + cs * 8) * 2,
                 A + (size_t)(rowBase + r) * K + kt + c8 * 8);
        }
        const uint32_t bB = shBase + (uint32_t)(NSTAGE * 8192 + buf * 8192) * 2;
#pragma unroll
        for (int j = 0; j < 4; j++) {
            const int i2 = tid + j * 256;
            const int r  = i2 >> 4;
            const int c8 = i2 & 15;
            const int gc = colBase + c8 * 8;
            const int cs = c8 ^ (r & 7);
            cp16z(bB + (uint32_t)(r * 128 + cs * 8) * 2,
                  B + (size_t)(kt + r) * N + gc, gc < N);
        }
    };

    load_stage(0, 0); cp_commit();
    if (ntiles > 1) { load_stage(1, 1); cp_commit(); }

    for (int kt = 0; kt < ntiles; kt++) {
        if (kt == ntiles - 1) asm volatile("cp.async.wait_group 0;");
        else                  asm volatile("cp.async.wait_group 1;");
        __syncthreads();

        if (kt + 2 < ntiles) { load_stage(kt + 2, (kt + 2) % NSTAGE); cp_commit(); }

        const int buf = kt % NSTAGE;
        const uint32_t aB = shBase + (uint32_t)(buf * 8192) * 2;
        const uint32_t bB = shBase + (uint32_t)(NSTAGE * 8192 + buf * 8192) * 2;

#pragma unroll
        for (int s = 0; s < 4; s++) {
            uint32_t af[4][4];
            uint32_t bf[4][2];
#pragma unroll
            for (int mt = 0; mt < 4; mt++) {
                const int r  = wm * 64 + mt * 16 + (lane & 15);
                const int c  = s * 2 + (lane >> 4);
                const int cs = c ^ (r & 7);
                ldm_x4(af[mt][0], af[mt][1], af[mt][2], af[mt][3],
                       aB + (uint32_t)(r * 64 + cs * 8) * 2);
            }
#pragma unroll
            for (int pi = 0; pi < 2; pi++) {
                const int k  = s * 16 + (lane & 15);
                const int cc = wn * 4 + (lane >> 4) + pi * 2;
                const int cs = cc ^ (k & 7);
                ldm_x4_t(bf[pi*2][0], bf[pi*2][1], bf[pi*2+1][0], bf[pi*2+1][1],
                         bB + (uint32_t)(k * 128 + cs * 8) * 2);
            }
#pragma unroll
            for (int mt = 0; mt < 4; mt++)
#pragma unroll
                for (int nt = 0; nt < 4; nt++)
                    mma_f16(acc[mt][nt], af[mt][0], af[mt][1], af[mt][2], af[mt][3],
                            bf[nt][0], bf[nt][1]);
        }
    }

    // ---- epilogue (runtime flags) ----
    const int g  = lane >> 2;
    const int t4 = lane & 3;
#pragma unroll
    for (int mt = 0; mt < 4; mt++) {
#pragma unroll
        for (int nt = 0; nt < 4; nt++) {
            const int col = colBase + wn * 32 + nt * 8 + t4 * 2;
            if (col >= N) continue;
            const int r0 = rowBase + wm * 64 + mt * 16 + g;
            const float2 b2 = *reinterpret_cast<const float2*>(p.bias + col);
            float2 o0 = make_float2(acc[mt][nt][0] + b2.x, acc[mt][nt][1] + b2.y);
            float2 o1 = make_float2(acc[mt][nt][2] + b2.x, acc[mt][nt][3] + b2.y);
            if (p.res) {
                float2 r2a = *reinterpret_cast<const float2*>(p.res + (size_t)r0 * N + col);
                float2 r2b = *reinterpret_cast<const float2*>(p.res + (size_t)(r0 + 8) * N + col);
                o0.x += r2a.x; o0.y += r2a.y; o1.x += r2b.x; o1.y += r2b.y;
            }
            if (p.relu) {
                o0.x = fmaxf(o0.x, 0.f); o0.y = fmaxf(o0.y, 0.f);
                o1.x = fmaxf(o1.x, 0.f); o1.y = fmaxf(o1.y, 0.f);
            }
            if (p.outF) {
                *reinterpret_cast<__half2*>(p.outF + (size_t)r0 * N + col) = __float22half2_rn(o0);
                *reinterpret_cast<__half2*>(p.outF + (size_t)(r0 + 8) * N + col) = __float22half2_rn(o1);
            } else {
                *reinterpret_cast<float2*>(p.Cout + (size_t)r0 * N + col) = o0;
                *reinterpret_cast<float2*>(p.Cout + (size_t)(r0 + 8) * N + col) = o1;
            }
        }
    }
}

// ---------------------------------------------------------------------------
// Fused prep: weights->fp16 | pack bias | query/qsum->fp16 (+query_pos out)
//             value->fp16 (+value out) | ref2d/spatial out
// ---------------------------------------------------------------------------
__global__ void prep_all(const float* __restrict__ query, const float* __restrict__ query_pos,
                         const float* __restrict__ value, const float* __restrict__ ref2d,
                         const int* __restrict__ sp,
                         const float* __restrict__ sa_off_w, const float* __restrict__ sa_aw_w,
                         const float* __restrict__ sa_vp_w,  const float* __restrict__ sa_op_w,
                         const float* __restrict__ ca_off_w, const float* __restrict__ ca_aw_w,
                         const float* __restrict__ ca_vp_w,  const float* __restrict__ ca_op_w,
                         const float* __restrict__ ffn_w1,   const float* __restrict__ ffn_w2,
                         const float* __restrict__ sa_off_b, const float* __restrict__ sa_aw_b,
                         const float* __restrict__ ca_off_b, const float* __restrict__ ca_aw_b,
                         __half* __restrict__ wf, float* __restrict__ biasP,
                         __half* __restrict__ qF, __half* __restrict__ sF,
                         __half* __restrict__ vF,
                         float* __restrict__ out)
{
    const int b   = blockIdx.x;
    const int tid = threadIdx.x;
    if (b < PB_W) {
        int e = b * 256 + tid;
        if (e >= W_TOTAL) return;
        float val;
        if (e < OFF_SA_VP) {
            int r = e / 96, c = e % 96;
            val = (c < 64) ? sa_off_w[r * 64 + c] : sa_aw_w[r * 32 + (c - 64)];
        } else if (e < OFF_SA_OP)    val = sa_vp_w[e - OFF_SA_VP];
        else if (e < OFF_CA_OFFAW)   val = sa_op_w[e - OFF_SA_OP];
        else if (e < OFF_CA_VP) {
            int t = e - OFF_CA_OFFAW;
            int r = t / 192, c = t % 192;
            val = (c < 128) ? ca_off_w[r * 128 + c] : ca_aw_w[r * 64 + (c - 128)];
        } else if (e < OFF_CA_OP)    val = ca_vp_w[e - OFF_CA_VP];
        else if (e < OFF_FFN1)       val = ca_op_w[e - OFF_CA_OP];
        else if (e < OFF_FFN2)       val = ffn_w1[e - OFF_FFN1];
        else                         val = ffn_w2[e - OFF_FFN2];
        wf[e] = __float2half_rn(val);
    } else if (b < PB_W + PB_QS) {
        int i = (b - PB_W) * 256 + tid;
        float4 va = reinterpret_cast<const float4*>(query)[i];
        float4 vb = reinterpret_cast<const float4*>(query_pos)[i];
        reinterpret_cast<float4*>(out + QC)[i] = vb;
        __half2* q2 = reinterpret_cast<__half2*>(qF);
        __half2* s2 = reinterpret_cast<__half2*>(sF);
        q2[i*2]   = __float22half2_rn(make_float2(va.x, va.y));
        q2[i*2+1] = __float22half2_rn(make_float2(va.z, va.w));
        s2[i*2]   = __float22half2_rn(make_float2(va.x + vb.x, va.y + vb.y));
        s2[i*2+1] = __float22half2_rn(make_float2(va.z + vb.z, va.w + vb.w));
    } else if (b < PB_W + PB_QS + PB_VAL) {
        int i = (b - PB_W - PB_QS) * 256 + tid;
        float4 v = reinterpret_cast<const float4*>(value)[i];
        reinterpret_cast<float4*>(out + 2*QC)[i] = v;
        __half2* d2 = reinterpret_cast<__half2*>(vF);
        d2[i*2]   = __float22half2_rn(make_float2(v.x, v.y));
        d2[i*2+1] = __float22half2_rn(make_float2(v.z, v.w));
    } else if (b < PB_W + PB_QS + PB_VAL + PB_TAIL) {
        int i = (b - PB_W - PB_QS - PB_VAL) * 256 + tid;
        reinterpret_cast<float4*>(out + 4*QC)[i] = reinterpret_cast<const float4*>(ref2d)[i];
        if (i < 4) out[4*QC + Q*LC*2 + i] = (float)sp[i];
    } else {
        int i = (b - PB_W - PB_QS - PB_VAL - PB_TAIL) * 256 + tid;
        if (i >= 288) return;
        float v;
        if (i < 64)        v = sa_off_b[i];
        else if (i < 96)   v = sa_aw_b[i - 64];
        else if (i < 224)  v = ca_off_b[i - 96];
        else               v = ca_aw_b[i - 224];
        biasP[i] = v;
    }
}

// ---------------------------------------------------------------------------
// Deformable sampling: one warp per (q, h), fp16 value planes, fp16 output.
// ---------------------------------------------------------------------------
__device__ __forceinline__ float fetch_corner(const __half* __restrict__ vl, int xi, int yi)
{
    if (xi < 0 || xi >= Ww || yi < 0 || yi >= Hh) return 0.f;
    return __half2float(vl[(yi * Ww + xi) * C]);
}

template<int L>
__global__ void sampler_kernel(const __half* __restrict__ v,
                               const float* __restrict__ offaw,
                               const float* __restrict__ ref2d,
                               __half* __restrict__ outF)
{
    const int w    = (blockIdx.x * blockDim.x + threadIdx.x) >> 5;
    const int lane = threadIdx.x & 31;
    if (w >= Q * NH) return;
    const int q = w / NH;
    const int h = w % NH;

    constexpr int LNP = L * NP;
    constexpr int RS  = L * 96;
    const float* row = offaw + (size_t)q * RS;
    const float* awp = row + 64 * L + h * LNP;
    const float* offp = row + h * LNP * 2;

    float wgt[LNP];
    float m = -1e30f;
#pragma unroll
    for (int i = 0; i < LNP; i++) { wgt[i] = awp[i]; m = fmaxf(m, wgt[i]); }
    float s = 0.f;
#pragma unroll
    for (int i = 0; i < LNP; i++) { wgt[i] = __expf(wgt[i] - m); s += wgt[i]; }
    const float inv = 1.f / s;

    float acc = 0.f;
#pragma unroll
    for (int l = 0; l < L; l++) {
        const float rx = ref2d[(q * LC + l) * 2 + 0];
        const float ry = ref2d[(q * LC + l) * 2 + 1];
        const __half* vl = v + ((size_t)l * Q) * C + h * HD + lane;
#pragma unroll
        for (int p = 0; p < NP; p++) {
            const float ox = offp[(l * NP + p) * 2 + 0];
            const float oy = offp[(l * NP + p) * 2 + 1];
            const float x = (rx + ox * (1.f / (float)Ww)) * (float)Ww - 0.5f;
            const float y = (ry + oy * (1.f / (float)Hh)) * (float)Hh - 0.5f;
            const float x0f = floorf(x), y0f = floorf(y);
            const int x0 = (int)x0f, y0 = (int)y0f;
            const float tx = x - x0f, ty = y - y0f;
            const float wp = wgt[l * NP + p] * inv;

            const float c00 = fetch_corner(vl, x0,     y0);
            const float c10 = fetch_corner(vl, x0 + 1, y0);
            const float c01 = fetch_corner(vl, x0,     y0 + 1);
            const float c11 = fetch_corner(vl, x0 + 1, y0 + 1);

            const float top = c00 * (1.f - tx) + c10 * tx;
            const float bot = c01 * (1.f - tx) + c11 * tx;
            acc += wp * (top * (1.f - ty) + bot * ty);
        }
    }
    outF[(size_t)q * C + h * HD + lane] = __float2half_rn(acc);
}

// ---------------------------------------------------------------------------
// LayerNorm: one warp per row; optional fused (y + addIn) -> fp16 plane.
// ---------------------------------------------------------------------------
__global__ void ln_kernel(const float* __restrict__ x,
                          const float* __restrict__ g,
                          const float* __restrict__ b,
                          float* __restrict__ y,
                          const float* __restrict__ addIn,
                          __half* __restrict__ yF)
{
    const int row  = (blockIdx.x * blockDim.x + threadIdx.x) >> 5;
    const int lane = threadIdx.x & 31;
    if (row >= Q) return;
    const float* xr = x + (size_t)row * C;
    float v[8];
    float s = 0.f;
#pragma unroll
    for (int i = 0; i < 8; i++) { v[i] = xr[lane + 32 * i]; s += v[i]; }
#pragma unroll
    for (int o = 16; o; o >>= 1) s += __shfl_xor_sync(0xffffffffu, s, o);
    const float mu = s * (1.f / (float)C);
    float s2 = 0.f;
#pragma unroll
    for (int i = 0; i < 8; i++) { const float d = v[i] - mu; s2 += d * d; }
#pragma unroll
    for (int o = 16; o; o >>= 1) s2 += __shfl_xor_sync(0xffffffffu, s2, o);
    const float rstd = rsqrtf(s2 * (1.f / (float)C) + 1e-5f);
#pragma unroll
    for (int i = 0; i < 8; i++) {
        const int c = lane + 32 * i;
        const float o = (v[i] - mu) * rstd * g[c] + b[c];
        y[(size_t)row * C + c] = o;
        if (yF) {
            const float a = addIn ? addIn[(size_t)row * C + c] : 0.f;
            yF[(size_t)row * C + c] = __float2half_rn(o + a);
        }
    }
}

// ---------------------------------------------------------------------------
// Driver
// ---------------------------------------------------------------------------
extern "C" void kernel_launch(void* const* d_in, const int* in_sizes, int n_in,
                              void* d_out, int out_size)
{
    (void)in_sizes; (void)n_in; (void)out_size;

    const float* query     = (const float*)d_in[0];
    const float* query_pos = (const float*)d_in[1];
    const float* value     = (const float*)d_in[2];
    const float* ref2d     = (const float*)d_in[3];
    const int*   spatial   = (const int*)  d_in[4];
    const float* sa_off_w = (const float*)d_in[5];
    const float* sa_off_b = (const float*)d_in[6];
    const float* sa_aw_w  = (const float*)d_in[7];
    const float* sa_aw_b  = (const float*)d_in[8];
    const float* sa_vp_w  = (const float*)d_in[9];
    const float* sa_vp_b  = (const float*)d_in[10];
    const float* sa_op_w  = (const float*)d_in[11];
    const float* sa_op_b  = (const float*)d_in[12];
    const float* ca_off_w = (const float*)d_in[13];
    const float* ca_off_b = (const float*)d_in[14];
    const float* ca_aw_w  = (const float*)d_in[15];
    const float* ca_aw_b  = (const float*)d_in[16];
    const float* ca_vp_w  = (const float*)d_in[17];
    const float* ca_vp_b  = (const float*)d_in[18];
    const float* ca_op_w  = (const float*)d_in[19];
    const float* ca_op_b  = (const float*)d_in[20];
    const float* ffn_w1   = (const float*)d_in[21];
    const float* ffn_b1   = (const float*)d_in[22];
    const float* ffn_w2   = (const float*)d_in[23];
    const float* ffn_b2   = (const float*)d_in[24];
    const float* ln1_g = (const float*)d_in[25];
    const float* ln1_b = (const float*)d_in[26];
    const float* ln2_g = (const float*)d_in[27];
    const float* ln2_b = (const float*)d_in[28];
    const float* ln3_g = (const float*)d_in[29];
    const float* ln3_b = (const float*)d_in[30];

    static bool attr_done = false;
    if (!attr_done) {
        cudaFuncSetAttribute(mma_gemm2,
                             cudaFuncAttributeMaxDynamicSharedMemorySize, GEMM_SMEM);
        attr_done = true;
    }

    float *offaw, *x, *q1, *q2, *biasP;
    __half *qF, *sF, *vF, *vpF, *aF, *q2F, *hidF, *wF;
    cudaGetSymbolAddress((void**)&offaw, g_offaw);
    cudaGetSymbolAddress((void**)&x,     g_x);
    cudaGetSymbolAddress((void**)&q1,    g_q1);
    cudaGetSymbolAddress((void**)&q2,    g_q2);
    cudaGetSymbolAddress((void**)&biasP, g_biasPack);
    cudaGetSymbolAddress((void**)&qF,    g_qF);
    cudaGetSymbolAddress((void**)&sF,    g_sF);
    cudaGetSymbolAddress((void**)&vF,    g_vF);
    cudaGetSymbolAddress((void**)&vpF,   g_vpF);
    cudaGetSymbolAddress((void**)&aF,    g_aF);
    cudaGetSymbolAddress((void**)&q2F,   g_q2F);
    cudaGetSymbolAddress((void**)&hidF,  g_hidF);
    cudaGetSymbolAddress((void**)&wF,    g_wF);

    float* out = (float*)d_out;

    // problem descriptors
    GemmP pSAVP  = { qF,   wF+OFF_SA_VP,    sa_vp_b,  nullptr, nullptr, vpF,  Q,   256,  256, 0, 2 };
    GemmP pSAOA  = { sF,   wF+OFF_SA_OFFAW, biasP,    nullptr, offaw,  nullptr, Q, 96,  256, 0, 1 };
    GemmP pSAOP  = { aF,   wF+OFF_SA_OP,    sa_op_b,  query,   x,      nullptr, Q, 256, 256, 0, 2 };
    GemmP pCAVP  = { vF,   wF+OFF_CA_VP,    ca_vp_b,  nullptr, nullptr, vpF,  2*Q, 256,  256, 0, 2 };
    GemmP pCAOA  = { sF,   wF+OFF_CA_OFFAW, biasP+96, nullptr, offaw,  nullptr, Q, 192, 256, 0, 2 };
    GemmP pCAOP  = { aF,   wF+OFF_CA_OP,    ca_op_b,  q1,      x,      nullptr, Q, 256, 256, 0, 2 };
    GemmP pFFN1  = { q2F,  wF+OFF_FFN1,     ffn_b1,   nullptr, nullptr, hidF, Q,   1024, 256, 1, 8 };
    GemmP pFFN2  = { hidF, wF+OFF_FFN2,     ffn_b2,   q2,      x,      nullptr, Q, 256, 1024, 0, 2 };

    // 1. fused prep (all conversions + passthrough outputs)
    prep_all<<<PB_TOT, 256>>>(query, query_pos, value, ref2d, spatial,
        sa_off_w, sa_aw_w, sa_vp_w, sa_op_w, ca_off_w, ca_aw_w, ca_vp_w, ca_op_w,
        ffn_w1, ffn_w2, sa_off_b, sa_aw_b, ca_off_b, ca_aw_b,
        wF, biasP, qF, sF, vF, out);

    // 2. SA VP (400) + SA OFFAW (200)
    mma_gemm2<<<600, 256, GEMM_SMEM>>>(pSAVP, pSAOA, 400);
    // 3. SA sampler
    sampler_kernel<1><<<Q*NH/8, 256>>>(vpF, offaw, ref2d, aF);
    // 4. SA OP (400) + CA VP (800)  (CA VP depends only on prep; vpF free after sampler1)
    mma_gemm2<<<1200, 256, GEMM_SMEM>>>(pSAOP, pCAVP, 400);
    // 5. LN1 (+ fused qsum fp16)
    ln_kernel<<<Q/8, 256>>>(x, ln1_g, ln1_b, q1, query_pos, sF);
    // 6. CA OFFAW (400)
    mma_gemm2<<<400, 256, GEMM_SMEM>>>(pCAOA, pCAOA, 400);
    // 7. CA sampler
    sampler_kernel<2><<<Q*NH/8, 256>>>(vpF, offaw, ref2d, aF);
    // 8. CA OP (400)
    mma_gemm2<<<400, 256, GEMM_SMEM>>>(pCAOP, pCAOP, 400);
    // 9. LN2 (+ fused fp16)
    ln_kernel<<<Q/8, 256>>>(x, ln2_g, ln2_b, q2, nullptr, q2F);
    // 10. FFN1 (1600)
    mma_gemm2<<<1600, 256, GEMM_SMEM>>>(pFFN1, pFFN1, 1600);
    // 11. FFN2 (400)
    mma_gemm2<<<400, 256, GEMM_SMEM>>>(pFFN2, pFFN2, 400);
    // 12. LN3 -> out
    ln_kernel<<<Q/8, 256>>>(x, ln3_g, ln3_b, out, nullptr, nullptr);
}